// round 1
// baseline (speedup 1.0000x reference)
#include <cuda_runtime.h>
#include <math.h>

// ---------------------------------------------------------------------------
// Problem constants
//   B=2, N=2048, C=64, MV=16, D=64, H=8, BLADE=9
//   x:     [2,2048,64,16]          (d_in[0])
//   blade: [9,16,16]               (d_in[1])
//   w_q:   [512,64,9]              (d_in[2])
//   w_k:   [64,64,9]               (d_in[3])
//   w_v:   [64,64,9]               (d_in[4])
//   w_o:   [64,512,9]              (d_in[5])
//   out:   [2,2048,64,16] float32
// ---------------------------------------------------------------------------

#define NB 2
#define NI 2048
#define NC 64
#define MV 16
#define ND 64
#define NH 8
#define M_ROWS (NB*NI)          // 4096
#define K_IN   (NC*MV)          // 1024

__constant__ int c_ip[8] = {0, 2, 3, 4, 8, 9, 10, 14};

// ------------------------- scratch (device globals) ------------------------
__device__ __align__(128) float g_Wq2[1024 * 4096];            // [K_IN, H*D*8]
__device__ __align__(128) float g_Wk2[1024 * 512];             // [K_IN, D*8]
__device__ __align__(128) float g_Wv [1024 * 1024];            // [K_IN, D*16]
__device__ __align__(128) float g_Wo [8192 * 1024];            // [H*D*16, C*16]
__device__ __align__(128) float g_qm [4096 * 4096];            // [b*n, h*512 + d*8+e]
__device__ __align__(128) float g_km [4096 * 512];             // [b*n, d*8+e]
__device__ __align__(128) float g_v  [4096 * 1024];            // [b*n, d*16+c]
__device__ __align__(128) float g_sc [16LL * 2048 * 2048];     // [b,h,q,k]
__device__ __align__(128) float g_ao [4096LL * 8192];          // [b*n, h*1024 + d*16+c]

// ------------------------- weight precompute -------------------------------
// mode 0: col = j*16 + y           (full multivector output)
// mode 1: col = h*512 + d*8 + e ;  j = d*8 + h ; y = IP[e]   (q, scale folded)
// mode 2: col = d*8 + e ;          j = d       ; y = IP[e]   (k)
__global__ void make_weight(const float* __restrict__ w,
                            const float* __restrict__ blade,
                            float* __restrict__ W,
                            int I, int J, int mode, float scale, long long total,
                            int ncols)
{
    long long idx = (long long)blockIdx.x * 256 + threadIdx.x;
    if (idx >= total) return;
    long long row = idx / ncols;
    int col = (int)(idx % ncols);
    int i  = (int)(row >> 4);
    int xc = (int)(row & 15);
    int j, y;
    if (mode == 0)      { j = col >> 4;  y = col & 15; }
    else if (mode == 1) { int e = col & 7; int d = (col >> 3) & 63; int h = col >> 9;
                          j = d * 8 + h; y = c_ip[e]; }
    else                { int e = col & 7; j = col >> 3; y = c_ip[e]; }
    float s = 0.f;
    #pragma unroll
    for (int b = 0; b < 9; b++)
        s += w[((long long)j * I + i) * 9 + b] * blade[b * 256 + xc * 16 + y];
    W[idx] = s * scale;
}

// ------------------------------ SGEMM --------------------------------------
// C[m,n] = sum_k A[m,k] * B[k,n]   (TRANSB=0, B row-major [K,N])
// C[m,n] = sum_k A[m,k] * B[n,k]   (TRANSB=1, B row-major [N,K])
// Tiles: 128x128x8, 256 threads, 8x8 microtile. All dims multiples of tile.
// Batched over blockIdx.z with (b,h) decomposition: z = b*nH + h.
template<int TRANSB>
__global__ __launch_bounds__(256) void sgemm(
    const float* __restrict__ A, const float* __restrict__ Bm,
    float* __restrict__ Cm, int K, int lda, int ldb, int ldc,
    long long sAb, long long sAh, long long sBb, long long sBh,
    long long sCb, long long sCh, int nH)
{
    __shared__ float As[8][128];
    __shared__ float Bs[8][128];

    const int z = blockIdx.z;
    const int bb = z / nH, hh = z % nH;
    A  += bb * sAb + hh * sAh;
    Bm += bb * sBb + hh * sBh;
    Cm += bb * sCb + hh * sCh;

    const int bm = blockIdx.y * 128;
    const int bn = blockIdx.x * 128;
    const int t  = threadIdx.x;
    const int tm = (t >> 4) << 3;
    const int tn = (t & 15) << 3;
    const int arow = t >> 1;
    const int aseg = (t & 1) << 2;
    const int brow = t >> 5;
    const int bcol = (t & 31) << 2;

    const float* Aptr = A + (long long)(bm + arow) * lda + aseg;
    const float* Bptr = TRANSB ? (Bm + (long long)(bn + arow) * ldb + aseg)
                               : (Bm + (long long)brow * ldb + bn + bcol);

    float acc[8][8];
    #pragma unroll
    for (int i = 0; i < 8; i++)
        #pragma unroll
        for (int j = 0; j < 8; j++) acc[i][j] = 0.f;

    for (int k0 = 0; k0 < K; k0 += 8) {
        float4 av = *reinterpret_cast<const float4*>(Aptr + k0);
        As[aseg + 0][arow] = av.x;
        As[aseg + 1][arow] = av.y;
        As[aseg + 2][arow] = av.z;
        As[aseg + 3][arow] = av.w;
        if (TRANSB) {
            float4 bv = *reinterpret_cast<const float4*>(Bptr + k0);
            Bs[aseg + 0][arow] = bv.x;
            Bs[aseg + 1][arow] = bv.y;
            Bs[aseg + 2][arow] = bv.z;
            Bs[aseg + 3][arow] = bv.w;
        } else {
            float4 bv = *reinterpret_cast<const float4*>(Bptr + (long long)k0 * ldb);
            *reinterpret_cast<float4*>(&Bs[brow][bcol]) = bv;
        }
        __syncthreads();
        #pragma unroll
        for (int k = 0; k < 8; k++) {
            float4 a0 = *reinterpret_cast<const float4*>(&As[k][tm]);
            float4 a1 = *reinterpret_cast<const float4*>(&As[k][tm + 4]);
            float4 b0 = *reinterpret_cast<const float4*>(&Bs[k][tn]);
            float4 b1 = *reinterpret_cast<const float4*>(&Bs[k][tn + 4]);
            float ar[8] = {a0.x, a0.y, a0.z, a0.w, a1.x, a1.y, a1.z, a1.w};
            float br[8] = {b0.x, b0.y, b0.z, b0.w, b1.x, b1.y, b1.z, b1.w};
            #pragma unroll
            for (int i = 0; i < 8; i++)
                #pragma unroll
                for (int j = 0; j < 8; j++)
                    acc[i][j] = fmaf(ar[i], br[j], acc[i][j]);
        }
        __syncthreads();
    }

    #pragma unroll
    for (int i = 0; i < 8; i++) {
        float* crow = Cm + (long long)(bm + tm + i) * ldc + bn + tn;
        float4 c0 = make_float4(acc[i][0], acc[i][1], acc[i][2], acc[i][3]);
        float4 c1 = make_float4(acc[i][4], acc[i][5], acc[i][6], acc[i][7]);
        *reinterpret_cast<float4*>(crow)     = c0;
        *reinterpret_cast<float4*>(crow + 4) = c1;
    }
}

// ------------------------------ softmax ------------------------------------
__global__ void softmax_rows(float* __restrict__ data, int ncols)
{
    __shared__ float red[256];
    float* p = data + (long long)blockIdx.x * ncols;
    const int t = threadIdx.x;

    float mx = -INFINITY;
    for (int c = t; c < ncols; c += 256) mx = fmaxf(mx, p[c]);
    red[t] = mx; __syncthreads();
    #pragma unroll
    for (int s = 128; s > 0; s >>= 1) {
        if (t < s) red[t] = fmaxf(red[t], red[t + s]);
        __syncthreads();
    }
    mx = red[0]; __syncthreads();

    float sum = 0.f;
    for (int c = t; c < ncols; c += 256) {
        float e = __expf(p[c] - mx);
        p[c] = e;
        sum += e;
    }
    red[t] = sum; __syncthreads();
    #pragma unroll
    for (int s = 128; s > 0; s >>= 1) {
        if (t < s) red[t] += red[t + s];
        __syncthreads();
    }
    float inv = 1.0f / red[0];
    for (int c = t; c < ncols; c += 256) p[c] *= inv;
}

// ------------------------------ launch -------------------------------------
static float* sym_addr(const void* symbol)
{
    void* p = nullptr;
    cudaGetSymbolAddress(&p, symbol);
    return (float*)p;
}

extern "C" void kernel_launch(void* const* d_in, const int* in_sizes, int n_in,
                              void* d_out, int out_size)
{
    const float* x     = (const float*)d_in[0];
    const float* blade = (const float*)d_in[1];
    const float* w_q   = (const float*)d_in[2];
    const float* w_k   = (const float*)d_in[3];
    const float* w_v   = (const float*)d_in[4];
    const float* w_o   = (const float*)d_in[5];
    float* out = (float*)d_out;

    float* Wq2 = sym_addr(g_Wq2);
    float* Wk2 = sym_addr(g_Wk2);
    float* Wv  = sym_addr(g_Wv);
    float* Wo  = sym_addr(g_Wo);
    float* qm  = sym_addr(g_qm);
    float* km  = sym_addr(g_km);
    float* v   = sym_addr(g_v);
    float* sc  = sym_addr(g_sc);
    float* ao  = sym_addr(g_ao);

    const float scale = 1.0f / sqrtf(512.0f);

    // weight precompute (blade contraction folded into GEMM weights)
    {
        long long tq = 1024LL * 4096;
        make_weight<<<(unsigned)((tq + 255) / 256), 256>>>(w_q, blade, Wq2, 64, 512, 1, scale, tq, 4096);
        long long tk = 1024LL * 512;
        make_weight<<<(unsigned)((tk + 255) / 256), 256>>>(w_k, blade, Wk2, 64, 64, 2, 1.0f, tk, 512);
        long long tv = 1024LL * 1024;
        make_weight<<<(unsigned)((tv + 255) / 256), 256>>>(w_v, blade, Wv, 64, 64, 0, 1.0f, tv, 1024);
        long long to = 8192LL * 1024;
        make_weight<<<(unsigned)((to + 255) / 256), 256>>>(w_o, blade, Wo, 512, 64, 0, 1.0f, to, 1024);
    }

    // q projection (+IP gather +head permute +scale, all folded into Wq2)
    // qm[b*2048+n, h*512 + d*8+e]
    sgemm<0><<<dim3(4096 / 128, 4096 / 128, 1), 256>>>(
        x, Wq2, qm, 1024, 1024, 4096, 4096,
        0, 0, 0, 0, 0, 0, 1);

    // k projection (+IP gather): km[b*2048+n, d*8+e]
    sgemm<0><<<dim3(512 / 128, 4096 / 128, 1), 256>>>(
        x, Wk2, km, 1024, 1024, 512, 512,
        0, 0, 0, 0, 0, 0, 1);

    // v projection: v[b*2048+n, d*16+c]
    sgemm<0><<<dim3(1024 / 128, 4096 / 128, 1), 256>>>(
        x, Wv, v, 1024, 1024, 1024, 1024,
        0, 0, 0, 0, 0, 0, 1);

    // scores[b,h,q,k] = qm(b,h) @ km(b)^T   (scale already in qm)
    sgemm<1><<<dim3(2048 / 128, 2048 / 128, NB * NH), 256>>>(
        qm, km, sc, 512, 4096, 512, 2048,
        /*sAb*/ 2048LL * 4096, /*sAh*/ 512,
        /*sBb*/ 2048LL * 512,  /*sBh*/ 0,
        /*sCb*/ 8LL * 2048 * 2048, /*sCh*/ 2048LL * 2048, NH);

    // softmax over keys
    softmax_rows<<<NB * NH * 2048, 256>>>(sc, 2048);

    // out(b,h) = attn(b,h) @ vf(b); write directly into [b,n, h*1024 + f]
    sgemm<0><<<dim3(1024 / 128, 2048 / 128, NB * NH), 256>>>(
        sc, v, ao, 2048, 2048, 1024, 8192,
        /*sAb*/ 8LL * 2048 * 2048, /*sAh*/ 2048LL * 2048,
        /*sBb*/ 2048LL * 1024, /*sBh*/ 0,
        /*sCb*/ 2048LL * 8192, /*sCh*/ 1024, NH);

    // final projection: out[b*n, j*16+y] = ao @ Wo
    sgemm<0><<<dim3(1024 / 128, 4096 / 128, 1), 256>>>(
        ao, Wo, out, 8192, 8192, 1024, 1024,
        0, 0, 0, 0, 0, 0, 1);
}

// round 4
// speedup vs baseline: 2.7413x; 2.7413x over previous
#include <cuda_runtime.h>
#include <math.h>
#include <stdint.h>

// ---------------------------------------------------------------------------
// GeometricAttentionLayer on GB300 — tf32 mma.sync, 3xTF32 split precision
// Split (3-pass) GEMMs: q-proj, k-proj, v-proj, scores (softmax-amplified path)
// Single-pass GEMMs:    attn@V, out-proj (linear path, rel-err preserved)
// ---------------------------------------------------------------------------

#define BM 128
#define BN 128
#define BK 32
#define NSTAGE 3
#define STILE (BM * BK)
#define SMEM_1 (NSTAGE * 2 * STILE * 4)      // single kernel: 98304
#define SMEM_3 (2 * 4 * STILE * 4)           // split kernel:  131072

__constant__ int c_ip[8] = {0, 2, 3, 4, 8, 9, 10, 14};

// ------------------------- scratch (device globals) ------------------------
__device__ __align__(1024) float g_xh [4096LL * 1024];
__device__ __align__(1024) float g_xl [4096LL * 1024];
__device__ __align__(1024) float g_Wqh[4096 * 1024];
__device__ __align__(1024) float g_Wql[4096 * 1024];
__device__ __align__(1024) float g_Wkh[512 * 1024];
__device__ __align__(1024) float g_Wkl[512 * 1024];
__device__ __align__(1024) float g_Wvh[1024 * 1024];
__device__ __align__(1024) float g_Wvl[1024 * 1024];
__device__ __align__(1024) float g_Woh[1024 * 8192];
__device__ __align__(1024) float g_Wol[1024 * 8192];
__device__ __align__(1024) float g_qmh[4096LL * 4096];
__device__ __align__(1024) float g_qml[4096LL * 4096];
__device__ __align__(1024) float g_kmh[4096LL * 512];
__device__ __align__(1024) float g_kml[4096LL * 512];
__device__ __align__(1024) float g_vT [1024LL * 4096];
__device__ __align__(1024) float g_sc [16LL * 2048 * 2048];
__device__ __align__(1024) float g_ao [4096LL * 8192];

// ------------------------------ helpers ------------------------------------
__device__ __forceinline__ float to_tf32(float x) {
    float y;
    asm("cvt.rna.tf32.f32 %0, %1;" : "=f"(y) : "f"(x));
    return y;
}

__device__ __forceinline__ uint32_t smem_u32(const void* p) {
    uint32_t a;
    asm("{ .reg .u64 t; cvta.to.shared.u64 t, %1; cvt.u32.u64 %0, t; }" : "=r"(a) : "l"(p));
    return a;
}

__device__ __forceinline__ void cp16(uint32_t dst, const float* src) {
    asm volatile("cp.async.cg.shared.global [%0], [%1], 16;"
                 :: "r"(dst), "l"(src) : "memory");
}

#define MMA_TF32(acc, a, b)                                                   \
    asm volatile(                                                             \
        "mma.sync.aligned.m16n8k8.row.col.f32.tf32.tf32.f32 "                 \
        "{%0,%1,%2,%3}, {%4,%5,%6,%7}, {%8,%9}, {%0,%1,%2,%3};"               \
        : "+f"((acc)[0]), "+f"((acc)[1]), "+f"((acc)[2]), "+f"((acc)[3])      \
        : "r"((a)[0]), "r"((a)[1]), "r"((a)[2]), "r"((a)[3]),                 \
          "r"((b)[0]), "r"((b)[1]))

// ------------------------- weight precompute (split, transposed) -----------
__global__ void make_weightT(const float* __restrict__ w,
                             const float* __restrict__ blade,
                             float* __restrict__ Wh, float* __restrict__ Wl,
                             int I, int mode, float scale, long long total, int Kr)
{
    long long idx = (long long)blockIdx.x * 256 + threadIdx.x;
    if (idx >= total) return;
    int col = (int)(idx / Kr);
    int k   = (int)(idx % Kr);
    int i = k >> 4, xc = k & 15;
    int j, y;
    if (mode == 0)      { j = col >> 4; y = col & 15; }
    else if (mode == 1) { int e = col & 7; int d = (col >> 3) & 63; int h = col >> 9;
                          j = d * 8 + h; y = c_ip[e]; }
    else                { int e = col & 7; j = col >> 3; y = c_ip[e]; }
    float s = 0.f;
    #pragma unroll
    for (int b = 0; b < 9; b++)
        s += w[((long long)j * I + i) * 9 + b] * blade[b * 256 + xc * 16 + y];
    s *= scale;
    float hi = to_tf32(s);
    Wh[idx] = hi;
    Wl[idx] = to_tf32(s - hi);
}

// ------------------------------ tf32 split pass -----------------------------
__global__ void split_tf32(const float4* __restrict__ in,
                           float4* __restrict__ oh, float4* __restrict__ ol, int n4)
{
    int i = blockIdx.x * 256 + threadIdx.x;
    if (i >= n4) return;
    float4 v = in[i];
    float4 h, l;
    h.x = to_tf32(v.x); l.x = to_tf32(v.x - h.x);
    h.y = to_tf32(v.y); l.y = to_tf32(v.y - h.y);
    h.z = to_tf32(v.z); l.z = to_tf32(v.z - h.z);
    h.w = to_tf32(v.w); l.w = to_tf32(v.w - h.w);
    oh[i] = h;
    ol[i] = l;
}

// ------------------------------ single tf32 GEMM (NT) ----------------------
__global__ __launch_bounds__(256, 2) void gemm_mma(
    const float* __restrict__ Ag, const float* __restrict__ Bg, float* __restrict__ Cg,
    int K, int lda, int ldb, int ldc,
    long long aB, long long aH, long long bB, long long bH,
    long long cB, long long cH, int nH, int roundC)
{
    extern __shared__ float sm[];
    const uint32_t smb = smem_u32(sm);
    const uint32_t sA0 = smb;
    const uint32_t sB0 = smb + NSTAGE * STILE * 4;

    const int tid = threadIdx.x;
    const int bb = blockIdx.z / nH, hh = blockIdx.z - bb * nH;
    const float* A = Ag + bb * aB + hh * aH + (long long)(blockIdx.y * BM) * lda;
    const float* B = Bg + bb * bB + hh * bH + (long long)(blockIdx.x * BN) * ldb;

    const int ldrow = tid >> 3;
    const int ldcol = (tid & 7) << 2;
    uint32_t stoff[4];
    #pragma unroll
    for (int i = 0; i < 4; i++) {
        int row = ldrow + 32 * i;
        stoff[i] = (uint32_t)(row * BK + (ldcol ^ ((row & 7) << 2))) * 4;
    }

#define ISSUE1(base, G, ld, ch, slot) do {                                   \
        const float* _s = (G) + (long long)(ch) * BK + ldcol;                \
        uint32_t _d = (base) + (uint32_t)(slot) * (STILE * 4);               \
        _Pragma("unroll")                                                    \
        for (int _i = 0; _i < 4; _i++)                                       \
            cp16(_d + stoff[_i], _s + (long long)(ldrow + 32 * _i) * (ld));  \
    } while (0)

    const int lane = tid & 31;
    const int wm = ((tid >> 5) & 1) * 64;
    const int wn = (tid >> 6) * 32;
    const int qr = lane >> 2;
    const int qc = lane & 3;
    const int swz = qr << 2;

    float acc[4][4][4];
    #pragma unroll
    for (int mi = 0; mi < 4; mi++)
        #pragma unroll
        for (int ni = 0; ni < 4; ni++)
            #pragma unroll
            for (int q = 0; q < 4; q++) acc[mi][ni][q] = 0.f;

    const int nch = K >> 5;

    #pragma unroll
    for (int p = 0; p < NSTAGE - 1; p++) {
        if (p < nch) {
            ISSUE1(sA0, A, lda, p, p);
            ISSUE1(sB0, B, ldb, p, p);
        }
        asm volatile("cp.async.commit_group;" ::: "memory");
    }

    for (int ch = 0; ch < nch; ch++) {
        asm volatile("cp.async.wait_group 1;" ::: "memory");
        __syncthreads();

        int pf = ch + NSTAGE - 1;
        if (pf < nch) {
            int sl = pf % NSTAGE;
            ISSUE1(sA0, A, lda, pf, sl);
            ISSUE1(sB0, B, ldb, pf, sl);
        }
        asm volatile("cp.async.commit_group;" ::: "memory");

        const int slot = ch % NSTAGE;
        const float* tA = sm + slot * STILE;
        const float* tB = sm + NSTAGE * STILE + slot * STILE;

        #pragma unroll
        for (int kk = 0; kk < 4; kk++) {
            const int k0 = ((kk << 3) + qc) ^ swz;
            const int k1 = ((kk << 3) + qc + 4) ^ swz;
            uint32_t a[4][4], b[4][2];
            #pragma unroll
            for (int mi = 0; mi < 4; mi++) {
                int r = wm + mi * 16 + qr;
                a[mi][0] = __float_as_uint(tA[r * BK + k0]);
                a[mi][1] = __float_as_uint(tA[(r + 8) * BK + k0]);
                a[mi][2] = __float_as_uint(tA[r * BK + k1]);
                a[mi][3] = __float_as_uint(tA[(r + 8) * BK + k1]);
            }
            #pragma unroll
            for (int ni = 0; ni < 4; ni++) {
                int n = wn + ni * 8 + qr;
                b[ni][0] = __float_as_uint(tB[n * BK + k0]);
                b[ni][1] = __float_as_uint(tB[n * BK + k1]);
            }
            #pragma unroll
            for (int mi = 0; mi < 4; mi++)
                #pragma unroll
                for (int ni = 0; ni < 4; ni++)
                    MMA_TF32(acc[mi][ni], a[mi], b[ni]);
        }
    }
#undef ISSUE1

    float* Cb = Cg + bb * cB + hh * cH;
    const int rbase = blockIdx.y * BM + wm + qr;
    const int cbase = blockIdx.x * BN + wn + (qc << 1);
    #pragma unroll
    for (int mi = 0; mi < 4; mi++) {
        #pragma unroll
        for (int ni = 0; ni < 4; ni++) {
            float v0 = acc[mi][ni][0], v1 = acc[mi][ni][1];
            float v2 = acc[mi][ni][2], v3 = acc[mi][ni][3];
            if (roundC) {
                v0 = to_tf32(v0); v1 = to_tf32(v1);
                v2 = to_tf32(v2); v3 = to_tf32(v3);
            }
            const long long r = rbase + mi * 16;
            const int c = cbase + ni * 8;
            *reinterpret_cast<float2*>(&Cb[r * ldc + c])       = make_float2(v0, v1);
            *reinterpret_cast<float2*>(&Cb[(r + 8) * ldc + c]) = make_float2(v2, v3);
        }
    }
}

// ------------------------------ 3xTF32 split GEMM (NT) ---------------------
// acc += Ahi*Bhi + Ahi*Blo + Alo*Bhi  (fp32-quality)
// outmode: 0 = plain fp32 C, 1 = tf32-rounded C, 2 = split C (Ch, Cl)
__global__ __launch_bounds__(256, 1) void gemm_mma3(
    const float* __restrict__ Ah, const float* __restrict__ Al,
    const float* __restrict__ Bh, const float* __restrict__ Bl,
    float* __restrict__ Ch, float* __restrict__ Cl,
    int K, int lda, int ldb, int ldc,
    long long aB, long long aH, long long bB, long long bH,
    long long cB, long long cH, int nH, int outmode)
{
    extern __shared__ float sm[];
    const uint32_t smb = smem_u32(sm);

    const int tid = threadIdx.x;
    const int bb = blockIdx.z / nH, hh = blockIdx.z - bb * nH;
    const long long aOff = bb * aB + hh * aH + (long long)(blockIdx.y * BM) * lda;
    const long long bOff = bb * bB + hh * bH + (long long)(blockIdx.x * BN) * ldb;
    const float* pA[2] = {Ah + aOff, Al + aOff};
    const float* pB[2] = {Bh + bOff, Bl + bOff};

    const int ldrow = tid >> 3;
    const int ldcol = (tid & 7) << 2;
    uint32_t stoff[4];
    #pragma unroll
    for (int i = 0; i < 4; i++) {
        int row = ldrow + 32 * i;
        stoff[i] = (uint32_t)(row * BK + (ldcol ^ ((row & 7) << 2))) * 4;
    }

    // smem layout: [slot][tile] tile: 0=Ah 1=Al 2=Bh 3=Bl
#define TBASE(slot, t) (smb + ((slot) * 4 + (t)) * (STILE * 4))
#define ISSUE3(ch, slot) do {                                                 \
        _Pragma("unroll")                                                     \
        for (int _t = 0; _t < 4; _t++) {                                      \
            const float* _g = (_t < 2 ? pA[_t] : pB[_t - 2]);                 \
            const int _ld = (_t < 2 ? lda : ldb);                             \
            const float* _s = _g + (long long)(ch) * BK + ldcol;              \
            uint32_t _d = TBASE(slot, _t);                                    \
            _Pragma("unroll")                                                 \
            for (int _i = 0; _i < 4; _i++)                                    \
                cp16(_d + stoff[_i], _s + (long long)(ldrow + 32 * _i) * _ld);\
        }                                                                     \
    } while (0)

    const int lane = tid & 31;
    const int wm = ((tid >> 5) & 1) * 64;
    const int wn = (tid >> 6) * 32;
    const int qr = lane >> 2;
    const int qc = lane & 3;
    const int swz = qr << 2;

    float acc[4][4][4];
    #pragma unroll
    for (int mi = 0; mi < 4; mi++)
        #pragma unroll
        for (int ni = 0; ni < 4; ni++)
            #pragma unroll
            for (int q = 0; q < 4; q++) acc[mi][ni][q] = 0.f;

    const int nch = K >> 5;

    ISSUE3(0, 0);
    asm volatile("cp.async.commit_group;" ::: "memory");

    for (int ch = 0; ch < nch; ch++) {
        asm volatile("cp.async.wait_group 0;" ::: "memory");
        __syncthreads();
        if (ch + 1 < nch) {
            ISSUE3(ch + 1, (ch + 1) & 1);
            asm volatile("cp.async.commit_group;" ::: "memory");
        }

        const int slot = ch & 1;
        const float* tAh = sm + (slot * 4 + 0) * STILE;
        const float* tAl = sm + (slot * 4 + 1) * STILE;
        const float* tBh = sm + (slot * 4 + 2) * STILE;
        const float* tBl = sm + (slot * 4 + 3) * STILE;

        #pragma unroll
        for (int kk = 0; kk < 4; kk++) {
            const int k0 = ((kk << 3) + qc) ^ swz;
            const int k1 = ((kk << 3) + qc + 4) ^ swz;
            uint32_t ah[4][4], al[4][4], bh[4][2], bl[4][2];
            #pragma unroll
            for (int mi = 0; mi < 4; mi++) {
                int r = wm + mi * 16 + qr;
                ah[mi][0] = __float_as_uint(tAh[r * BK + k0]);
                ah[mi][1] = __float_as_uint(tAh[(r + 8) * BK + k0]);
                ah[mi][2] = __float_as_uint(tAh[r * BK + k1]);
                ah[mi][3] = __float_as_uint(tAh[(r + 8) * BK + k1]);
                al[mi][0] = __float_as_uint(tAl[r * BK + k0]);
                al[mi][1] = __float_as_uint(tAl[(r + 8) * BK + k0]);
                al[mi][2] = __float_as_uint(tAl[r * BK + k1]);
                al[mi][3] = __float_as_uint(tAl[(r + 8) * BK + k1]);
            }
            #pragma unroll
            for (int ni = 0; ni < 4; ni++) {
                int n = wn + ni * 8 + qr;
                bh[ni][0] = __float_as_uint(tBh[n * BK + k0]);
                bh[ni][1] = __float_as_uint(tBh[n * BK + k1]);
                bl[ni][0] = __float_as_uint(tBl[n * BK + k0]);
                bl[ni][1] = __float_as_uint(tBl[n * BK + k1]);
            }
            #pragma unroll
            for (int mi = 0; mi < 4; mi++)
                #pragma unroll
                for (int ni = 0; ni < 4; ni++) {
                    MMA_TF32(acc[mi][ni], ah[mi], bl[ni]);
                    MMA_TF32(acc[mi][ni], al[mi], bh[ni]);
                    MMA_TF32(acc[mi][ni], ah[mi], bh[ni]);
                }
        }
    }
#undef ISSUE3
#undef TBASE

    const long long cOff = bb * cB + hh * cH;
    const int rbase = blockIdx.y * BM + wm + qr;
    const int cbase = blockIdx.x * BN + wn + (qc << 1);
    #pragma unroll
    for (int mi = 0; mi < 4; mi++) {
        #pragma unroll
        for (int ni = 0; ni < 4; ni++) {
            const long long r = rbase + mi * 16;
            const int c = cbase + ni * 8;
            float v[4] = {acc[mi][ni][0], acc[mi][ni][1], acc[mi][ni][2], acc[mi][ni][3]};
            if (outmode == 2) {
                float h0 = to_tf32(v[0]), h1 = to_tf32(v[1]);
                float h2 = to_tf32(v[2]), h3 = to_tf32(v[3]);
                float* ch_ = Ch + cOff;
                float* cl_ = Cl + cOff;
                *reinterpret_cast<float2*>(&ch_[r * ldc + c])       = make_float2(h0, h1);
                *reinterpret_cast<float2*>(&ch_[(r + 8) * ldc + c]) = make_float2(h2, h3);
                *reinterpret_cast<float2*>(&cl_[r * ldc + c]) =
                    make_float2(to_tf32(v[0] - h0), to_tf32(v[1] - h1));
                *reinterpret_cast<float2*>(&cl_[(r + 8) * ldc + c]) =
                    make_float2(to_tf32(v[2] - h2), to_tf32(v[3] - h3));
            } else {
                if (outmode == 1) {
                    v[0] = to_tf32(v[0]); v[1] = to_tf32(v[1]);
                    v[2] = to_tf32(v[2]); v[3] = to_tf32(v[3]);
                }
                float* cb = Ch + cOff;
                *reinterpret_cast<float2*>(&cb[r * ldc + c])       = make_float2(v[0], v[1]);
                *reinterpret_cast<float2*>(&cb[(r + 8) * ldc + c]) = make_float2(v[2], v[3]);
            }
        }
    }
}

// ------------------------------ softmax (2048 cols) ------------------------
__global__ __launch_bounds__(256) void softmax2048(float* __restrict__ data)
{
    __shared__ float red[8];
    float4* p = reinterpret_cast<float4*>(data + (long long)blockIdx.x * 2048);
    const int t = threadIdx.x;
    const int wid = t >> 5, lid = t & 31;

    float4 a = p[t];
    float4 b = p[t + 256];

    float mx = fmaxf(fmaxf(fmaxf(a.x, a.y), fmaxf(a.z, a.w)),
                     fmaxf(fmaxf(b.x, b.y), fmaxf(b.z, b.w)));
    #pragma unroll
    for (int s = 16; s > 0; s >>= 1) mx = fmaxf(mx, __shfl_xor_sync(0xffffffffu, mx, s));
    if (lid == 0) red[wid] = mx;
    __syncthreads();
    if (t < 32) {
        float m = (t < 8) ? red[t] : -INFINITY;
        #pragma unroll
        for (int s = 4; s > 0; s >>= 1) m = fmaxf(m, __shfl_xor_sync(0xffffffffu, m, s));
        if (t == 0) red[0] = m;
    }
    __syncthreads();
    mx = red[0];
    __syncthreads();

    a.x = __expf(a.x - mx); a.y = __expf(a.y - mx); a.z = __expf(a.z - mx); a.w = __expf(a.w - mx);
    b.x = __expf(b.x - mx); b.y = __expf(b.y - mx); b.z = __expf(b.z - mx); b.w = __expf(b.w - mx);
    float sum = a.x + a.y + a.z + a.w + b.x + b.y + b.z + b.w;
    #pragma unroll
    for (int s = 16; s > 0; s >>= 1) sum += __shfl_xor_sync(0xffffffffu, sum, s);
    if (lid == 0) red[wid] = sum;
    __syncthreads();
    if (t < 32) {
        float m = (t < 8) ? red[t] : 0.f;
        #pragma unroll
        for (int s = 4; s > 0; s >>= 1) m += __shfl_xor_sync(0xffffffffu, m, s);
        if (t == 0) red[0] = m;
    }
    __syncthreads();
    float inv = 1.0f / red[0];

    a.x = to_tf32(a.x * inv); a.y = to_tf32(a.y * inv);
    a.z = to_tf32(a.z * inv); a.w = to_tf32(a.w * inv);
    b.x = to_tf32(b.x * inv); b.y = to_tf32(b.y * inv);
    b.z = to_tf32(b.z * inv); b.w = to_tf32(b.w * inv);
    p[t] = a;
    p[t + 256] = b;
}

// ------------------------------ host side ----------------------------------
static float* sym_addr(const void* symbol)
{
    void* p = nullptr;
    cudaGetSymbolAddress(&p, symbol);
    return (float*)p;
}

extern "C" void kernel_launch(void* const* d_in, const int* in_sizes, int n_in,
                              void* d_out, int out_size)
{
    const float* x     = (const float*)d_in[0];
    const float* blade = (const float*)d_in[1];
    const float* w_q   = (const float*)d_in[2];
    const float* w_k   = (const float*)d_in[3];
    const float* w_v   = (const float*)d_in[4];
    const float* w_o   = (const float*)d_in[5];
    float* out = (float*)d_out;

    float* xh  = sym_addr(g_xh),  *xl  = sym_addr(g_xl);
    float* Wqh = sym_addr(g_Wqh), *Wql = sym_addr(g_Wql);
    float* Wkh = sym_addr(g_Wkh), *Wkl = sym_addr(g_Wkl);
    float* Wvh = sym_addr(g_Wvh), *Wvl = sym_addr(g_Wvl);
    float* Woh = sym_addr(g_Woh), *Wol = sym_addr(g_Wol);
    float* qmh = sym_addr(g_qmh), *qml = sym_addr(g_qml);
    float* kmh = sym_addr(g_kmh), *kml = sym_addr(g_kml);
    float* vT  = sym_addr(g_vT);
    float* sc  = sym_addr(g_sc);
    float* ao  = sym_addr(g_ao);

    cudaFuncSetAttribute(gemm_mma,  cudaFuncAttributeMaxDynamicSharedMemorySize, SMEM_1);
    cudaFuncSetAttribute(gemm_mma3, cudaFuncAttributeMaxDynamicSharedMemorySize, SMEM_3);

    const float scale = 1.0f / sqrtf(512.0f);

    // ---- input split + weight precompute (split, transposed) ----
    split_tf32<<<4096, 256>>>((const float4*)x, (float4*)xh, (float4*)xl, 4096 * 1024 / 4);
    {
        long long tq = 4096LL * 1024;
        make_weightT<<<(unsigned)((tq + 255) / 256), 256>>>(w_q, blade, Wqh, Wql, 64, 1, scale, tq, 1024);
        long long tk = 512LL * 1024;
        make_weightT<<<(unsigned)((tk + 255) / 256), 256>>>(w_k, blade, Wkh, Wkl, 64, 2, 1.0f, tk, 1024);
        long long tv = 1024LL * 1024;
        make_weightT<<<(unsigned)((tv + 255) / 256), 256>>>(w_v, blade, Wvh, Wvl, 64, 0, 1.0f, tv, 1024);
        long long to = 1024LL * 8192;
        make_weightT<<<(unsigned)((to + 255) / 256), 256>>>(w_o, blade, Woh, Wol, 512, 0, 1.0f, to, 8192);
    }

    // ---- q projection (split in, split out): qm[m, h*512+d*8+e] ----
    gemm_mma3<<<dim3(32, 32, 1), 256, SMEM_3>>>(
        xh, xl, Wqh, Wql, qmh, qml, 1024, 1024, 1024, 4096,
        0, 0, 0, 0, 0, 0, 1, 2);

    // ---- k projection (split in, split out): km[m, d*8+e] ----
    gemm_mma3<<<dim3(4, 32, 1), 256, SMEM_3>>>(
        xh, xl, Wkh, Wkl, kmh, kml, 1024, 1024, 1024, 512,
        0, 0, 0, 0, 0, 0, 1, 2);

    // ---- v projection (split in, rounded out): vT[f, m] ----
    gemm_mma3<<<dim3(32, 8, 1), 256, SMEM_3>>>(
        Wvh, Wvl, xh, xl, vT, nullptr, 1024, 1024, 1024, 4096,
        0, 0, 0, 0, 0, 0, 1, 1);

    // ---- scores (split in, fp32 out): sc[b,h,q,k], scale folded into qm ----
    gemm_mma3<<<dim3(16, 16, 16), 256, SMEM_3>>>(
        qmh, qml, kmh, kml, sc, nullptr, 512, 4096, 512, 2048,
        /*aB*/ 2048LL * 4096, /*aH*/ 512,
        /*bB*/ 2048LL * 512,  /*bH*/ 0,
        /*cB*/ 8LL * 2048 * 2048, /*cH*/ 2048LL * 2048, 8, 0);

    // ---- softmax over keys (rounds probs to tf32) ----
    softmax2048<<<16 * 2048, 256>>>(sc);

    // ---- attn @ V (single): ao[b*n, h*1024+f], rounded out ----
    gemm_mma<<<dim3(8, 16, 16), 256, SMEM_1>>>(
        sc, vT, ao, 2048, 2048, 4096, 8192,
        /*aB*/ 8LL * 2048 * 2048, /*aH*/ 2048LL * 2048,
        /*bB*/ 2048, /*bH*/ 0,
        /*cB*/ 2048LL * 8192, /*cH*/ 1024, 8, 1);

    // ---- output projection (single): out = ao @ Woh^T ----
    gemm_mma<<<dim3(8, 32, 1), 256, SMEM_1>>>(
        ao, Woh, out, 8192, 8192, 8192, 1024,
        0, 0, 0, 0, 0, 0, 1, 0);
}

// round 5
// speedup vs baseline: 3.6087x; 1.3164x over previous
#include <cuda_runtime.h>
#include <cuda_fp16.h>
#include <math.h>
#include <stdint.h>

// ---------------------------------------------------------------------------
// GeometricAttentionLayer on GB300 — fp16 mma.sync (m16n8k16), split precision
//   fp16 mantissa == tf32 mantissa (11 bits), 2x the MMA throughput.
//   Split (3-pass) GEMMs: q-proj, k-proj, scores   (softmax-amplified path)
//   Single-pass GEMMs:    v-proj, attn@V, out-proj (linear path)
// ---------------------------------------------------------------------------

#define BM 128
#define BN 128
#define BK 32                                  // halves per K-chunk
#define TILEB 8192                             // 128 rows x 64 B
#define SMEM_1 (3 * 2 * TILEB)                 // 48 KB  (3-stage, 2 tiles)
#define SMEM_3 (3 * 4 * TILEB)                 // 96 KB  (3-stage, 4 tiles)

__constant__ int c_ip[8] = {0, 2, 3, 4, 8, 9, 10, 14};

// ------------------------- scratch (device globals) ------------------------
__device__ __align__(1024) __half g_xh [4096LL * 1024];
__device__ __align__(1024) __half g_xl [4096LL * 1024];
__device__ __align__(1024) __half g_Wqh[4096 * 1024];
__device__ __align__(1024) __half g_Wql[4096 * 1024];
__device__ __align__(1024) __half g_Wkh[512 * 1024];
__device__ __align__(1024) __half g_Wkl[512 * 1024];
__device__ __align__(1024) __half g_Wvh[1024 * 1024];
__device__ __align__(1024) __half g_Wvl[1024 * 1024];
__device__ __align__(1024) __half g_Woh[1024 * 8192];
__device__ __align__(1024) __half g_Wol[1024 * 8192];
__device__ __align__(1024) __half g_qmh[4096LL * 4096];
__device__ __align__(1024) __half g_qml[4096LL * 4096];
__device__ __align__(1024) __half g_kmh[4096LL * 512];
__device__ __align__(1024) __half g_kml[4096LL * 512];
__device__ __align__(1024) __half g_vT [1024LL * 4096];
__device__ __align__(1024) float  g_sc [16LL * 2048 * 2048];
__device__ __align__(1024) __half g_pr [16LL * 2048 * 2048];
__device__ __align__(1024) __half g_ao [4096LL * 8192];

// ------------------------------ helpers ------------------------------------
__device__ __forceinline__ uint32_t smem_u32(const void* p) {
    uint32_t a;
    asm("{ .reg .u64 t; cvta.to.shared.u64 t, %1; cvt.u32.u64 %0, t; }" : "=r"(a) : "l"(p));
    return a;
}

__device__ __forceinline__ void cp8(uint32_t dst, const __half* src) {
    asm volatile("cp.async.ca.shared.global [%0], [%1], 8;"
                 :: "r"(dst), "l"(src) : "memory");
}

// XOR-swizzled b32 load: logical (row r, 4B-word w in 0..15)
__device__ __forceinline__ uint32_t lds32(const char* tile, int r, int w) {
    int word = ((((w >> 1) ^ (r & 7)) << 1) | (w & 1));
    return *reinterpret_cast<const uint32_t*>(tile + r * 64 + word * 4);
}

#define MMA_F16(acc, a, b)                                                    \
    asm volatile(                                                             \
        "mma.sync.aligned.m16n8k16.row.col.f32.f16.f16.f32 "                  \
        "{%0,%1,%2,%3}, {%4,%5,%6,%7}, {%8,%9}, {%0,%1,%2,%3};"               \
        : "+f"((acc)[0]), "+f"((acc)[1]), "+f"((acc)[2]), "+f"((acc)[3])      \
        : "r"((a)[0]), "r"((a)[1]), "r"((a)[2]), "r"((a)[3]),                 \
          "r"((b)[0]), "r"((b)[1]))

// ------------------------- weight precompute (split, transposed) -----------
__global__ void make_weightT(const float* __restrict__ w,
                             const float* __restrict__ blade,
                             __half* __restrict__ Wh, __half* __restrict__ Wl,
                             int I, int mode, float scale, long long total, int Kr)
{
    long long idx = (long long)blockIdx.x * 256 + threadIdx.x;
    if (idx >= total) return;
    int col = (int)(idx / Kr);
    int k   = (int)(idx % Kr);
    int i = k >> 4, xc = k & 15;
    int j, y;
    if (mode == 0)      { j = col >> 4; y = col & 15; }
    else if (mode == 1) { int e = col & 7; int d = (col >> 3) & 63; int h = col >> 9;
                          j = d * 8 + h; y = c_ip[e]; }
    else                { int e = col & 7; j = col >> 3; y = c_ip[e]; }
    float s = 0.f;
    #pragma unroll
    for (int b = 0; b < 9; b++)
        s += w[((long long)j * I + i) * 9 + b] * blade[b * 256 + xc * 16 + y];
    s *= scale;
    __half hi = __float2half_rn(s);
    Wh[idx] = hi;
    Wl[idx] = __float2half_rn(s - __half2float(hi));
}

// ------------------------------ fp16 split pass ----------------------------
__global__ void split_f16(const float4* __restrict__ in,
                          __half2* __restrict__ oh, __half2* __restrict__ ol, int n4)
{
    int i = blockIdx.x * 256 + threadIdx.x;
    if (i >= n4) return;
    float4 v = in[i];
    __half hx = __float2half_rn(v.x), hy = __float2half_rn(v.y);
    __half hz = __float2half_rn(v.z), hw = __float2half_rn(v.w);
    oh[i * 2 + 0] = __halves2half2(hx, hy);
    oh[i * 2 + 1] = __halves2half2(hz, hw);
    ol[i * 2 + 0] = __halves2half2(__float2half_rn(v.x - __half2float(hx)),
                                   __float2half_rn(v.y - __half2float(hy)));
    ol[i * 2 + 1] = __halves2half2(__float2half_rn(v.z - __half2float(hz)),
                                   __float2half_rn(v.w - __half2float(hw)));
}

// ------------------------------ single fp16 GEMM (NT) ----------------------
// C[m,n] = sum_k A[m,k]*B[n,k].  halfout: 0 -> fp32 C, 1 -> half C.
__global__ __launch_bounds__(256, 2) void gemm_h1(
    const __half* __restrict__ Ag, const __half* __restrict__ Bg,
    float* __restrict__ Cf, __half* __restrict__ Chh,
    int K, int lda, int ldb, int ldc,
    long long aB, long long aH, long long bB, long long bH,
    long long cB, long long cH, int nH, int halfout)
{
    extern __shared__ char sm[];
    const uint32_t smb = smem_u32(sm);

    const int tid = threadIdx.x;
    const int bb = blockIdx.z / nH, hh = blockIdx.z - bb * nH;
    const __half* A = Ag + bb * aB + hh * aH + (long long)(blockIdx.y * BM) * lda;
    const __half* B = Bg + bb * bB + hh * bH + (long long)(blockIdx.x * BN) * ldb;

    const int ldrow = tid >> 3;           // 0..31
    const int seg   = tid & 7;            // 8B segment
    const uint32_t sseg = (uint32_t)((seg ^ (ldrow & 7)) << 3);
    uint32_t stoff[4];
    #pragma unroll
    for (int i = 0; i < 4; i++) stoff[i] = (uint32_t)((ldrow + 32 * i) * 64) + sseg;

#define ISSUE1(tbase, G, ld, ch, slot) do {                                   \
        const __half* _s = (G) + (long long)(ch) * BK + seg * 4;              \
        uint32_t _d = (tbase) + (uint32_t)(slot) * TILEB;                     \
        _Pragma("unroll")                                                     \
        for (int _i = 0; _i < 4; _i++)                                        \
            cp8(_d + stoff[_i], _s + (long long)(ldrow + 32 * _i) * (ld));    \
    } while (0)

    const int lane = tid & 31;
    const int wm = ((tid >> 5) & 1) * 64;
    const int wn = (tid >> 6) * 32;
    const int qr = lane >> 2;
    const int qc = lane & 3;

    float acc[4][4][4];
    #pragma unroll
    for (int mi = 0; mi < 4; mi++)
        #pragma unroll
        for (int ni = 0; ni < 4; ni++)
            #pragma unroll
            for (int q = 0; q < 4; q++) acc[mi][ni][q] = 0.f;

    const int nch = K >> 5;
    const uint32_t sA0 = smb, sB0 = smb + 3 * TILEB;

    #pragma unroll
    for (int p = 0; p < 2; p++) {
        if (p < nch) {
            ISSUE1(sA0, A, lda, p, p);
            ISSUE1(sB0, B, ldb, p, p);
        }
        asm volatile("cp.async.commit_group;" ::: "memory");
    }

    for (int ch = 0; ch < nch; ch++) {
        asm volatile("cp.async.wait_group 1;" ::: "memory");
        __syncthreads();

        int pf = ch + 2;
        if (pf < nch) {
            int sl = pf % 3;
            ISSUE1(sA0, A, lda, pf, sl);
            ISSUE1(sB0, B, ldb, pf, sl);
        }
        asm volatile("cp.async.commit_group;" ::: "memory");

        const int slot = ch % 3;
        const char* tA = sm + slot * TILEB;
        const char* tB = sm + (3 + slot) * TILEB;

        #pragma unroll
        for (int kk = 0; kk < 2; kk++) {
            const int w0 = (kk << 3) + qc;
            const int w2 = w0 + 4;
            uint32_t a[4][4], b[4][2];
            #pragma unroll
            for (int mi = 0; mi < 4; mi++) {
                int r = wm + mi * 16 + qr;
                a[mi][0] = lds32(tA, r, w0);
                a[mi][1] = lds32(tA, r + 8, w0);
                a[mi][2] = lds32(tA, r, w2);
                a[mi][3] = lds32(tA, r + 8, w2);
            }
            #pragma unroll
            for (int ni = 0; ni < 4; ni++) {
                int n = wn + ni * 8 + qr;
                b[ni][0] = lds32(tB, n, w0);
                b[ni][1] = lds32(tB, n, w2);
            }
            #pragma unroll
            for (int mi = 0; mi < 4; mi++)
                #pragma unroll
                for (int ni = 0; ni < 4; ni++)
                    MMA_F16(acc[mi][ni], a[mi], b[ni]);
        }
    }
#undef ISSUE1

    const long long cOff = bb * cB + hh * cH;
    const int rbase = blockIdx.y * BM + wm + qr;
    const int cbase = blockIdx.x * BN + wn + (qc << 1);
    #pragma unroll
    for (int mi = 0; mi < 4; mi++) {
        #pragma unroll
        for (int ni = 0; ni < 4; ni++) {
            const long long r = rbase + mi * 16;
            const int c = cbase + ni * 8;
            if (halfout) {
                __half* cb = Chh + cOff;
                *reinterpret_cast<__half2*>(&cb[r * ldc + c]) =
                    __halves2half2(__float2half_rn(acc[mi][ni][0]),
                                   __float2half_rn(acc[mi][ni][1]));
                *reinterpret_cast<__half2*>(&cb[(r + 8) * ldc + c]) =
                    __halves2half2(__float2half_rn(acc[mi][ni][2]),
                                   __float2half_rn(acc[mi][ni][3]));
            } else {
                float* cb = Cf + cOff;
                *reinterpret_cast<float2*>(&cb[r * ldc + c]) =
                    make_float2(acc[mi][ni][0], acc[mi][ni][1]);
                *reinterpret_cast<float2*>(&cb[(r + 8) * ldc + c]) =
                    make_float2(acc[mi][ni][2], acc[mi][ni][3]);
            }
        }
    }
}

// ------------------------------ 3-term fp16 split GEMM (NT) ----------------
// acc += Ahi*Bhi + Ahi*Blo + Alo*Bhi.  outmode: 0 -> fp32 C, 2 -> split half C.
__global__ __launch_bounds__(256, 1) void gemm_h3(
    const __half* __restrict__ Ah, const __half* __restrict__ Al,
    const __half* __restrict__ Bh, const __half* __restrict__ Bl,
    float* __restrict__ Cf, __half* __restrict__ Chh, __half* __restrict__ Chl,
    int K, int lda, int ldb, int ldc,
    long long aB, long long aH, long long bB, long long bH,
    long long cB, long long cH, int nH, int outmode)
{
    extern __shared__ char sm[];
    const uint32_t smb = smem_u32(sm);

    const int tid = threadIdx.x;
    const int bb = blockIdx.z / nH, hh = blockIdx.z - bb * nH;
    const long long aOff = bb * aB + hh * aH + (long long)(blockIdx.y * BM) * lda;
    const long long bOff = bb * bB + hh * bH + (long long)(blockIdx.x * BN) * ldb;
    const __half* pT[4] = {Ah + aOff, Al + aOff, Bh + bOff, Bl + bOff};

    const int ldrow = tid >> 3;
    const int seg   = tid & 7;
    const uint32_t sseg = (uint32_t)((seg ^ (ldrow & 7)) << 3);
    uint32_t stoff[4];
    #pragma unroll
    for (int i = 0; i < 4; i++) stoff[i] = (uint32_t)((ldrow + 32 * i) * 64) + sseg;

#define ISSUE3(ch, slot) do {                                                 \
        _Pragma("unroll")                                                     \
        for (int _t = 0; _t < 4; _t++) {                                      \
            const int _ld = (_t < 2 ? lda : ldb);                             \
            const __half* _s = pT[_t] + (long long)(ch) * BK + seg * 4;       \
            uint32_t _d = smb + ((uint32_t)(slot) * 4 + _t) * TILEB;          \
            _Pragma("unroll")                                                 \
            for (int _i = 0; _i < 4; _i++)                                    \
                cp8(_d + stoff[_i], _s + (long long)(ldrow + 32 * _i) * _ld); \
        }                                                                     \
    } while (0)

    const int lane = tid & 31;
    const int wm = ((tid >> 5) & 1) * 64;
    const int wn = (tid >> 6) * 32;
    const int qr = lane >> 2;
    const int qc = lane & 3;

    float acc[4][4][4];
    #pragma unroll
    for (int mi = 0; mi < 4; mi++)
        #pragma unroll
        for (int ni = 0; ni < 4; ni++)
            #pragma unroll
            for (int q = 0; q < 4; q++) acc[mi][ni][q] = 0.f;

    const int nch = K >> 5;

    #pragma unroll
    for (int p = 0; p < 2; p++) {
        if (p < nch) ISSUE3(p, p);
        asm volatile("cp.async.commit_group;" ::: "memory");
    }

    for (int ch = 0; ch < nch; ch++) {
        asm volatile("cp.async.wait_group 1;" ::: "memory");
        __syncthreads();

        int pf = ch + 2;
        if (pf < nch) ISSUE3(pf, pf % 3);
        asm volatile("cp.async.commit_group;" ::: "memory");

        const int slot = ch % 3;
        const char* tAh = sm + (slot * 4 + 0) * TILEB;
        const char* tAl = sm + (slot * 4 + 1) * TILEB;
        const char* tBh = sm + (slot * 4 + 2) * TILEB;
        const char* tBl = sm + (slot * 4 + 3) * TILEB;

        #pragma unroll
        for (int kk = 0; kk < 2; kk++) {
            const int w0 = (kk << 3) + qc;
            const int w2 = w0 + 4;
            uint32_t ah[4][4], al[4][4], bh[4][2], bl[4][2];
            #pragma unroll
            for (int mi = 0; mi < 4; mi++) {
                int r = wm + mi * 16 + qr;
                ah[mi][0] = lds32(tAh, r, w0);
                ah[mi][1] = lds32(tAh, r + 8, w0);
                ah[mi][2] = lds32(tAh, r, w2);
                ah[mi][3] = lds32(tAh, r + 8, w2);
                al[mi][0] = lds32(tAl, r, w0);
                al[mi][1] = lds32(tAl, r + 8, w0);
                al[mi][2] = lds32(tAl, r, w2);
                al[mi][3] = lds32(tAl, r + 8, w2);
            }
            #pragma unroll
            for (int ni = 0; ni < 4; ni++) {
                int n = wn + ni * 8 + qr;
                bh[ni][0] = lds32(tBh, n, w0);
                bh[ni][1] = lds32(tBh, n, w2);
                bl[ni][0] = lds32(tBl, n, w0);
                bl[ni][1] = lds32(tBl, n, w2);
            }
            #pragma unroll
            for (int mi = 0; mi < 4; mi++)
                #pragma unroll
                for (int ni = 0; ni < 4; ni++) {
                    MMA_F16(acc[mi][ni], ah[mi], bl[ni]);
                    MMA_F16(acc[mi][ni], al[mi], bh[ni]);
                    MMA_F16(acc[mi][ni], ah[mi], bh[ni]);
                }
        }
    }
#undef ISSUE3

    const long long cOff = bb * cB + hh * cH;
    const int rbase = blockIdx.y * BM + wm + qr;
    const int cbase = blockIdx.x * BN + wn + (qc << 1);
    #pragma unroll
    for (int mi = 0; mi < 4; mi++) {
        #pragma unroll
        for (int ni = 0; ni < 4; ni++) {
            const long long r = rbase + mi * 16;
            const int c = cbase + ni * 8;
            float v[4] = {acc[mi][ni][0], acc[mi][ni][1], acc[mi][ni][2], acc[mi][ni][3]};
            if (outmode == 2) {
                __half h0 = __float2half_rn(v[0]), h1 = __float2half_rn(v[1]);
                __half h2 = __float2half_rn(v[2]), h3 = __float2half_rn(v[3]);
                __half* ch_ = Chh + cOff;
                __half* cl_ = Chl + cOff;
                *reinterpret_cast<__half2*>(&ch_[r * ldc + c])       = __halves2half2(h0, h1);
                *reinterpret_cast<__half2*>(&ch_[(r + 8) * ldc + c]) = __halves2half2(h2, h3);
                *reinterpret_cast<__half2*>(&cl_[r * ldc + c]) =
                    __halves2half2(__float2half_rn(v[0] - __half2float(h0)),
                                   __float2half_rn(v[1] - __half2float(h1)));
                *reinterpret_cast<__half2*>(&cl_[(r + 8) * ldc + c]) =
                    __halves2half2(__float2half_rn(v[2] - __half2float(h2)),
                                   __float2half_rn(v[3] - __half2float(h3)));
            } else {
                float* cb = Cf + cOff;
                *reinterpret_cast<float2*>(&cb[r * ldc + c])       = make_float2(v[0], v[1]);
                *reinterpret_cast<float2*>(&cb[(r + 8) * ldc + c]) = make_float2(v[2], v[3]);
            }
        }
    }
}

// ------------------------- softmax (2048 cols, fp32 -> half) ---------------
__global__ __launch_bounds__(256) void softmax2048(const float* __restrict__ sc,
                                                   __half* __restrict__ pr)
{
    __shared__ float red[8];
    const float4* p = reinterpret_cast<const float4*>(sc + (long long)blockIdx.x * 2048);
    __half2* q = reinterpret_cast<__half2*>(pr + (long long)blockIdx.x * 2048);
    const int t = threadIdx.x;
    const int wid = t >> 5, lid = t & 31;

    float4 a = p[t];
    float4 b = p[t + 256];

    float mx = fmaxf(fmaxf(fmaxf(a.x, a.y), fmaxf(a.z, a.w)),
                     fmaxf(fmaxf(b.x, b.y), fmaxf(b.z, b.w)));
    #pragma unroll
    for (int s = 16; s > 0; s >>= 1) mx = fmaxf(mx, __shfl_xor_sync(0xffffffffu, mx, s));
    if (lid == 0) red[wid] = mx;
    __syncthreads();
    if (t < 32) {
        float m = (t < 8) ? red[t] : -INFINITY;
        #pragma unroll
        for (int s = 4; s > 0; s >>= 1) m = fmaxf(m, __shfl_xor_sync(0xffffffffu, m, s));
        if (t == 0) red[0] = m;
    }
    __syncthreads();
    mx = red[0];
    __syncthreads();

    a.x = __expf(a.x - mx); a.y = __expf(a.y - mx); a.z = __expf(a.z - mx); a.w = __expf(a.w - mx);
    b.x = __expf(b.x - mx); b.y = __expf(b.y - mx); b.z = __expf(b.z - mx); b.w = __expf(b.w - mx);
    float sum = a.x + a.y + a.z + a.w + b.x + b.y + b.z + b.w;
    #pragma unroll
    for (int s = 16; s > 0; s >>= 1) sum += __shfl_xor_sync(0xffffffffu, sum, s);
    if (lid == 0) red[wid] = sum;
    __syncthreads();
    if (t < 32) {
        float m = (t < 8) ? red[t] : 0.f;
        #pragma unroll
        for (int s = 4; s > 0; s >>= 1) m += __shfl_xor_sync(0xffffffffu, m, s);
        if (t == 0) red[0] = m;
    }
    __syncthreads();
    float inv = 1.0f / red[0];

    q[t * 2 + 0] = __halves2half2(__float2half_rn(a.x * inv), __float2half_rn(a.y * inv));
    q[t * 2 + 1] = __halves2half2(__float2half_rn(a.z * inv), __float2half_rn(a.w * inv));
    q[(t + 256) * 2 + 0] = __halves2half2(__float2half_rn(b.x * inv), __float2half_rn(b.y * inv));
    q[(t + 256) * 2 + 1] = __halves2half2(__float2half_rn(b.z * inv), __float2half_rn(b.w * inv));
}

// ------------------------------ host side ----------------------------------
template <typename T>
static T* sym_addr(const void* symbol)
{
    void* p = nullptr;
    cudaGetSymbolAddress(&p, symbol);
    return (T*)p;
}

extern "C" void kernel_launch(void* const* d_in, const int* in_sizes, int n_in,
                              void* d_out, int out_size)
{
    const float* x     = (const float*)d_in[0];
    const float* blade = (const float*)d_in[1];
    const float* w_q   = (const float*)d_in[2];
    const float* w_k   = (const float*)d_in[3];
    const float* w_v   = (const float*)d_in[4];
    const float* w_o   = (const float*)d_in[5];
    float* out = (float*)d_out;

    __half* xh  = sym_addr<__half>(g_xh),  *xl  = sym_addr<__half>(g_xl);
    __half* Wqh = sym_addr<__half>(g_Wqh), *Wql = sym_addr<__half>(g_Wql);
    __half* Wkh = sym_addr<__half>(g_Wkh), *Wkl = sym_addr<__half>(g_Wkl);
    __half* Wvh = sym_addr<__half>(g_Wvh), *Wvl = sym_addr<__half>(g_Wvl);
    __half* Woh = sym_addr<__half>(g_Woh), *Wol = sym_addr<__half>(g_Wol);
    __half* qmh = sym_addr<__half>(g_qmh), *qml = sym_addr<__half>(g_qml);
    __half* kmh = sym_addr<__half>(g_kmh), *kml = sym_addr<__half>(g_kml);
    __half* vT  = sym_addr<__half>(g_vT);
    float*  sc  = sym_addr<float >(g_sc);
    __half* pr  = sym_addr<__half>(g_pr);
    __half* ao  = sym_addr<__half>(g_ao);

    cudaFuncSetAttribute(gemm_h1, cudaFuncAttributeMaxDynamicSharedMemorySize, SMEM_1);
    cudaFuncSetAttribute(gemm_h3, cudaFuncAttributeMaxDynamicSharedMemorySize, SMEM_3);

    const float scale = 1.0f / sqrtf(512.0f);

    // ---- input split + weight precompute ----
    split_f16<<<4096, 256>>>((const float4*)x, (__half2*)xh, (__half2*)xl, 4096 * 1024 / 4);
    {
        long long tq = 4096LL * 1024;
        make_weightT<<<(unsigned)((tq + 255) / 256), 256>>>(w_q, blade, Wqh, Wql, 64, 1, scale, tq, 1024);
        long long tk = 512LL * 1024;
        make_weightT<<<(unsigned)((tk + 255) / 256), 256>>>(w_k, blade, Wkh, Wkl, 64, 2, 1.0f, tk, 1024);
        long long tv = 1024LL * 1024;
        make_weightT<<<(unsigned)((tv + 255) / 256), 256>>>(w_v, blade, Wvh, Wvl, 64, 0, 1.0f, tv, 1024);
        long long to = 1024LL * 8192;
        make_weightT<<<(unsigned)((to + 255) / 256), 256>>>(w_o, blade, Woh, Wol, 512, 0, 1.0f, to, 8192);
    }

    // ---- q projection (split in, split out): qm[m, h*512+d*8+e] ----
    gemm_h3<<<dim3(32, 32, 1), 256, SMEM_3>>>(
        xh, xl, Wqh, Wql, nullptr, qmh, qml, 1024, 1024, 1024, 4096,
        0, 0, 0, 0, 0, 0, 1, 2);

    // ---- k projection (split in, split out): km[m, d*8+e] ----
    gemm_h3<<<dim3(4, 32, 1), 256, SMEM_3>>>(
        xh, xl, Wkh, Wkl, nullptr, kmh, kml, 1024, 1024, 1024, 512,
        0, 0, 0, 0, 0, 0, 1, 2);

    // ---- v projection (single, half out): vT[f, m] ----
    gemm_h1<<<dim3(32, 8, 1), 256, SMEM_1>>>(
        Wvh, xh, nullptr, vT, 1024, 1024, 1024, 4096,
        0, 0, 0, 0, 0, 0, 1, 1);

    // ---- scores (split in, fp32 out): sc[b,h,q,k], scale folded into qm ----
    gemm_h3<<<dim3(16, 16, 16), 256, SMEM_3>>>(
        qmh, qml, kmh, kml, sc, nullptr, nullptr, 512, 4096, 512, 2048,
        /*aB*/ 2048LL * 4096, /*aH*/ 512,
        /*bB*/ 2048LL * 512,  /*bH*/ 0,
        /*cB*/ 8LL * 2048 * 2048, /*cH*/ 2048LL * 2048, 8, 0);

    // ---- softmax over keys (fp32 -> half probs) ----
    softmax2048<<<16 * 2048, 256>>>(sc, pr);

    // ---- attn @ V (single): ao[b*n, h*1024+f], half out ----
    gemm_h1<<<dim3(8, 16, 16), 256, SMEM_1>>>(
        pr, vT, nullptr, ao, 2048, 2048, 4096, 8192,
        /*aB*/ 8LL * 2048 * 2048, /*aH*/ 2048LL * 2048,
        /*bB*/ 2048, /*bH*/ 0,
        /*cB*/ 2048LL * 8192, /*cH*/ 1024, 8, 1);

    // ---- output projection (single): out = ao @ Woh^T, fp32 out ----
    gemm_h1<<<dim3(8, 32, 1), 256, SMEM_1>>>(
        ao, Woh, out, nullptr, 8192, 8192, 8192, 1024,
        0, 0, 0, 0, 0, 0, 1, 0);
}

// round 6
// speedup vs baseline: 5.2848x; 1.4645x over previous
#include <cuda_runtime.h>
#include <cuda_fp16.h>
#include <math.h>
#include <stdint.h>

// ---------------------------------------------------------------------------
// GeometricAttentionLayer on GB300 — fp16 mma.sync + ldmatrix engine
//   Split (3-pass) GEMMs: q-proj, k-proj, scores   (softmax-amplified path)
//   Single-pass GEMMs:    v-proj, attn@V, out-proj (linear path)
//   BK=64 halves (128B rows), SW128-style swizzle, ldmatrix.x4 fragments.
// ---------------------------------------------------------------------------

#define BM 128
#define BN 128
#define BK 64                                  // halves per K-chunk
#define TILEB 16384                            // 128 rows x 128 B
#define SMEM_1 (3 * 2 * TILEB)                 // 96 KB  (3-stage, 2 tiles)
#define SMEM_3 (3 * 4 * TILEB)                 // 192 KB (3-stage, 4 tiles)

__constant__ int c_ip[8] = {0, 2, 3, 4, 8, 9, 10, 14};

// ------------------------- scratch (device globals) ------------------------
__device__ __align__(1024) __half g_xh [4096LL * 1024];
__device__ __align__(1024) __half g_xl [4096LL * 1024];
__device__ __align__(1024) __half g_Wqh[4096 * 1024];
__device__ __align__(1024) __half g_Wql[4096 * 1024];
__device__ __align__(1024) __half g_Wkh[512 * 1024];
__device__ __align__(1024) __half g_Wkl[512 * 1024];
__device__ __align__(1024) __half g_Wvh[1024 * 1024];
__device__ __align__(1024) __half g_Wvl[1024 * 1024];
__device__ __align__(1024) __half g_Woh[1024 * 8192];
__device__ __align__(1024) __half g_Wol[1024 * 8192];
__device__ __align__(1024) __half g_qmh[4096LL * 4096];
__device__ __align__(1024) __half g_qml[4096LL * 4096];
__device__ __align__(1024) __half g_kmh[4096LL * 512];
__device__ __align__(1024) __half g_kml[4096LL * 512];
__device__ __align__(1024) __half g_vT [1024LL * 4096];
__device__ __align__(1024) float  g_sc [16LL * 2048 * 2048];
__device__ __align__(1024) __half g_pr [16LL * 2048 * 2048];
__device__ __align__(1024) __half g_ao [4096LL * 8192];

// ------------------------------ helpers ------------------------------------
__device__ __forceinline__ uint32_t smem_u32(const void* p) {
    uint32_t a;
    asm("{ .reg .u64 t; cvta.to.shared.u64 t, %1; cvt.u32.u64 %0, t; }" : "=r"(a) : "l"(p));
    return a;
}

__device__ __forceinline__ void cp16(uint32_t dst, const __half* src) {
    asm volatile("cp.async.cg.shared.global [%0], [%1], 16;"
                 :: "r"(dst), "l"(src) : "memory");
}

#define LDSM_X4(r0, r1, r2, r3, addr)                                         \
    asm volatile("ldmatrix.sync.aligned.m8n8.x4.shared.b16 {%0,%1,%2,%3}, [%4];" \
        : "=r"(r0), "=r"(r1), "=r"(r2), "=r"(r3) : "r"(addr))

#define MMA_F16(acc, a, b)                                                    \
    asm volatile(                                                             \
        "mma.sync.aligned.m16n8k16.row.col.f32.f16.f16.f32 "                  \
        "{%0,%1,%2,%3}, {%4,%5,%6,%7}, {%8,%9}, {%0,%1,%2,%3};"               \
        : "+f"((acc)[0]), "+f"((acc)[1]), "+f"((acc)[2]), "+f"((acc)[3])      \
        : "r"((a)[0]), "r"((a)[1]), "r"((a)[2]), "r"((a)[3]),                 \
          "r"((b)[0]), "r"((b)[1]))

// ------------------------- weight precompute (split, transposed) -----------
__global__ void make_weightT(const float* __restrict__ w,
                             const float* __restrict__ blade,
                             __half* __restrict__ Wh, __half* __restrict__ Wl,
                             int I, int mode, float scale, long long total, int Kr)
{
    long long idx = (long long)blockIdx.x * 256 + threadIdx.x;
    if (idx >= total) return;
    int col = (int)(idx / Kr);
    int k   = (int)(idx % Kr);
    int i = k >> 4, xc = k & 15;
    int j, y;
    if (mode == 0)      { j = col >> 4; y = col & 15; }
    else if (mode == 1) { int e = col & 7; int d = (col >> 3) & 63; int h = col >> 9;
                          j = d * 8 + h; y = c_ip[e]; }
    else                { int e = col & 7; j = col >> 3; y = c_ip[e]; }
    float s = 0.f;
    #pragma unroll
    for (int b = 0; b < 9; b++)
        s += w[((long long)j * I + i) * 9 + b] * blade[b * 256 + xc * 16 + y];
    s *= scale;
    __half hi = __float2half_rn(s);
    Wh[idx] = hi;
    Wl[idx] = __float2half_rn(s - __half2float(hi));
}

// ------------------------------ fp16 split pass ----------------------------
__global__ void split_f16(const float4* __restrict__ in,
                          __half2* __restrict__ oh, __half2* __restrict__ ol, int n4)
{
    int i = blockIdx.x * 256 + threadIdx.x;
    if (i >= n4) return;
    float4 v = in[i];
    __half hx = __float2half_rn(v.x), hy = __float2half_rn(v.y);
    __half hz = __float2half_rn(v.z), hw = __float2half_rn(v.w);
    oh[i * 2 + 0] = __halves2half2(hx, hy);
    oh[i * 2 + 1] = __halves2half2(hz, hw);
    ol[i * 2 + 0] = __halves2half2(__float2half_rn(v.x - __half2float(hx)),
                                   __float2half_rn(v.y - __half2float(hy)));
    ol[i * 2 + 1] = __halves2half2(__float2half_rn(v.z - __half2float(hz)),
                                   __float2half_rn(v.w - __half2float(hw)));
}

// ------------------------------ single fp16 GEMM (NT) ----------------------
// C[m,n] = sum_k A[m,k]*B[n,k].  halfout: 0 -> fp32 C, 1 -> half C.
__global__ __launch_bounds__(256, 2) void gemm_h1(
    const __half* __restrict__ Ag, const __half* __restrict__ Bg,
    float* __restrict__ Cf, __half* __restrict__ Chh,
    int K, int lda, int ldb, int ldc,
    long long aB, long long aH, long long bB, long long bH,
    long long cB, long long cH, int nH, int halfout)
{
    extern __shared__ char sm[];
    const uint32_t smb = smem_u32(sm);

    const int tid = threadIdx.x;
    const int bb = blockIdx.z / nH, hh = blockIdx.z - bb * nH;
    const __half* A = Ag + bb * aB + hh * aH + (long long)(blockIdx.y * BM) * lda;
    const __half* B = Bg + bb * bB + hh * bH + (long long)(blockIdx.x * BN) * ldb;

    // cp.async: thread t -> rows (t>>3)+32i, 16B chunk t&7, swizzled
    const int ldrow = tid >> 3;
    const int seg   = tid & 7;
    const uint32_t swoff = (uint32_t)((seg ^ (ldrow & 7)) << 4);
    uint32_t stoff[4];
    #pragma unroll
    for (int i = 0; i < 4; i++) stoff[i] = (uint32_t)((ldrow + 32 * i) * 128) + swoff;

#define ISSUE1(tbase, G, ld, ch, slot) do {                                   \
        const __half* _s = (G) + (long long)(ch) * BK + (seg << 3);           \
        uint32_t _d = (tbase) + (uint32_t)(slot) * TILEB;                     \
        _Pragma("unroll")                                                     \
        for (int _i = 0; _i < 4; _i++)                                        \
            cp16(_d + stoff[_i], _s + (long long)(ldrow + 32 * _i) * (ld));   \
    } while (0)

    const int lane = tid & 31;
    const int wm = ((tid >> 5) & 1) * 64;
    const int wn = (tid >> 6) * 32;
    const int qr = lane >> 2;
    const int qc = lane & 3;
    const int l7 = lane & 7;
    // ldmatrix per-lane row/chunk decomposition
    const uint32_t aRow = (uint32_t)(wm + (lane & 15)) * 128;
    const int aCb = lane >> 4;
    const uint32_t bRow = (uint32_t)(wn + l7 + ((lane >> 4) << 3)) * 128;
    const int bCb = (lane >> 3) & 1;

    float acc[4][4][4];
    #pragma unroll
    for (int mi = 0; mi < 4; mi++)
        #pragma unroll
        for (int ni = 0; ni < 4; ni++)
            #pragma unroll
            for (int q = 0; q < 4; q++) acc[mi][ni][q] = 0.f;

    const int nch = K >> 6;
    const uint32_t sA0 = smb, sB0 = smb + 3 * TILEB;

    #pragma unroll
    for (int p = 0; p < 2; p++) {
        if (p < nch) {
            ISSUE1(sA0, A, lda, p, p);
            ISSUE1(sB0, B, ldb, p, p);
        }
        asm volatile("cp.async.commit_group;" ::: "memory");
    }

    for (int ch = 0; ch < nch; ch++) {
        asm volatile("cp.async.wait_group 1;" ::: "memory");
        __syncthreads();

        int pf = ch + 2;
        if (pf < nch) {
            int sl = pf % 3;
            ISSUE1(sA0, A, lda, pf, sl);
            ISSUE1(sB0, B, ldb, pf, sl);
        }
        asm volatile("cp.async.commit_group;" ::: "memory");

        const int slot = ch % 3;
        const uint32_t tA = sA0 + slot * TILEB + aRow;
        const uint32_t tB = sB0 + slot * TILEB + bRow;

        #pragma unroll
        for (int kk = 0; kk < 4; kk++) {
            const uint32_t aC = (uint32_t)((((kk << 1) + aCb) ^ l7) << 4);
            const uint32_t bC = (uint32_t)((((kk << 1) + bCb) ^ l7) << 4);
            uint32_t a[4][4], b[4][2];
            #pragma unroll
            for (int mi = 0; mi < 4; mi++)
                LDSM_X4(a[mi][0], a[mi][1], a[mi][2], a[mi][3], tA + mi * 2048 + aC);
            #pragma unroll
            for (int g = 0; g < 2; g++)
                LDSM_X4(b[2*g][0], b[2*g][1], b[2*g+1][0], b[2*g+1][1], tB + g * 2048 + bC);
            #pragma unroll
            for (int mi = 0; mi < 4; mi++)
                #pragma unroll
                for (int ni = 0; ni < 4; ni++)
                    MMA_F16(acc[mi][ni], a[mi], b[ni]);
        }
    }
#undef ISSUE1

    const long long cOff = bb * cB + hh * cH;
    const int rbase = blockIdx.y * BM + wm + qr;
    const int cbase = blockIdx.x * BN + wn + (qc << 1);
    #pragma unroll
    for (int mi = 0; mi < 4; mi++) {
        #pragma unroll
        for (int ni = 0; ni < 4; ni++) {
            const long long r = rbase + mi * 16;
            const int c = cbase + ni * 8;
            if (halfout) {
                __half* cb = Chh + cOff;
                *reinterpret_cast<__half2*>(&cb[r * ldc + c]) =
                    __halves2half2(__float2half_rn(acc[mi][ni][0]),
                                   __float2half_rn(acc[mi][ni][1]));
                *reinterpret_cast<__half2*>(&cb[(r + 8) * ldc + c]) =
                    __halves2half2(__float2half_rn(acc[mi][ni][2]),
                                   __float2half_rn(acc[mi][ni][3]));
            } else {
                float* cb = Cf + cOff;
                *reinterpret_cast<float2*>(&cb[r * ldc + c]) =
                    make_float2(acc[mi][ni][0], acc[mi][ni][1]);
                *reinterpret_cast<float2*>(&cb[(r + 8) * ldc + c]) =
                    make_float2(acc[mi][ni][2], acc[mi][ni][3]);
            }
        }
    }
}

// ------------------------------ 3-term fp16 split GEMM (NT) ----------------
// acc += Ahi*Bhi + Ahi*Blo + Alo*Bhi.  outmode: 0 -> fp32 C, 2 -> split half C.
__global__ __launch_bounds__(256, 1) void gemm_h3(
    const __half* __restrict__ Ah, const __half* __restrict__ Al,
    const __half* __restrict__ Bh, const __half* __restrict__ Bl,
    float* __restrict__ Cf, __half* __restrict__ Chh, __half* __restrict__ Chl,
    int K, int lda, int ldb, int ldc,
    long long aB, long long aH, long long bB, long long bH,
    long long cB, long long cH, int nH, int outmode)
{
    extern __shared__ char sm[];
    const uint32_t smb = smem_u32(sm);

    const int tid = threadIdx.x;
    const int bb = blockIdx.z / nH, hh = blockIdx.z - bb * nH;
    const long long aOff = bb * aB + hh * aH + (long long)(blockIdx.y * BM) * lda;
    const long long bOff = bb * bB + hh * bH + (long long)(blockIdx.x * BN) * ldb;
    const __half* pT[4] = {Ah + aOff, Al + aOff, Bh + bOff, Bl + bOff};

    const int ldrow = tid >> 3;
    const int seg   = tid & 7;
    const uint32_t swoff = (uint32_t)((seg ^ (ldrow & 7)) << 4);
    uint32_t stoff[4];
    #pragma unroll
    for (int i = 0; i < 4; i++) stoff[i] = (uint32_t)((ldrow + 32 * i) * 128) + swoff;

#define ISSUE3(ch, slot) do {                                                 \
        _Pragma("unroll")                                                     \
        for (int _t = 0; _t < 4; _t++) {                                      \
            const int _ld = (_t < 2 ? lda : ldb);                             \
            const __half* _s = pT[_t] + (long long)(ch) * BK + (seg << 3);    \
            uint32_t _d = smb + ((uint32_t)(slot) * 4 + _t) * TILEB;          \
            _Pragma("unroll")                                                 \
            for (int _i = 0; _i < 4; _i++)                                    \
                cp16(_d + stoff[_i], _s + (long long)(ldrow + 32 * _i) * _ld);\
        }                                                                     \
    } while (0)

    const int lane = tid & 31;
    const int wm = ((tid >> 5) & 1) * 64;
    const int wn = (tid >> 6) * 32;
    const int qr = lane >> 2;
    const int qc = lane & 3;
    const int l7 = lane & 7;
    const uint32_t aRow = (uint32_t)(wm + (lane & 15)) * 128;
    const int aCb = lane >> 4;
    const uint32_t bRow = (uint32_t)(wn + l7 + ((lane >> 4) << 3)) * 128;
    const int bCb = (lane >> 3) & 1;

    float acc[4][4][4];
    #pragma unroll
    for (int mi = 0; mi < 4; mi++)
        #pragma unroll
        for (int ni = 0; ni < 4; ni++)
            #pragma unroll
            for (int q = 0; q < 4; q++) acc[mi][ni][q] = 0.f;

    const int nch = K >> 6;

    #pragma unroll
    for (int p = 0; p < 2; p++) {
        if (p < nch) ISSUE3(p, p);
        asm volatile("cp.async.commit_group;" ::: "memory");
    }

    for (int ch = 0; ch < nch; ch++) {
        asm volatile("cp.async.wait_group 1;" ::: "memory");
        __syncthreads();

        int pf = ch + 2;
        if (pf < nch) ISSUE3(pf, pf % 3);
        asm volatile("cp.async.commit_group;" ::: "memory");

        const int slot = ch % 3;
        const uint32_t tAh = smb + (slot * 4 + 0) * TILEB + aRow;
        const uint32_t tAl = smb + (slot * 4 + 1) * TILEB + aRow;
        const uint32_t tBh = smb + (slot * 4 + 2) * TILEB + bRow;
        const uint32_t tBl = smb + (slot * 4 + 3) * TILEB + bRow;

        #pragma unroll
        for (int kk = 0; kk < 4; kk++) {
            const uint32_t aC = (uint32_t)((((kk << 1) + aCb) ^ l7) << 4);
            const uint32_t bC = (uint32_t)((((kk << 1) + bCb) ^ l7) << 4);
            uint32_t ah[4][4], al[4][4], bh[4][2], bl[4][2];
            #pragma unroll
            for (int mi = 0; mi < 4; mi++) {
                LDSM_X4(ah[mi][0], ah[mi][1], ah[mi][2], ah[mi][3], tAh + mi * 2048 + aC);
                LDSM_X4(al[mi][0], al[mi][1], al[mi][2], al[mi][3], tAl + mi * 2048 + aC);
            }
            #pragma unroll
            for (int g = 0; g < 2; g++) {
                LDSM_X4(bh[2*g][0], bh[2*g][1], bh[2*g+1][0], bh[2*g+1][1], tBh + g * 2048 + bC);
                LDSM_X4(bl[2*g][0], bl[2*g][1], bl[2*g+1][0], bl[2*g+1][1], tBl + g * 2048 + bC);
            }
            #pragma unroll
            for (int mi = 0; mi < 4; mi++)
                #pragma unroll
                for (int ni = 0; ni < 4; ni++) {
                    MMA_F16(acc[mi][ni], ah[mi], bl[ni]);
                    MMA_F16(acc[mi][ni], al[mi], bh[ni]);
                    MMA_F16(acc[mi][ni], ah[mi], bh[ni]);
                }
        }
    }
#undef ISSUE3

    const long long cOff = bb * cB + hh * cH;
    const int rbase = blockIdx.y * BM + wm + qr;
    const int cbase = blockIdx.x * BN + wn + (qc << 1);
    #pragma unroll
    for (int mi = 0; mi < 4; mi++) {
        #pragma unroll
        for (int ni = 0; ni < 4; ni++) {
            const long long r = rbase + mi * 16;
            const int c = cbase + ni * 8;
            float v[4] = {acc[mi][ni][0], acc[mi][ni][1], acc[mi][ni][2], acc[mi][ni][3]};
            if (outmode == 2) {
                __half h0 = __float2half_rn(v[0]), h1 = __float2half_rn(v[1]);
                __half h2 = __float2half_rn(v[2]), h3 = __float2half_rn(v[3]);
                __half* ch_ = Chh + cOff;
                __half* cl_ = Chl + cOff;
                *reinterpret_cast<__half2*>(&ch_[r * ldc + c])       = __halves2half2(h0, h1);
                *reinterpret_cast<__half2*>(&ch_[(r + 8) * ldc + c]) = __halves2half2(h2, h3);
                *reinterpret_cast<__half2*>(&cl_[r * ldc + c]) =
                    __halves2half2(__float2half_rn(v[0] - __half2float(h0)),
                                   __float2half_rn(v[1] - __half2float(h1)));
                *reinterpret_cast<__half2*>(&cl_[(r + 8) * ldc + c]) =
                    __halves2half2(__float2half_rn(v[2] - __half2float(h2)),
                                   __float2half_rn(v[3] - __half2float(h3)));
            } else {
                float* cb = Cf + cOff;
                *reinterpret_cast<float2*>(&cb[r * ldc + c])       = make_float2(v[0], v[1]);
                *reinterpret_cast<float2*>(&cb[(r + 8) * ldc + c]) = make_float2(v[2], v[3]);
            }
        }
    }
}

// ------------------------- softmax (2048 cols, fp32 -> half) ---------------
__global__ __launch_bounds__(256) void softmax2048(const float* __restrict__ sc,
                                                   __half* __restrict__ pr)
{
    __shared__ float red[8];
    const float4* p = reinterpret_cast<const float4*>(sc + (long long)blockIdx.x * 2048);
    __half2* q = reinterpret_cast<__half2*>(pr + (long long)blockIdx.x * 2048);
    const int t = threadIdx.x;
    const int wid = t >> 5, lid = t & 31;

    float4 a = p[t];
    float4 b = p[t + 256];

    float mx = fmaxf(fmaxf(fmaxf(a.x, a.y), fmaxf(a.z, a.w)),
                     fmaxf(fmaxf(b.x, b.y), fmaxf(b.z, b.w)));
    #pragma unroll
    for (int s = 16; s > 0; s >>= 1) mx = fmaxf(mx, __shfl_xor_sync(0xffffffffu, mx, s));
    if (lid == 0) red[wid] = mx;
    __syncthreads();
    if (t < 32) {
        float m = (t < 8) ? red[t] : -INFINITY;
        #pragma unroll
        for (int s = 4; s > 0; s >>= 1) m = fmaxf(m, __shfl_xor_sync(0xffffffffu, m, s));
        if (t == 0) red[0] = m;
    }
    __syncthreads();
    mx = red[0];
    __syncthreads();

    a.x = __expf(a.x - mx); a.y = __expf(a.y - mx); a.z = __expf(a.z - mx); a.w = __expf(a.w - mx);
    b.x = __expf(b.x - mx); b.y = __expf(b.y - mx); b.z = __expf(b.z - mx); b.w = __expf(b.w - mx);
    float sum = a.x + a.y + a.z + a.w + b.x + b.y + b.z + b.w;
    #pragma unroll
    for (int s = 16; s > 0; s >>= 1) sum += __shfl_xor_sync(0xffffffffu, sum, s);
    if (lid == 0) red[wid] = sum;
    __syncthreads();
    if (t < 32) {
        float m = (t < 8) ? red[t] : 0.f;
        #pragma unroll
        for (int s = 4; s > 0; s >>= 1) m += __shfl_xor_sync(0xffffffffu, m, s);
        if (t == 0) red[0] = m;
    }
    __syncthreads();
    float inv = 1.0f / red[0];

    q[t * 2 + 0] = __halves2half2(__float2half_rn(a.x * inv), __float2half_rn(a.y * inv));
    q[t * 2 + 1] = __halves2half2(__float2half_rn(a.z * inv), __float2half_rn(a.w * inv));
    q[(t + 256) * 2 + 0] = __halves2half2(__float2half_rn(b.x * inv), __float2half_rn(b.y * inv));
    q[(t + 256) * 2 + 1] = __halves2half2(__float2half_rn(b.z * inv), __float2half_rn(b.w * inv));
}

// ------------------------------ host side ----------------------------------
template <typename T>
static T* sym_addr(const void* symbol)
{
    void* p = nullptr;
    cudaGetSymbolAddress(&p, symbol);
    return (T*)p;
}

extern "C" void kernel_launch(void* const* d_in, const int* in_sizes, int n_in,
                              void* d_out, int out_size)
{
    const float* x     = (const float*)d_in[0];
    const float* blade = (const float*)d_in[1];
    const float* w_q   = (const float*)d_in[2];
    const float* w_k   = (const float*)d_in[3];
    const float* w_v   = (const float*)d_in[4];
    const float* w_o   = (const float*)d_in[5];
    float* out = (float*)d_out;

    __half* xh  = sym_addr<__half>(g_xh),  *xl  = sym_addr<__half>(g_xl);
    __half* Wqh = sym_addr<__half>(g_Wqh), *Wql = sym_addr<__half>(g_Wql);
    __half* Wkh = sym_addr<__half>(g_Wkh), *Wkl = sym_addr<__half>(g_Wkl);
    __half* Wvh = sym_addr<__half>(g_Wvh), *Wvl = sym_addr<__half>(g_Wvl);
    __half* Woh = sym_addr<__half>(g_Woh), *Wol = sym_addr<__half>(g_Wol);
    __half* qmh = sym_addr<__half>(g_qmh), *qml = sym_addr<__half>(g_qml);
    __half* kmh = sym_addr<__half>(g_kmh), *kml = sym_addr<__half>(g_kml);
    __half* vT  = sym_addr<__half>(g_vT);
    float*  sc  = sym_addr<float >(g_sc);
    __half* pr  = sym_addr<__half>(g_pr);
    __half* ao  = sym_addr<__half>(g_ao);

    cudaFuncSetAttribute(gemm_h1, cudaFuncAttributeMaxDynamicSharedMemorySize, SMEM_1);
    cudaFuncSetAttribute(gemm_h3, cudaFuncAttributeMaxDynamicSharedMemorySize, SMEM_3);

    const float scale = 1.0f / sqrtf(512.0f);

    // ---- input split + weight precompute ----
    split_f16<<<4096, 256>>>((const float4*)x, (__half2*)xh, (__half2*)xl, 4096 * 1024 / 4);
    {
        long long tq = 4096LL * 1024;
        make_weightT<<<(unsigned)((tq + 255) / 256), 256>>>(w_q, blade, Wqh, Wql, 64, 1, scale, tq, 1024);
        long long tk = 512LL * 1024;
        make_weightT<<<(unsigned)((tk + 255) / 256), 256>>>(w_k, blade, Wkh, Wkl, 64, 2, 1.0f, tk, 1024);
        long long tv = 1024LL * 1024;
        make_weightT<<<(unsigned)((tv + 255) / 256), 256>>>(w_v, blade, Wvh, Wvl, 64, 0, 1.0f, tv, 1024);
        long long to = 1024LL * 8192;
        make_weightT<<<(unsigned)((to + 255) / 256), 256>>>(w_o, blade, Woh, Wol, 512, 0, 1.0f, to, 8192);
    }

    // ---- q projection (split in, split out): qm[m, h*512+d*8+e] ----
    gemm_h3<<<dim3(32, 32, 1), 256, SMEM_3>>>(
        xh, xl, Wqh, Wql, nullptr, qmh, qml, 1024, 1024, 1024, 4096,
        0, 0, 0, 0, 0, 0, 1, 2);

    // ---- k projection (split in, split out): km[m, d*8+e] ----
    gemm_h3<<<dim3(4, 32, 1), 256, SMEM_3>>>(
        xh, xl, Wkh, Wkl, nullptr, kmh, kml, 1024, 1024, 1024, 512,
        0, 0, 0, 0, 0, 0, 1, 2);

    // ---- v projection (single, half out): vT[f, m] ----
    gemm_h1<<<dim3(32, 8, 1), 256, SMEM_1>>>(
        Wvh, xh, nullptr, vT, 1024, 1024, 1024, 4096,
        0, 0, 0, 0, 0, 0, 1, 1);

    // ---- scores (split in, fp32 out): sc[b,h,q,k], scale folded into qm ----
    gemm_h3<<<dim3(16, 16, 16), 256, SMEM_3>>>(
        qmh, qml, kmh, kml, sc, nullptr, nullptr, 512, 4096, 512, 2048,
        /*aB*/ 2048LL * 4096, /*aH*/ 512,
        /*bB*/ 2048LL * 512,  /*bH*/ 0,
        /*cB*/ 8LL * 2048 * 2048, /*cH*/ 2048LL * 2048, 8, 0);

    // ---- softmax over keys (fp32 -> half probs) ----
    softmax2048<<<16 * 2048, 256>>>(sc, pr);

    // ---- attn @ V (single): ao[b*n, h*1024+f], half out ----
    gemm_h1<<<dim3(8, 16, 16), 256, SMEM_1>>>(
        pr, vT, nullptr, ao, 2048, 2048, 4096, 8192,
        /*aB*/ 8LL * 2048 * 2048, /*aH*/ 2048LL * 2048,
        /*bB*/ 2048, /*bH*/ 0,
        /*cB*/ 2048LL * 8192, /*cH*/ 1024, 8, 1);

    // ---- output projection (single): out = ao @ Woh^T, fp32 out ----
    gemm_h1<<<dim3(8, 32, 1), 256, SMEM_1>>>(
        ao, Woh, out, nullptr, 8192, 8192, 8192, 1024,
        0, 0, 0, 0, 0, 0, 1, 0);
}

// round 8
// speedup vs baseline: 5.4164x; 1.0249x over previous
#include <cuda_runtime.h>
#include <cuda_fp16.h>
#include <math.h>
#include <stdint.h>

// ---------------------------------------------------------------------------
// GeometricAttentionLayer on GB300 — fp16 mma.sync + ldmatrix engine v2
//   CTA tile 256x128, warp tile 64x64 (8 warps, 1 CTA/SM), BK=64.
//   Split (3-pass) GEMMs: q+k proj (merged), scores.
//   Single-pass GEMMs:    v-proj, attn@V, out-proj.
// ---------------------------------------------------------------------------

#define BM 256
#define BN 128
#define BK 64
#define ATILE 32768                       // 256 rows x 128 B
#define BTILE 16384                       // 128 rows x 128 B
#define ST1 (ATILE + BTILE)               // 48 KB / stage
#define SMEM_1 (3 * ST1)                  // 144 KB
#define ST3 (2 * ATILE + 2 * BTILE)       // 96 KB / stage
#define SMEM_3 (2 * ST3)                  // 192 KB

__constant__ int c_ip[8] = {0, 2, 3, 4, 8, 9, 10, 14};

// ------------------------- scratch (device globals) ------------------------
__device__ __align__(1024) __half g_xh  [4096LL * 1024];
__device__ __align__(1024) __half g_xl  [4096LL * 1024];
__device__ __align__(1024) __half g_Wqkh[4608 * 1024];       // q cols 0..4095, k cols 4096..4607
__device__ __align__(1024) __half g_Wqkl[4608 * 1024];
__device__ __align__(1024) __half g_Wvh [1024 * 1024];
__device__ __align__(1024) __half g_Woh [1024 * 8192];
__device__ __align__(1024) __half g_qkmh[4096LL * 4608];     // [token, h*512+d*8+e | 4096+d*8+e]
__device__ __align__(1024) __half g_qkml[4096LL * 4608];
__device__ __align__(1024) __half g_vT  [1024LL * 4096];
__device__ __align__(1024) float  g_sc  [16LL * 2048 * 2048];
__device__ __align__(1024) __half g_pr  [16LL * 2048 * 2048];
__device__ __align__(1024) __half g_ao  [4096LL * 8192];

// ------------------------------ helpers ------------------------------------
__device__ __forceinline__ uint32_t smem_u32(const void* p) {
    uint32_t a;
    asm("{ .reg .u64 t; cvta.to.shared.u64 t, %1; cvt.u32.u64 %0, t; }" : "=r"(a) : "l"(p));
    return a;
}

__device__ __forceinline__ void cp16(uint32_t dst, const __half* src) {
    asm volatile("cp.async.cg.shared.global [%0], [%1], 16;"
                 :: "r"(dst), "l"(src) : "memory");
}

#define LDSM_X4(r0, r1, r2, r3, addr)                                         \
    asm volatile("ldmatrix.sync.aligned.m8n8.x4.shared.b16 {%0,%1,%2,%3}, [%4];" \
        : "=r"(r0), "=r"(r1), "=r"(r2), "=r"(r3) : "r"(addr))

#define MMA_F16(acc, a, b)                                                    \
    asm volatile(                                                             \
        "mma.sync.aligned.m16n8k16.row.col.f32.f16.f16.f32 "                  \
        "{%0,%1,%2,%3}, {%4,%5,%6,%7}, {%8,%9}, {%0,%1,%2,%3};"               \
        : "+f"((acc)[0]), "+f"((acc)[1]), "+f"((acc)[2]), "+f"((acc)[3])      \
        : "r"((a)[0]), "r"((a)[1]), "r"((a)[2]), "r"((a)[3]),                 \
          "r"((b)[0]), "r"((b)[1]))

// ------------------------- weight precompute (split, transposed) -----------
__global__ void make_weightT(const float* __restrict__ w,
                             const float* __restrict__ blade,
                             __half* __restrict__ Wh, __half* __restrict__ Wl,
                             int I, int mode, float scale, long long total, int Kr,
                             int storeLo)
{
    long long idx = (long long)blockIdx.x * 256 + threadIdx.x;
    if (idx >= total) return;
    int col = (int)(idx / Kr);
    int k   = (int)(idx % Kr);
    int i = k >> 4, xc = k & 15;
    int j, y;
    if (mode == 0)      { j = col >> 4; y = col & 15; }
    else if (mode == 1) { int e = col & 7; int d = (col >> 3) & 63; int h = col >> 9;
                          j = d * 8 + h; y = c_ip[e]; }
    else                { int e = col & 7; j = col >> 3; y = c_ip[e]; }
    float s = 0.f;
    #pragma unroll
    for (int b = 0; b < 9; b++)
        s += w[((long long)j * I + i) * 9 + b] * blade[b * 256 + xc * 16 + y];
    s *= scale;
    __half hi = __float2half_rn(s);
    Wh[idx] = hi;
    if (storeLo)
        Wl[idx] = __float2half_rn(s - __half2float(hi));
}

// ------------------------------ fp16 split pass ----------------------------
__global__ void split_f16(const float4* __restrict__ in,
                          __half2* __restrict__ oh, __half2* __restrict__ ol, int n4)
{
    int i = blockIdx.x * 256 + threadIdx.x;
    if (i >= n4) return;
    float4 v = in[i];
    __half hx = __float2half_rn(v.x), hy = __float2half_rn(v.y);
    __half hz = __float2half_rn(v.z), hw = __float2half_rn(v.w);
    oh[i * 2 + 0] = __halves2half2(hx, hy);
    oh[i * 2 + 1] = __halves2half2(hz, hw);
    ol[i * 2 + 0] = __halves2half2(__float2half_rn(v.x - __half2float(hx)),
                                   __float2half_rn(v.y - __half2float(hy)));
    ol[i * 2 + 1] = __halves2half2(__float2half_rn(v.z - __half2float(hz)),
                                   __float2half_rn(v.w - __half2float(hw)));
}

// ------------------------------ single fp16 GEMM (NT) ----------------------
// C[m,n] = sum_k A[m,k]*B[n,k].  halfout: 0 -> fp32 C, 1 -> half C.
__global__ __launch_bounds__(256, 1) void gemm_h1(
    const __half* __restrict__ Ag, const __half* __restrict__ Bg,
    float* __restrict__ Cf, __half* __restrict__ Chh,
    int K, int lda, int ldb, int ldc,
    long long aB, long long aH, long long bB, long long bH,
    long long cB, long long cH, int nH, int halfout)
{
    extern __shared__ char sm[];
    const uint32_t smb = smem_u32(sm);

    const int tid = threadIdx.x;
    const int bb = blockIdx.z / nH, hh = blockIdx.z - bb * nH;
    const __half* A = Ag + bb * aB + hh * aH + (long long)(blockIdx.y * BM) * lda;
    const __half* B = Bg + bb * bB + hh * bH + (long long)(blockIdx.x * BN) * ldb;

    const int ldrow = tid >> 3;
    const int seg   = tid & 7;
    const uint32_t swoff = (uint32_t)((seg ^ (ldrow & 7)) << 4);

#define ISSUE1(ch, slot) do {                                                 \
        const __half* _a = A + (long long)(ch) * BK + (seg << 3);             \
        uint32_t _da = smb + (uint32_t)(slot) * ST1;                          \
        _Pragma("unroll")                                                     \
        for (int _i = 0; _i < 8; _i++)                                        \
            cp16(_da + (uint32_t)((ldrow + 32 * _i) * 128) + swoff,           \
                 _a + (long long)(ldrow + 32 * _i) * lda);                    \
        const __half* _b = B + (long long)(ch) * BK + (seg << 3);             \
        uint32_t _db = smb + (uint32_t)(slot) * ST1 + ATILE;                  \
        _Pragma("unroll")                                                     \
        for (int _i = 0; _i < 4; _i++)                                        \
            cp16(_db + (uint32_t)((ldrow + 32 * _i) * 128) + swoff,           \
                 _b + (long long)(ldrow + 32 * _i) * ldb);                    \
    } while (0)

    const int lane = tid & 31;
    const int wid = tid >> 5;
    const int wm = (wid & 3) * 64;
    const int wn = (wid >> 2) * 64;
    const int qr = lane >> 2;
    const int qc = lane & 3;
    const int l7 = lane & 7;
    const uint32_t aRow = (uint32_t)(wm + (lane & 15)) * 128;
    const int aCb = lane >> 4;
    const uint32_t bRow = (uint32_t)(wn + l7 + ((lane >> 4) << 3)) * 128;
    const int bCb = (lane >> 3) & 1;

    float acc[4][8][4];
    #pragma unroll
    for (int mi = 0; mi < 4; mi++)
        #pragma unroll
        for (int ni = 0; ni < 8; ni++)
            #pragma unroll
            for (int q = 0; q < 4; q++) acc[mi][ni][q] = 0.f;

    const int nch = K >> 6;

    #pragma unroll
    for (int p = 0; p < 2; p++) {
        if (p < nch) ISSUE1(p, p);
        asm volatile("cp.async.commit_group;" ::: "memory");
    }

    for (int ch = 0; ch < nch; ch++) {
        asm volatile("cp.async.wait_group 1;" ::: "memory");
        __syncthreads();

        int pf = ch + 2;
        if (pf < nch) ISSUE1(pf, pf % 3);
        asm volatile("cp.async.commit_group;" ::: "memory");

        const int slot = ch % 3;
        const uint32_t tA = smb + slot * ST1 + aRow;
        const uint32_t tB = smb + slot * ST1 + ATILE + bRow;

        #pragma unroll
        for (int kk = 0; kk < 4; kk++) {
            const uint32_t aC = (uint32_t)((((kk << 1) + aCb) ^ l7) << 4);
            const uint32_t bC = (uint32_t)((((kk << 1) + bCb) ^ l7) << 4);
            uint32_t a[4][4], b[8][2];
            #pragma unroll
            for (int mi = 0; mi < 4; mi++)
                LDSM_X4(a[mi][0], a[mi][1], a[mi][2], a[mi][3], tA + mi * 2048 + aC);
            #pragma unroll
            for (int g = 0; g < 4; g++)
                LDSM_X4(b[2*g][0], b[2*g][1], b[2*g+1][0], b[2*g+1][1], tB + g * 2048 + bC);
            #pragma unroll
            for (int mi = 0; mi < 4; mi++)
                #pragma unroll
                for (int ni = 0; ni < 8; ni++)
                    MMA_F16(acc[mi][ni], a[mi], b[ni]);
        }
    }
#undef ISSUE1

    const long long cOff = bb * cB + hh * cH;
    const int rbase = blockIdx.y * BM + wm + qr;
    const int cbase = blockIdx.x * BN + wn + (qc << 1);
    #pragma unroll
    for (int mi = 0; mi < 4; mi++) {
        #pragma unroll
        for (int ni = 0; ni < 8; ni++) {
            const long long r = rbase + mi * 16;
            const int c = cbase + ni * 8;
            if (halfout) {
                __half* cb = Chh + cOff;
                *reinterpret_cast<__half2*>(&cb[r * ldc + c]) =
                    __halves2half2(__float2half_rn(acc[mi][ni][0]),
                                   __float2half_rn(acc[mi][ni][1]));
                *reinterpret_cast<__half2*>(&cb[(r + 8) * ldc + c]) =
                    __halves2half2(__float2half_rn(acc[mi][ni][2]),
                                   __float2half_rn(acc[mi][ni][3]));
            } else {
                float* cb = Cf + cOff;
                *reinterpret_cast<float2*>(&cb[r * ldc + c]) =
                    make_float2(acc[mi][ni][0], acc[mi][ni][1]);
                *reinterpret_cast<float2*>(&cb[(r + 8) * ldc + c]) =
                    make_float2(acc[mi][ni][2], acc[mi][ni][3]);
            }
        }
    }
}

// ------------------------------ 3-term fp16 split GEMM (NT) ----------------
// acc += Ahi*Bhi + Ahi*Blo + Alo*Bhi.  outmode: 0 -> fp32 C, 2 -> split half C.
__global__ __launch_bounds__(256, 1) void gemm_h3(
    const __half* __restrict__ Ah, const __half* __restrict__ Al,
    const __half* __restrict__ Bh, const __half* __restrict__ Bl,
    float* __restrict__ Cf, __half* __restrict__ Chh, __half* __restrict__ Chl,
    int K, int lda, int ldb, int ldc,
    long long aB, long long aH, long long bB, long long bH,
    long long cB, long long cH, int nH, int outmode)
{
    extern __shared__ char sm[];
    const uint32_t smb = smem_u32(sm);

    const int tid = threadIdx.x;
    const int bb = blockIdx.z / nH, hh = blockIdx.z - bb * nH;
    const long long aOff = bb * aB + hh * aH + (long long)(blockIdx.y * BM) * lda;
    const long long bOff = bb * bB + hh * bH + (long long)(blockIdx.x * BN) * ldb;
    const __half* pAh = Ah + aOff;
    const __half* pAl = Al + aOff;
    const __half* pBh = Bh + bOff;
    const __half* pBl = Bl + bOff;

    const int ldrow = tid >> 3;
    const int seg   = tid & 7;
    const uint32_t swoff = (uint32_t)((seg ^ (ldrow & 7)) << 4);

#define ISSUE3(ch, slot) do {                                                 \
        uint32_t _sb = smb + (uint32_t)(slot) * ST3;                          \
        const __half* _s0 = pAh + (long long)(ch) * BK + (seg << 3);          \
        const __half* _s1 = pAl + (long long)(ch) * BK + (seg << 3);          \
        _Pragma("unroll")                                                     \
        for (int _i = 0; _i < 8; _i++) {                                      \
            uint32_t _o = (uint32_t)((ldrow + 32 * _i) * 128) + swoff;        \
            long long _g = (long long)(ldrow + 32 * _i) * lda;                \
            cp16(_sb + _o, _s0 + _g);                                         \
            cp16(_sb + ATILE + _o, _s1 + _g);                                 \
        }                                                                     \
        const __half* _s2 = pBh + (long long)(ch) * BK + (seg << 3);          \
        const __half* _s3 = pBl + (long long)(ch) * BK + (seg << 3);          \
        _Pragma("unroll")                                                     \
        for (int _i = 0; _i < 4; _i++) {                                      \
            uint32_t _o = (uint32_t)((ldrow + 32 * _i) * 128) + swoff;        \
            long long _g = (long long)(ldrow + 32 * _i) * ldb;                \
            cp16(_sb + 2 * ATILE + _o, _s2 + _g);                             \
            cp16(_sb + 2 * ATILE + BTILE + _o, _s3 + _g);                     \
        }                                                                     \
    } while (0)

    const int lane = tid & 31;
    const int wid = tid >> 5;
    const int wm = (wid & 3) * 64;
    const int wn = (wid >> 2) * 64;
    const int qr = lane >> 2;
    const int qc = lane & 3;
    const int l7 = lane & 7;
    const uint32_t aRow = (uint32_t)(wm + (lane & 15)) * 128;
    const int aCb = lane >> 4;
    const uint32_t bRow = (uint32_t)(wn + l7 + ((lane >> 4) << 3)) * 128;
    const int bCb = (lane >> 3) & 1;

    float acc[4][8][4];
    #pragma unroll
    for (int mi = 0; mi < 4; mi++)
        #pragma unroll
        for (int ni = 0; ni < 8; ni++)
            #pragma unroll
            for (int q = 0; q < 4; q++) acc[mi][ni][q] = 0.f;

    const int nch = K >> 6;

    ISSUE3(0, 0);
    asm volatile("cp.async.commit_group;" ::: "memory");

    for (int ch = 0; ch < nch; ch++) {
        asm volatile("cp.async.wait_group 0;" ::: "memory");
        __syncthreads();
        if (ch + 1 < nch) {
            ISSUE3(ch + 1, (ch + 1) & 1);
            asm volatile("cp.async.commit_group;" ::: "memory");
        }

        const int slot = ch & 1;
        const uint32_t tAh = smb + slot * ST3 + aRow;
        const uint32_t tAl = smb + slot * ST3 + ATILE + aRow;
        const uint32_t tBh = smb + slot * ST3 + 2 * ATILE + bRow;
        const uint32_t tBl = smb + slot * ST3 + 2 * ATILE + BTILE + bRow;

        #pragma unroll
        for (int kk = 0; kk < 4; kk++) {
            const uint32_t aC = (uint32_t)((((kk << 1) + aCb) ^ l7) << 4);
            const uint32_t bC = (uint32_t)((((kk << 1) + bCb) ^ l7) << 4);
            uint32_t ah[4][4], al[4][4], bh[8][2], bl[8][2];
            #pragma unroll
            for (int mi = 0; mi < 4; mi++) {
                LDSM_X4(ah[mi][0], ah[mi][1], ah[mi][2], ah[mi][3], tAh + mi * 2048 + aC);
                LDSM_X4(al[mi][0], al[mi][1], al[mi][2], al[mi][3], tAl + mi * 2048 + aC);
            }
            #pragma unroll
            for (int g = 0; g < 4; g++) {
                LDSM_X4(bh[2*g][0], bh[2*g][1], bh[2*g+1][0], bh[2*g+1][1], tBh + g * 2048 + bC);
                LDSM_X4(bl[2*g][0], bl[2*g][1], bl[2*g+1][0], bl[2*g+1][1], tBl + g * 2048 + bC);
            }
            #pragma unroll
            for (int mi = 0; mi < 4; mi++)
                #pragma unroll
                for (int ni = 0; ni < 8; ni++) {
                    MMA_F16(acc[mi][ni], ah[mi], bl[ni]);
                    MMA_F16(acc[mi][ni], al[mi], bh[ni]);
                    MMA_F16(acc[mi][ni], ah[mi], bh[ni]);
                }
        }
    }
#undef ISSUE3

    const long long cOff = bb * cB + hh * cH;
    const int rbase = blockIdx.y * BM + wm + qr;
    const int cbase = blockIdx.x * BN + wn + (qc << 1);
    #pragma unroll
    for (int mi = 0; mi < 4; mi++) {
        #pragma unroll
        for (int ni = 0; ni < 8; ni++) {
            const long long r = rbase + mi * 16;
            const int c = cbase + ni * 8;
            float v[4] = {acc[mi][ni][0], acc[mi][ni][1], acc[mi][ni][2], acc[mi][ni][3]};
            if (outmode == 2) {
                __half h0 = __float2half_rn(v[0]), h1 = __float2half_rn(v[1]);
                __half h2 = __float2half_rn(v[2]), h3 = __float2half_rn(v[3]);
                __half* ch_ = Chh + cOff;
                __half* cl_ = Chl + cOff;
                *reinterpret_cast<__half2*>(&ch_[r * ldc + c])       = __halves2half2(h0, h1);
                *reinterpret_cast<__half2*>(&ch_[(r + 8) * ldc + c]) = __halves2half2(h2, h3);
                *reinterpret_cast<__half2*>(&cl_[r * ldc + c]) =
                    __halves2half2(__float2half_rn(v[0] - __half2float(h0)),
                                   __float2half_rn(v[1] - __half2float(h1)));
                *reinterpret_cast<__half2*>(&cl_[(r + 8) * ldc + c]) =
                    __halves2half2(__float2half_rn(v[2] - __half2float(h2)),
                                   __float2half_rn(v[3] - __half2float(h3)));
            } else {
                float* cb = Cf + cOff;
                *reinterpret_cast<float2*>(&cb[r * ldc + c])       = make_float2(v[0], v[1]);
                *reinterpret_cast<float2*>(&cb[(r + 8) * ldc + c]) = make_float2(v[2], v[3]);
            }
        }
    }
}

// ------------------------- softmax (2048 cols, fp32 -> half) ---------------
__global__ __launch_bounds__(256) void softmax2048(const float* __restrict__ sc,
                                                   __half* __restrict__ pr)
{
    __shared__ float red[8];
    const float4* p = reinterpret_cast<const float4*>(sc + (long long)blockIdx.x * 2048);
    __half2* q = reinterpret_cast<__half2*>(pr + (long long)blockIdx.x * 2048);
    const int t = threadIdx.x;
    const int wid = t >> 5, lid = t & 31;

    float4 a = p[t];
    float4 b = p[t + 256];

    float mx = fmaxf(fmaxf(fmaxf(a.x, a.y), fmaxf(a.z, a.w)),
                     fmaxf(fmaxf(b.x, b.y), fmaxf(b.z, b.w)));
    #pragma unroll
    for (int s = 16; s > 0; s >>= 1) mx = fmaxf(mx, __shfl_xor_sync(0xffffffffu, mx, s));
    if (lid == 0) red[wid] = mx;
    __syncthreads();
    if (t < 32) {
        float m = (t < 8) ? red[t] : -INFINITY;
        #pragma unroll
        for (int s = 4; s > 0; s >>= 1) m = fmaxf(m, __shfl_xor_sync(0xffffffffu, m, s));
        if (t == 0) red[0] = m;
    }
    __syncthreads();
    mx = red[0];
    __syncthreads();

    a.x = __expf(a.x - mx); a.y = __expf(a.y - mx); a.z = __expf(a.z - mx); a.w = __expf(a.w - mx);
    b.x = __expf(b.x - mx); b.y = __expf(b.y - mx); b.z = __expf(b.z - mx); b.w = __expf(b.w - mx);
    float sum = a.x + a.y + a.z + a.w + b.x + b.y + b.z + b.w;
    #pragma unroll
    for (int s = 16; s > 0; s >>= 1) sum += __shfl_xor_sync(0xffffffffu, sum, s);
    if (lid == 0) red[wid] = sum;
    __syncthreads();
    if (t < 32) {
        float m = (t < 8) ? red[t] : 0.f;
        #pragma unroll
        for (int s = 4; s > 0; s >>= 1) m += __shfl_xor_sync(0xffffffffu, m, s);
        if (t == 0) red[0] = m;
    }
    __syncthreads();
    float inv = 1.0f / red[0];

    q[t * 2 + 0] = __halves2half2(__float2half_rn(a.x * inv), __float2half_rn(a.y * inv));
    q[t * 2 + 1] = __halves2half2(__float2half_rn(a.z * inv), __float2half_rn(a.w * inv));
    q[(t + 256) * 2 + 0] = __halves2half2(__float2half_rn(b.x * inv), __float2half_rn(b.y * inv));
    q[(t + 256) * 2 + 1] = __halves2half2(__float2half_rn(b.z * inv), __float2half_rn(b.w * inv));
}

// ------------------------------ host side ----------------------------------
template <typename T>
static T* sym_addr(const void* symbol)
{
    void* p = nullptr;
    cudaGetSymbolAddress(&p, symbol);
    return (T*)p;
}

extern "C" void kernel_launch(void* const* d_in, const int* in_sizes, int n_in,
                              void* d_out, int out_size)
{
    const float* x     = (const float*)d_in[0];
    const float* blade = (const float*)d_in[1];
    const float* w_q   = (const float*)d_in[2];
    const float* w_k   = (const float*)d_in[3];
    const float* w_v   = (const float*)d_in[4];
    const float* w_o   = (const float*)d_in[5];
    float* out = (float*)d_out;

    __half* xh   = sym_addr<__half>(g_xh),   *xl   = sym_addr<__half>(g_xl);
    __half* Wqkh = sym_addr<__half>(g_Wqkh), *Wqkl = sym_addr<__half>(g_Wqkl);
    __half* Wvh  = sym_addr<__half>(g_Wvh);
    __half* Woh  = sym_addr<__half>(g_Woh);
    __half* qkmh = sym_addr<__half>(g_qkmh), *qkml = sym_addr<__half>(g_qkml);
    __half* vT   = sym_addr<__half>(g_vT);
    float*  sc   = sym_addr<float >(g_sc);
    __half* pr   = sym_addr<__half>(g_pr);
    __half* ao   = sym_addr<__half>(g_ao);

    cudaFuncSetAttribute(gemm_h1, cudaFuncAttributeMaxDynamicSharedMemorySize, SMEM_1);
    cudaFuncSetAttribute(gemm_h3, cudaFuncAttributeMaxDynamicSharedMemorySize, SMEM_3);

    const float scale = 1.0f / sqrtf(512.0f);

    // ---- input split + weight precompute ----
    split_f16<<<4096, 256>>>((const float4*)x, (__half2*)xh, (__half2*)xl, 4096 * 1024 / 4);
    {
        long long tq = 4096LL * 1024;   // q part of combined weight (cols 0..4095)
        make_weightT<<<(unsigned)((tq + 255) / 256), 256>>>(
            w_q, blade, Wqkh, Wqkl, 64, 1, scale, tq, 1024, 1);
        long long tk = 512LL * 1024;    // k part (cols 4096..4607)
        make_weightT<<<(unsigned)((tk + 255) / 256), 256>>>(
            w_k, blade, Wqkh + 4096LL * 1024, Wqkl + 4096LL * 1024, 64, 2, 1.0f, tk, 1024, 1);
        long long tv = 1024LL * 1024;   // v weight, hi only
        make_weightT<<<(unsigned)((tv + 255) / 256), 256>>>(
            w_v, blade, Wvh, nullptr, 64, 0, 1.0f, tv, 1024, 0);
        long long to = 1024LL * 8192;   // o weight, hi only
        make_weightT<<<(unsigned)((to + 255) / 256), 256>>>(
            w_o, blade, Woh, nullptr, 512, 0, 1.0f, to, 8192, 0);
    }

    // ---- q+k projection (split in, split out): qkm[m, 0..4607] ----
    gemm_h3<<<dim3(4608 / 128, 4096 / 256, 1), 256, SMEM_3>>>(
        xh, xl, Wqkh, Wqkl, nullptr, qkmh, qkml, 1024, 1024, 1024, 4608,
        0, 0, 0, 0, 0, 0, 1, 2);

    // ---- v projection (single, half out): vT[f, m] ----
    gemm_h1<<<dim3(4096 / 128, 1024 / 256, 1), 256, SMEM_1>>>(
        Wvh, xh, nullptr, vT, 1024, 1024, 1024, 4096,
        0, 0, 0, 0, 0, 0, 1, 1);

    // ---- scores (split in, fp32 out): sc[b,h,q,k]; km = cols 4096.. of qkm ----
    gemm_h3<<<dim3(2048 / 128, 2048 / 256, 16), 256, SMEM_3>>>(
        qkmh, qkml, qkmh + 4096, qkml + 4096, sc, nullptr, nullptr,
        512, 4608, 4608, 2048,
        /*aB*/ 2048LL * 4608, /*aH*/ 512,
        /*bB*/ 2048LL * 4608, /*bH*/ 0,
        /*cB*/ 8LL * 2048 * 2048, /*cH*/ 2048LL * 2048, 8, 0);

    // ---- softmax over keys (fp32 -> half probs) ----
    softmax2048<<<16 * 2048, 256>>>(sc, pr);

    // ---- attn @ V (single): ao[b*n, h*1024+f], half out ----
    gemm_h1<<<dim3(1024 / 128, 2048 / 256, 16), 256, SMEM_1>>>(
        pr, vT, nullptr, ao, 2048, 2048, 4096, 8192,
        /*aB*/ 8LL * 2048 * 2048, /*aH*/ 2048LL * 2048,
        /*bB*/ 2048, /*bH*/ 0,
        /*cB*/ 2048LL * 8192, /*cH*/ 1024, 8, 1);

    // ---- output projection (single): out = ao @ Woh^T, fp32 out ----
    gemm_h1<<<dim3(1024 / 128, 4096 / 256, 1), 256, SMEM_1>>>(
        ao, Woh, out, nullptr, 8192, 8192, 8192, 1024,
        0, 0, 0, 0, 0, 0, 1, 0);
}

// round 9
// speedup vs baseline: 5.4431x; 1.0049x over previous
#include <cuda_runtime.h>
#include <cuda_fp16.h>
#include <math.h>
#include <stdint.h>

// ---------------------------------------------------------------------------
// GeometricAttentionLayer on GB300 — fp16 mma.sync + ldmatrix engine v3
//   CTA tile 256x128, warp tile 64x64 (8 warps, 1 CTA/SM), BK=64.
//   Split (3-pass) GEMMs: q+k proj (merged), scores.
//   Single-pass GEMMs:    v-proj, attn@V, out-proj.
//   v3: multi-stream overlap (weights ∥ split, v-proj ∥ qk-proj),
//       streaming cache hints on sc/pr, h1 fragment double-buffering.
// ---------------------------------------------------------------------------

#define BM 256
#define BN 128
#define BK 64
#define ATILE 32768                       // 256 rows x 128 B
#define BTILE 16384                       // 128 rows x 128 B
#define ST1 (ATILE + BTILE)               // 48 KB / stage
#define SMEM_1 (3 * ST1)                  // 144 KB
#define ST3 (2 * ATILE + 2 * BTILE)       // 96 KB / stage
#define SMEM_3 (2 * ST3)                  // 192 KB

__constant__ int c_ip[8] = {0, 2, 3, 4, 8, 9, 10, 14};

// ------------------------- scratch (device globals) ------------------------
__device__ __align__(1024) __half g_xh  [4096LL * 1024];
__device__ __align__(1024) __half g_xl  [4096LL * 1024];
__device__ __align__(1024) __half g_Wqkh[4608 * 1024];       // q cols 0..4095, k cols 4096..4607
__device__ __align__(1024) __half g_Wqkl[4608 * 1024];
__device__ __align__(1024) __half g_Wvh [1024 * 1024];
__device__ __align__(1024) __half g_Woh [1024 * 8192];
__device__ __align__(1024) __half g_qkmh[4096LL * 4608];
__device__ __align__(1024) __half g_qkml[4096LL * 4608];
__device__ __align__(1024) __half g_vT  [1024LL * 4096];
__device__ __align__(1024) float  g_sc  [16LL * 2048 * 2048];
__device__ __align__(1024) __half g_pr  [16LL * 2048 * 2048];
__device__ __align__(1024) __half g_ao  [4096LL * 8192];

// ------------------------------ helpers ------------------------------------
__device__ __forceinline__ uint32_t smem_u32(const void* p) {
    uint32_t a;
    asm("{ .reg .u64 t; cvta.to.shared.u64 t, %1; cvt.u32.u64 %0, t; }" : "=r"(a) : "l"(p));
    return a;
}

__device__ __forceinline__ void cp16(uint32_t dst, const __half* src) {
    asm volatile("cp.async.cg.shared.global [%0], [%1], 16;"
                 :: "r"(dst), "l"(src) : "memory");
}

#define LDSM_X4(r0, r1, r2, r3, addr)                                         \
    asm volatile("ldmatrix.sync.aligned.m8n8.x4.shared.b16 {%0,%1,%2,%3}, [%4];" \
        : "=r"(r0), "=r"(r1), "=r"(r2), "=r"(r3) : "r"(addr))

#define MMA_F16(acc, a, b)                                                    \
    asm volatile(                                                             \
        "mma.sync.aligned.m16n8k16.row.col.f32.f16.f16.f32 "                  \
        "{%0,%1,%2,%3}, {%4,%5,%6,%7}, {%8,%9}, {%0,%1,%2,%3};"               \
        : "+f"((acc)[0]), "+f"((acc)[1]), "+f"((acc)[2]), "+f"((acc)[3])      \
        : "r"((a)[0]), "r"((a)[1]), "r"((a)[2]), "r"((a)[3]),                 \
          "r"((b)[0]), "r"((b)[1]))

// ------------------------- weight precompute (split, transposed) -----------
__global__ void make_weightT(const float* __restrict__ w,
                             const float* __restrict__ blade,
                             __half* __restrict__ Wh, __half* __restrict__ Wl,
                             int I, int mode, float scale, long long total, int Kr,
                             int storeLo)
{
    long long idx = (long long)blockIdx.x * 256 + threadIdx.x;
    if (idx >= total) return;
    int col = (int)(idx / Kr);
    int k   = (int)(idx % Kr);
    int i = k >> 4, xc = k & 15;
    int j, y;
    if (mode == 0)      { j = col >> 4; y = col & 15; }
    else if (mode == 1) { int e = col & 7; int d = (col >> 3) & 63; int h = col >> 9;
                          j = d * 8 + h; y = c_ip[e]; }
    else                { int e = col & 7; j = col >> 3; y = c_ip[e]; }
    float s = 0.f;
    #pragma unroll
    for (int b = 0; b < 9; b++)
        s += w[((long long)j * I + i) * 9 + b] * blade[b * 256 + xc * 16 + y];
    s *= scale;
    __half hi = __float2half_rn(s);
    Wh[idx] = hi;
    if (storeLo)
        Wl[idx] = __float2half_rn(s - __half2float(hi));
}

// ------------------------------ fp16 split pass ----------------------------
__global__ void split_f16(const float4* __restrict__ in,
                          __half2* __restrict__ oh, __half2* __restrict__ ol, int n4)
{
    int i = blockIdx.x * 256 + threadIdx.x;
    if (i >= n4) return;
    float4 v = in[i];
    __half hx = __float2half_rn(v.x), hy = __float2half_rn(v.y);
    __half hz = __float2half_rn(v.z), hw = __float2half_rn(v.w);
    oh[i * 2 + 0] = __halves2half2(hx, hy);
    oh[i * 2 + 1] = __halves2half2(hz, hw);
    ol[i * 2 + 0] = __halves2half2(__float2half_rn(v.x - __half2float(hx)),
                                   __float2half_rn(v.y - __half2float(hy)));
    ol[i * 2 + 1] = __halves2half2(__float2half_rn(v.z - __half2float(hz)),
                                   __float2half_rn(v.w - __half2float(hw)));
}

// ------------------------------ single fp16 GEMM (NT) ----------------------
// C[m,n] = sum_k A[m,k]*B[n,k].  halfout: 0 -> fp32 C, 1 -> half C.
__global__ __launch_bounds__(256, 1) void gemm_h1(
    const __half* __restrict__ Ag, const __half* __restrict__ Bg,
    float* __restrict__ Cf, __half* __restrict__ Chh,
    int K, int lda, int ldb, int ldc,
    long long aB, long long aH, long long bB, long long bH,
    long long cB, long long cH, int nH, int halfout)
{
    extern __shared__ char sm[];
    const uint32_t smb = smem_u32(sm);

    const int tid = threadIdx.x;
    const int bb = blockIdx.z / nH, hh = blockIdx.z - bb * nH;
    const __half* A = Ag + bb * aB + hh * aH + (long long)(blockIdx.y * BM) * lda;
    const __half* B = Bg + bb * bB + hh * bH + (long long)(blockIdx.x * BN) * ldb;

    const int ldrow = tid >> 3;
    const int seg   = tid & 7;
    const uint32_t swoff = (uint32_t)((seg ^ (ldrow & 7)) << 4);

#define ISSUE1(ch, slot) do {                                                 \
        const __half* _a = A + (long long)(ch) * BK + (seg << 3);             \
        uint32_t _da = smb + (uint32_t)(slot) * ST1;                          \
        _Pragma("unroll")                                                     \
        for (int _i = 0; _i < 8; _i++)                                        \
            cp16(_da + (uint32_t)((ldrow + 32 * _i) * 128) + swoff,           \
                 _a + (long long)(ldrow + 32 * _i) * lda);                    \
        const __half* _b = B + (long long)(ch) * BK + (seg << 3);             \
        uint32_t _db = smb + (uint32_t)(slot) * ST1 + ATILE;                  \
        _Pragma("unroll")                                                     \
        for (int _i = 0; _i < 4; _i++)                                        \
            cp16(_db + (uint32_t)((ldrow + 32 * _i) * 128) + swoff,           \
                 _b + (long long)(ldrow + 32 * _i) * ldb);                    \
    } while (0)

    const int lane = tid & 31;
    const int wid = tid >> 5;
    const int wm = (wid & 3) * 64;
    const int wn = (wid >> 2) * 64;
    const int qr = lane >> 2;
    const int qc = lane & 3;
    const int l7 = lane & 7;
    const uint32_t aRow = (uint32_t)(wm + (lane & 15)) * 128;
    const int aCb = lane >> 4;
    const uint32_t bRow = (uint32_t)(wn + l7 + ((lane >> 4) << 3)) * 128;
    const int bCb = (lane >> 3) & 1;

    float acc[4][8][4];
    #pragma unroll
    for (int mi = 0; mi < 4; mi++)
        #pragma unroll
        for (int ni = 0; ni < 8; ni++)
            #pragma unroll
            for (int q = 0; q < 4; q++) acc[mi][ni][q] = 0.f;

    const int nch = K >> 6;

    #pragma unroll
    for (int p = 0; p < 2; p++) {
        if (p < nch) ISSUE1(p, p);
        asm volatile("cp.async.commit_group;" ::: "memory");
    }

    uint32_t a[2][4][4], b[2][8][2];

#define LOADFRAG1(kk, buf, tA, tB) do {                                       \
        const uint32_t _aC = (uint32_t)(((((kk) << 1) + aCb) ^ l7) << 4);     \
        const uint32_t _bC = (uint32_t)(((((kk) << 1) + bCb) ^ l7) << 4);     \
        _Pragma("unroll")                                                     \
        for (int _mi = 0; _mi < 4; _mi++)                                     \
            LDSM_X4(a[buf][_mi][0], a[buf][_mi][1], a[buf][_mi][2],           \
                    a[buf][_mi][3], (tA) + _mi * 2048 + _aC);                 \
        _Pragma("unroll")                                                     \
        for (int _g = 0; _g < 4; _g++)                                        \
            LDSM_X4(b[buf][2*_g][0], b[buf][2*_g][1], b[buf][2*_g+1][0],      \
                    b[buf][2*_g+1][1], (tB) + _g * 2048 + _bC);               \
    } while (0)

    for (int ch = 0; ch < nch; ch++) {
        asm volatile("cp.async.wait_group 1;" ::: "memory");
        __syncthreads();

        int pf = ch + 2;
        if (pf < nch) ISSUE1(pf, pf % 3);
        asm volatile("cp.async.commit_group;" ::: "memory");

        const int slot = ch % 3;
        const uint32_t tA = smb + slot * ST1 + aRow;
        const uint32_t tB = smb + slot * ST1 + ATILE + bRow;

        LOADFRAG1(0, 0, tA, tB);
        #pragma unroll
        for (int kk = 0; kk < 4; kk++) {
            const int cur = kk & 1;
            if (kk < 3) LOADFRAG1(kk + 1, cur ^ 1, tA, tB);
            #pragma unroll
            for (int mi = 0; mi < 4; mi++)
                #pragma unroll
                for (int ni = 0; ni < 8; ni++)
                    MMA_F16(acc[mi][ni], a[cur][mi], b[cur][ni]);
        }
    }
#undef LOADFRAG1
#undef ISSUE1

    const long long cOff = bb * cB + hh * cH;
    const int rbase = blockIdx.y * BM + wm + qr;
    const int cbase = blockIdx.x * BN + wn + (qc << 1);
    #pragma unroll
    for (int mi = 0; mi < 4; mi++) {
        #pragma unroll
        for (int ni = 0; ni < 8; ni++) {
            const long long r = rbase + mi * 16;
            const int c = cbase + ni * 8;
            if (halfout) {
                __half* cb = Chh + cOff;
                *reinterpret_cast<__half2*>(&cb[r * ldc + c]) =
                    __halves2half2(__float2half_rn(acc[mi][ni][0]),
                                   __float2half_rn(acc[mi][ni][1]));
                *reinterpret_cast<__half2*>(&cb[(r + 8) * ldc + c]) =
                    __halves2half2(__float2half_rn(acc[mi][ni][2]),
                                   __float2half_rn(acc[mi][ni][3]));
            } else {
                float* cb = Cf + cOff;
                *reinterpret_cast<float2*>(&cb[r * ldc + c]) =
                    make_float2(acc[mi][ni][0], acc[mi][ni][1]);
                *reinterpret_cast<float2*>(&cb[(r + 8) * ldc + c]) =
                    make_float2(acc[mi][ni][2], acc[mi][ni][3]);
            }
        }
    }
}

// ------------------------------ 3-term fp16 split GEMM (NT) ----------------
// acc += Ahi*Bhi + Ahi*Blo + Alo*Bhi.  outmode: 0 -> fp32 C (.cs), 2 -> split half C.
__global__ __launch_bounds__(256, 1) void gemm_h3(
    const __half* __restrict__ Ah, const __half* __restrict__ Al,
    const __half* __restrict__ Bh, const __half* __restrict__ Bl,
    float* __restrict__ Cf, __half* __restrict__ Chh, __half* __restrict__ Chl,
    int K, int lda, int ldb, int ldc,
    long long aB, long long aH, long long bB, long long bH,
    long long cB, long long cH, int nH, int outmode)
{
    extern __shared__ char sm[];
    const uint32_t smb = smem_u32(sm);

    const int tid = threadIdx.x;
    const int bb = blockIdx.z / nH, hh = blockIdx.z - bb * nH;
    const long long aOff = bb * aB + hh * aH + (long long)(blockIdx.y * BM) * lda;
    const long long bOff = bb * bB + hh * bH + (long long)(blockIdx.x * BN) * ldb;
    const __half* pAh = Ah + aOff;
    const __half* pAl = Al + aOff;
    const __half* pBh = Bh + bOff;
    const __half* pBl = Bl + bOff;

    const int ldrow = tid >> 3;
    const int seg   = tid & 7;
    const uint32_t swoff = (uint32_t)((seg ^ (ldrow & 7)) << 4);

#define ISSUE3(ch, slot) do {                                                 \
        uint32_t _sb = smb + (uint32_t)(slot) * ST3;                          \
        const __half* _s0 = pAh + (long long)(ch) * BK + (seg << 3);          \
        const __half* _s1 = pAl + (long long)(ch) * BK + (seg << 3);          \
        _Pragma("unroll")                                                     \
        for (int _i = 0; _i < 8; _i++) {                                      \
            uint32_t _o = (uint32_t)((ldrow + 32 * _i) * 128) + swoff;        \
            long long _g = (long long)(ldrow + 32 * _i) * lda;                \
            cp16(_sb + _o, _s0 + _g);                                         \
            cp16(_sb + ATILE + _o, _s1 + _g);                                 \
        }                                                                     \
        const __half* _s2 = pBh + (long long)(ch) * BK + (seg << 3);          \
        const __half* _s3 = pBl + (long long)(ch) * BK + (seg << 3);          \
        _Pragma("unroll")                                                     \
        for (int _i = 0; _i < 4; _i++) {                                      \
            uint32_t _o = (uint32_t)((ldrow + 32 * _i) * 128) + swoff;        \
            long long _g = (long long)(ldrow + 32 * _i) * ldb;                \
            cp16(_sb + 2 * ATILE + _o, _s2 + _g);                             \
            cp16(_sb + 2 * ATILE + BTILE + _o, _s3 + _g);                     \
        }                                                                     \
    } while (0)

    const int lane = tid & 31;
    const int wid = tid >> 5;
    const int wm = (wid & 3) * 64;
    const int wn = (wid >> 2) * 64;
    const int qr = lane >> 2;
    const int qc = lane & 3;
    const int l7 = lane & 7;
    const uint32_t aRow = (uint32_t)(wm + (lane & 15)) * 128;
    const int aCb = lane >> 4;
    const uint32_t bRow = (uint32_t)(wn + l7 + ((lane >> 4) << 3)) * 128;
    const int bCb = (lane >> 3) & 1;

    float acc[4][8][4];
    #pragma unroll
    for (int mi = 0; mi < 4; mi++)
        #pragma unroll
        for (int ni = 0; ni < 8; ni++)
            #pragma unroll
            for (int q = 0; q < 4; q++) acc[mi][ni][q] = 0.f;

    const int nch = K >> 6;

    ISSUE3(0, 0);
    asm volatile("cp.async.commit_group;" ::: "memory");

    for (int ch = 0; ch < nch; ch++) {
        asm volatile("cp.async.wait_group 0;" ::: "memory");
        __syncthreads();
        if (ch + 1 < nch) {
            ISSUE3(ch + 1, (ch + 1) & 1);
            asm volatile("cp.async.commit_group;" ::: "memory");
        }

        const int slot = ch & 1;
        const uint32_t tAh = smb + slot * ST3 + aRow;
        const uint32_t tAl = smb + slot * ST3 + ATILE + aRow;
        const uint32_t tBh = smb + slot * ST3 + 2 * ATILE + bRow;
        const uint32_t tBl = smb + slot * ST3 + 2 * ATILE + BTILE + bRow;

        #pragma unroll
        for (int kk = 0; kk < 4; kk++) {
            const uint32_t aC = (uint32_t)((((kk << 1) + aCb) ^ l7) << 4);
            const uint32_t bC = (uint32_t)((((kk << 1) + bCb) ^ l7) << 4);
            uint32_t ah[4][4], al[4][4], bh[8][2], bl[8][2];
            #pragma unroll
            for (int mi = 0; mi < 4; mi++) {
                LDSM_X4(ah[mi][0], ah[mi][1], ah[mi][2], ah[mi][3], tAh + mi * 2048 + aC);
                LDSM_X4(al[mi][0], al[mi][1], al[mi][2], al[mi][3], tAl + mi * 2048 + aC);
            }
            #pragma unroll
            for (int g = 0; g < 4; g++) {
                LDSM_X4(bh[2*g][0], bh[2*g][1], bh[2*g+1][0], bh[2*g+1][1], tBh + g * 2048 + bC);
                LDSM_X4(bl[2*g][0], bl[2*g][1], bl[2*g+1][0], bl[2*g+1][1], tBl + g * 2048 + bC);
            }
            #pragma unroll
            for (int mi = 0; mi < 4; mi++)
                #pragma unroll
                for (int ni = 0; ni < 8; ni++) {
                    MMA_F16(acc[mi][ni], ah[mi], bl[ni]);
                    MMA_F16(acc[mi][ni], al[mi], bh[ni]);
                    MMA_F16(acc[mi][ni], ah[mi], bh[ni]);
                }
        }
    }
#undef ISSUE3

    const long long cOff = bb * cB + hh * cH;
    const int rbase = blockIdx.y * BM + wm + qr;
    const int cbase = blockIdx.x * BN + wn + (qc << 1);
    #pragma unroll
    for (int mi = 0; mi < 4; mi++) {
        #pragma unroll
        for (int ni = 0; ni < 8; ni++) {
            const long long r = rbase + mi * 16;
            const int c = cbase + ni * 8;
            float v[4] = {acc[mi][ni][0], acc[mi][ni][1], acc[mi][ni][2], acc[mi][ni][3]};
            if (outmode == 2) {
                __half h0 = __float2half_rn(v[0]), h1 = __float2half_rn(v[1]);
                __half h2 = __float2half_rn(v[2]), h3 = __float2half_rn(v[3]);
                __half* ch_ = Chh + cOff;
                __half* cl_ = Chl + cOff;
                *reinterpret_cast<__half2*>(&ch_[r * ldc + c])       = __halves2half2(h0, h1);
                *reinterpret_cast<__half2*>(&ch_[(r + 8) * ldc + c]) = __halves2half2(h2, h3);
                *reinterpret_cast<__half2*>(&cl_[r * ldc + c]) =
                    __halves2half2(__float2half_rn(v[0] - __half2float(h0)),
                                   __float2half_rn(v[1] - __half2float(h1)));
                *reinterpret_cast<__half2*>(&cl_[(r + 8) * ldc + c]) =
                    __halves2half2(__float2half_rn(v[2] - __half2float(h2)),
                                   __float2half_rn(v[3] - __half2float(h3)));
            } else {
                // scores: write-once-read-once -> streaming stores (keep L2 for tiles)
                float* cb = Cf + cOff;
                __stcs(reinterpret_cast<float2*>(&cb[r * ldc + c]),
                       make_float2(v[0], v[1]));
                __stcs(reinterpret_cast<float2*>(&cb[(r + 8) * ldc + c]),
                       make_float2(v[2], v[3]));
            }
        }
    }
}

// ------------------------- softmax (2048 cols, fp32 -> half) ---------------
__global__ __launch_bounds__(256) void softmax2048(const float* __restrict__ sc,
                                                   __half* __restrict__ pr)
{
    __shared__ float red[8];
    const float4* p = reinterpret_cast<const float4*>(sc + (long long)blockIdx.x * 2048);
    __half2* q = reinterpret_cast<__half2*>(pr + (long long)blockIdx.x * 2048);
    const int t = threadIdx.x;
    const int wid = t >> 5, lid = t & 31;

    float4 a = __ldcs(p + t);
    float4 b = __ldcs(p + t + 256);

    float mx = fmaxf(fmaxf(fmaxf(a.x, a.y), fmaxf(a.z, a.w)),
                     fmaxf(fmaxf(b.x, b.y), fmaxf(b.z, b.w)));
    #pragma unroll
    for (int s = 16; s > 0; s >>= 1) mx = fmaxf(mx, __shfl_xor_sync(0xffffffffu, mx, s));
    if (lid == 0) red[wid] = mx;
    __syncthreads();
    if (t < 32) {
        float m = (t < 8) ? red[t] : -INFINITY;
        #pragma unroll
        for (int s = 4; s > 0; s >>= 1) m = fmaxf(m, __shfl_xor_sync(0xffffffffu, m, s));
        if (t == 0) red[0] = m;
    }
    __syncthreads();
    mx = red[0];
    __syncthreads();

    a.x = __expf(a.x - mx); a.y = __expf(a.y - mx); a.z = __expf(a.z - mx); a.w = __expf(a.w - mx);
    b.x = __expf(b.x - mx); b.y = __expf(b.y - mx); b.z = __expf(b.z - mx); b.w = __expf(b.w - mx);
    float sum = a.x + a.y + a.z + a.w + b.x + b.y + b.z + b.w;
    #pragma unroll
    for (int s = 16; s > 0; s >>= 1) sum += __shfl_xor_sync(0xffffffffu, sum, s);
    if (lid == 0) red[wid] = sum;
    __syncthreads();
    if (t < 32) {
        float m = (t < 8) ? red[t] : 0.f;
        #pragma unroll
        for (int s = 4; s > 0; s >>= 1) m += __shfl_xor_sync(0xffffffffu, m, s);
        if (t == 0) red[0] = m;
    }
    __syncthreads();
    float inv = 1.0f / red[0];

    __half2 q0 = __halves2half2(__float2half_rn(a.x * inv), __float2half_rn(a.y * inv));
    __half2 q1 = __halves2half2(__float2half_rn(a.z * inv), __float2half_rn(a.w * inv));
    __half2 q2 = __halves2half2(__float2half_rn(b.x * inv), __float2half_rn(b.y * inv));
    __half2 q3 = __halves2half2(__float2half_rn(b.z * inv), __float2half_rn(b.w * inv));
    // streaming 8B stores
    uint2 u01 = make_uint2(*reinterpret_cast<uint32_t*>(&q0), *reinterpret_cast<uint32_t*>(&q1));
    uint2 u23 = make_uint2(*reinterpret_cast<uint32_t*>(&q2), *reinterpret_cast<uint32_t*>(&q3));
    __stcs(reinterpret_cast<uint2*>(q + t * 2), u01);
    __stcs(reinterpret_cast<uint2*>(q + (t + 256) * 2), u23);
}

// ------------------------------ host side ----------------------------------
template <typename T>
static T* sym_addr(const void* symbol)
{
    void* p = nullptr;
    cudaGetSymbolAddress(&p, symbol);
    return (T*)p;
}

extern "C" void kernel_launch(void* const* d_in, const int* in_sizes, int n_in,
                              void* d_out, int out_size)
{
    const float* x     = (const float*)d_in[0];
    const float* blade = (const float*)d_in[1];
    const float* w_q   = (const float*)d_in[2];
    const float* w_k   = (const float*)d_in[3];
    const float* w_v   = (const float*)d_in[4];
    const float* w_o   = (const float*)d_in[5];
    float* out = (float*)d_out;

    __half* xh   = sym_addr<__half>(g_xh),   *xl   = sym_addr<__half>(g_xl);
    __half* Wqkh = sym_addr<__half>(g_Wqkh), *Wqkl = sym_addr<__half>(g_Wqkl);
    __half* Wvh  = sym_addr<__half>(g_Wvh);
    __half* Woh  = sym_addr<__half>(g_Woh);
    __half* qkmh = sym_addr<__half>(g_qkmh), *qkml = sym_addr<__half>(g_qkml);
    __half* vT   = sym_addr<__half>(g_vT);
    float*  sc   = sym_addr<float >(g_sc);
    __half* pr   = sym_addr<__half>(g_pr);
    __half* ao   = sym_addr<__half>(g_ao);

    // streams/events for graph fork-join (created once, outside capture)
    static cudaStream_t s1 = nullptr, s2 = nullptr;
    static cudaEvent_t eF = nullptr, e0 = nullptr, e1 = nullptr, e3 = nullptr;
    if (s1 == nullptr) {
        cudaStreamCreateWithFlags(&s1, cudaStreamNonBlocking);
        cudaStreamCreateWithFlags(&s2, cudaStreamNonBlocking);
        cudaEventCreateWithFlags(&eF, cudaEventDisableTiming);
        cudaEventCreateWithFlags(&e0, cudaEventDisableTiming);
        cudaEventCreateWithFlags(&e1, cudaEventDisableTiming);
        cudaEventCreateWithFlags(&e3, cudaEventDisableTiming);
        cudaFuncSetAttribute(gemm_h1, cudaFuncAttributeMaxDynamicSharedMemorySize, SMEM_1);
        cudaFuncSetAttribute(gemm_h3, cudaFuncAttributeMaxDynamicSharedMemorySize, SMEM_3);
    }

    const float scale = 1.0f / sqrtf(512.0f);

    // ---- fork: side streams join the capture graph ----
    cudaEventRecord(eF, 0);
    cudaStreamWaitEvent(s1, eF, 0);
    cudaStreamWaitEvent(s2, eF, 0);

    // s1: q+k weight precompute
    {
        long long tq = 4096LL * 1024;
        make_weightT<<<(unsigned)((tq + 255) / 256), 256, 0, s1>>>(
            w_q, blade, Wqkh, Wqkl, 64, 1, scale, tq, 1024, 1);
        long long tk = 512LL * 1024;
        make_weightT<<<(unsigned)((tk + 255) / 256), 256, 0, s1>>>(
            w_k, blade, Wqkh + 4096LL * 1024, Wqkl + 4096LL * 1024, 64, 2, 1.0f, tk, 1024, 1);
        cudaEventRecord(e1, s1);
    }
    // s2: v + o weight precompute
    {
        long long tv = 1024LL * 1024;
        make_weightT<<<(unsigned)((tv + 255) / 256), 256, 0, s2>>>(
            w_v, blade, Wvh, nullptr, 64, 0, 1.0f, tv, 1024, 0);
        long long to = 1024LL * 8192;
        make_weightT<<<(unsigned)((to + 255) / 256), 256, 0, s2>>>(
            w_o, blade, Woh, nullptr, 512, 0, 1.0f, to, 8192, 0);
    }

    // main: input split
    split_f16<<<4096, 256>>>((const float4*)x, (__half2*)xh, (__half2*)xl, 4096 * 1024 / 4);
    cudaEventRecord(e0, 0);

    // s2: v projection (needs split + Wv) — runs concurrent with qk-proj
    cudaStreamWaitEvent(s2, e0, 0);
    gemm_h1<<<dim3(4096 / 128, 1024 / 256, 1), 256, SMEM_1, s2>>>(
        Wvh, xh, nullptr, vT, 1024, 1024, 1024, 4096,
        0, 0, 0, 0, 0, 0, 1, 1);
    cudaEventRecord(e3, s2);

    // main: q+k projection (needs split + Wqk)
    cudaStreamWaitEvent(0, e1, 0);
    gemm_h3<<<dim3(4608 / 128, 4096 / 256, 1), 256, SMEM_3>>>(
        xh, xl, Wqkh, Wqkl, nullptr, qkmh, qkml, 1024, 1024, 1024, 4608,
        0, 0, 0, 0, 0, 0, 1, 2);

    // main: scores (split in, fp32 .cs out); km = cols 4096.. of qkm
    gemm_h3<<<dim3(2048 / 128, 2048 / 256, 16), 256, SMEM_3>>>(
        qkmh, qkml, qkmh + 4096, qkml + 4096, sc, nullptr, nullptr,
        512, 4608, 4608, 2048,
        /*aB*/ 2048LL * 4608, /*aH*/ 512,
        /*bB*/ 2048LL * 4608, /*bH*/ 0,
        /*cB*/ 8LL * 2048 * 2048, /*cH*/ 2048LL * 2048, 8, 0);

    // main: softmax over keys (fp32 -> half probs)
    softmax2048<<<16 * 2048, 256>>>(sc, pr);

    // join v-proj, then attn @ V
    cudaStreamWaitEvent(0, e3, 0);
    gemm_h1<<<dim3(1024 / 128, 2048 / 256, 16), 256, SMEM_1>>>(
        pr, vT, nullptr, ao, 2048, 2048, 4096, 8192,
        /*aB*/ 8LL * 2048 * 2048, /*aH*/ 2048LL * 2048,
        /*bB*/ 2048, /*bH*/ 0,
        /*cB*/ 2048LL * 8192, /*cH*/ 1024, 8, 1);

    // main: output projection
    gemm_h1<<<dim3(1024 / 128, 4096 / 256, 1), 256, SMEM_1>>>(
        ao, Woh, out, nullptr, 8192, 8192, 8192, 1024,
        0, 0, 0, 0, 0, 0, 1, 0);
}

// round 10
// speedup vs baseline: 5.4999x; 1.0105x over previous
#include <cuda_runtime.h>
#include <cuda_fp16.h>
#include <math.h>
#include <stdint.h>

// ---------------------------------------------------------------------------
// GeometricAttentionLayer on GB300 — fp16 mma.sync + ldmatrix engine v4
//   CTA tile 256x128, warp tile 64x64 (8 warps, 1 CTA/SM), BK=64.
//   Split (3-pass) GEMMs: q+k proj (merged), scores.
//   Single-pass GEMMs:    v-proj, attn@V, out-proj.
//   v4: per-batch pipelining — qk/scores/softmax/attnV/outproj split by batch
//       across two streams so softmax + tail waves overlap with tensor work.
// ---------------------------------------------------------------------------

#define BM 256
#define BN 128
#define BK 64
#define ATILE 32768                       // 256 rows x 128 B
#define BTILE 16384                       // 128 rows x 128 B
#define ST1 (ATILE + BTILE)               // 48 KB / stage
#define SMEM_1 (3 * ST1)                  // 144 KB
#define ST3 (2 * ATILE + 2 * BTILE)       // 96 KB / stage
#define SMEM_3 (2 * ST3)                  // 192 KB

__constant__ int c_ip[8] = {0, 2, 3, 4, 8, 9, 10, 14};

// ------------------------- scratch (device globals) ------------------------
__device__ __align__(1024) __half g_xh  [4096LL * 1024];
__device__ __align__(1024) __half g_xl  [4096LL * 1024];
__device__ __align__(1024) __half g_Wqkh[4608 * 1024];       // q cols 0..4095, k cols 4096..4607
__device__ __align__(1024) __half g_Wqkl[4608 * 1024];
__device__ __align__(1024) __half g_Wvh [1024 * 1024];
__device__ __align__(1024) __half g_Woh [1024 * 8192];
__device__ __align__(1024) __half g_qkmh[4096LL * 4608];
__device__ __align__(1024) __half g_qkml[4096LL * 4608];
__device__ __align__(1024) __half g_vT  [1024LL * 4096];
__device__ __align__(1024) float  g_sc  [16LL * 2048 * 2048];
__device__ __align__(1024) __half g_pr  [16LL * 2048 * 2048];
__device__ __align__(1024) __half g_ao  [4096LL * 8192];

// ------------------------------ helpers ------------------------------------
__device__ __forceinline__ uint32_t smem_u32(const void* p) {
    uint32_t a;
    asm("{ .reg .u64 t; cvta.to.shared.u64 t, %1; cvt.u32.u64 %0, t; }" : "=r"(a) : "l"(p));
    return a;
}

__device__ __forceinline__ void cp16(uint32_t dst, const __half* src) {
    asm volatile("cp.async.cg.shared.global [%0], [%1], 16;"
                 :: "r"(dst), "l"(src) : "memory");
}

#define LDSM_X4(r0, r1, r2, r3, addr)                                         \
    asm volatile("ldmatrix.sync.aligned.m8n8.x4.shared.b16 {%0,%1,%2,%3}, [%4];" \
        : "=r"(r0), "=r"(r1), "=r"(r2), "=r"(r3) : "r"(addr))

#define MMA_F16(acc, a, b)                                                    \
    asm volatile(                                                             \
        "mma.sync.aligned.m16n8k16.row.col.f32.f16.f16.f32 "                  \
        "{%0,%1,%2,%3}, {%4,%5,%6,%7}, {%8,%9}, {%0,%1,%2,%3};"               \
        : "+f"((acc)[0]), "+f"((acc)[1]), "+f"((acc)[2]), "+f"((acc)[3])      \
        : "r"((a)[0]), "r"((a)[1]), "r"((a)[2]), "r"((a)[3]),                 \
          "r"((b)[0]), "r"((b)[1]))

// ------------------------- weight precompute (split, transposed) -----------
__global__ void make_weightT(const float* __restrict__ w,
                             const float* __restrict__ blade,
                             __half* __restrict__ Wh, __half* __restrict__ Wl,
                             int I, int mode, float scale, long long total, int Kr,
                             int storeLo)
{
    long long idx = (long long)blockIdx.x * 256 + threadIdx.x;
    if (idx >= total) return;
    int col = (int)(idx / Kr);
    int k   = (int)(idx % Kr);
    int i = k >> 4, xc = k & 15;
    int j, y;
    if (mode == 0)      { j = col >> 4; y = col & 15; }
    else if (mode == 1) { int e = col & 7; int d = (col >> 3) & 63; int h = col >> 9;
                          j = d * 8 + h; y = c_ip[e]; }
    else                { int e = col & 7; j = col >> 3; y = c_ip[e]; }
    float s = 0.f;
    #pragma unroll
    for (int b = 0; b < 9; b++)
        s += w[((long long)j * I + i) * 9 + b] * blade[b * 256 + xc * 16 + y];
    s *= scale;
    __half hi = __float2half_rn(s);
    Wh[idx] = hi;
    if (storeLo)
        Wl[idx] = __float2half_rn(s - __half2float(hi));
}

// ------------------------------ fp16 split pass ----------------------------
__global__ void split_f16(const float4* __restrict__ in,
                          __half2* __restrict__ oh, __half2* __restrict__ ol, int n4)
{
    int i = blockIdx.x * 256 + threadIdx.x;
    if (i >= n4) return;
    float4 v = in[i];
    __half hx = __float2half_rn(v.x), hy = __float2half_rn(v.y);
    __half hz = __float2half_rn(v.z), hw = __float2half_rn(v.w);
    oh[i * 2 + 0] = __halves2half2(hx, hy);
    oh[i * 2 + 1] = __halves2half2(hz, hw);
    ol[i * 2 + 0] = __halves2half2(__float2half_rn(v.x - __half2float(hx)),
                                   __float2half_rn(v.y - __half2float(hy)));
    ol[i * 2 + 1] = __halves2half2(__float2half_rn(v.z - __half2float(hz)),
                                   __float2half_rn(v.w - __half2float(hw)));
}

// ------------------------------ single fp16 GEMM (NT) ----------------------
// C[m,n] = sum_k A[m,k]*B[n,k].  halfout: 0 -> fp32 C, 1 -> half C.
__global__ __launch_bounds__(256, 1) void gemm_h1(
    const __half* __restrict__ Ag, const __half* __restrict__ Bg,
    float* __restrict__ Cf, __half* __restrict__ Chh,
    int K, int lda, int ldb, int ldc,
    long long aB, long long aH, long long bB, long long bH,
    long long cB, long long cH, int nH, int halfout)
{
    extern __shared__ char sm[];
    const uint32_t smb = smem_u32(sm);

    const int tid = threadIdx.x;
    const int bb = blockIdx.z / nH, hh = blockIdx.z - bb * nH;
    const __half* A = Ag + bb * aB + hh * aH + (long long)(blockIdx.y * BM) * lda;
    const __half* B = Bg + bb * bB + hh * bH + (long long)(blockIdx.x * BN) * ldb;

    const int ldrow = tid >> 3;
    const int seg   = tid & 7;
    const uint32_t swoff = (uint32_t)((seg ^ (ldrow & 7)) << 4);

#define ISSUE1(ch, slot) do {                                                 \
        const __half* _a = A + (long long)(ch) * BK + (seg << 3);             \
        uint32_t _da = smb + (uint32_t)(slot) * ST1;                          \
        _Pragma("unroll")                                                     \
        for (int _i = 0; _i < 8; _i++)                                        \
            cp16(_da + (uint32_t)((ldrow + 32 * _i) * 128) + swoff,           \
                 _a + (long long)(ldrow + 32 * _i) * lda);                    \
        const __half* _b = B + (long long)(ch) * BK + (seg << 3);             \
        uint32_t _db = smb + (uint32_t)(slot) * ST1 + ATILE;                  \
        _Pragma("unroll")                                                     \
        for (int _i = 0; _i < 4; _i++)                                        \
            cp16(_db + (uint32_t)((ldrow + 32 * _i) * 128) + swoff,           \
                 _b + (long long)(ldrow + 32 * _i) * ldb);                    \
    } while (0)

    const int lane = tid & 31;
    const int wid = tid >> 5;
    const int wm = (wid & 3) * 64;
    const int wn = (wid >> 2) * 64;
    const int qr = lane >> 2;
    const int qc = lane & 3;
    const int l7 = lane & 7;
    const uint32_t aRow = (uint32_t)(wm + (lane & 15)) * 128;
    const int aCb = lane >> 4;
    const uint32_t bRow = (uint32_t)(wn + l7 + ((lane >> 4) << 3)) * 128;
    const int bCb = (lane >> 3) & 1;

    float acc[4][8][4];
    #pragma unroll
    for (int mi = 0; mi < 4; mi++)
        #pragma unroll
        for (int ni = 0; ni < 8; ni++)
            #pragma unroll
            for (int q = 0; q < 4; q++) acc[mi][ni][q] = 0.f;

    const int nch = K >> 6;

    #pragma unroll
    for (int p = 0; p < 2; p++) {
        if (p < nch) ISSUE1(p, p);
        asm volatile("cp.async.commit_group;" ::: "memory");
    }

    uint32_t a[2][4][4], b[2][8][2];

#define LOADFRAG1(kk, buf, tA, tB) do {                                       \
        const uint32_t _aC = (uint32_t)(((((kk) << 1) + aCb) ^ l7) << 4);     \
        const uint32_t _bC = (uint32_t)(((((kk) << 1) + bCb) ^ l7) << 4);     \
        _Pragma("unroll")                                                     \
        for (int _mi = 0; _mi < 4; _mi++)                                     \
            LDSM_X4(a[buf][_mi][0], a[buf][_mi][1], a[buf][_mi][2],           \
                    a[buf][_mi][3], (tA) + _mi * 2048 + _aC);                 \
        _Pragma("unroll")                                                     \
        for (int _g = 0; _g < 4; _g++)                                        \
            LDSM_X4(b[buf][2*_g][0], b[buf][2*_g][1], b[buf][2*_g+1][0],      \
                    b[buf][2*_g+1][1], (tB) + _g * 2048 + _bC);               \
    } while (0)

    for (int ch = 0; ch < nch; ch++) {
        asm volatile("cp.async.wait_group 1;" ::: "memory");
        __syncthreads();

        int pf = ch + 2;
        if (pf < nch) ISSUE1(pf, pf % 3);
        asm volatile("cp.async.commit_group;" ::: "memory");

        const int slot = ch % 3;
        const uint32_t tA = smb + slot * ST1 + aRow;
        const uint32_t tB = smb + slot * ST1 + ATILE + bRow;

        LOADFRAG1(0, 0, tA, tB);
        #pragma unroll
        for (int kk = 0; kk < 4; kk++) {
            const int cur = kk & 1;
            if (kk < 3) LOADFRAG1(kk + 1, cur ^ 1, tA, tB);
            #pragma unroll
            for (int mi = 0; mi < 4; mi++)
                #pragma unroll
                for (int ni = 0; ni < 8; ni++)
                    MMA_F16(acc[mi][ni], a[cur][mi], b[cur][ni]);
        }
    }
#undef LOADFRAG1
#undef ISSUE1

    const long long cOff = bb * cB + hh * cH;
    const int rbase = blockIdx.y * BM + wm + qr;
    const int cbase = blockIdx.x * BN + wn + (qc << 1);
    #pragma unroll
    for (int mi = 0; mi < 4; mi++) {
        #pragma unroll
        for (int ni = 0; ni < 8; ni++) {
            const long long r = rbase + mi * 16;
            const int c = cbase + ni * 8;
            if (halfout) {
                __half* cb = Chh + cOff;
                *reinterpret_cast<__half2*>(&cb[r * ldc + c]) =
                    __halves2half2(__float2half_rn(acc[mi][ni][0]),
                                   __float2half_rn(acc[mi][ni][1]));
                *reinterpret_cast<__half2*>(&cb[(r + 8) * ldc + c]) =
                    __halves2half2(__float2half_rn(acc[mi][ni][2]),
                                   __float2half_rn(acc[mi][ni][3]));
            } else {
                float* cb = Cf + cOff;
                *reinterpret_cast<float2*>(&cb[r * ldc + c]) =
                    make_float2(acc[mi][ni][0], acc[mi][ni][1]);
                *reinterpret_cast<float2*>(&cb[(r + 8) * ldc + c]) =
                    make_float2(acc[mi][ni][2], acc[mi][ni][3]);
            }
        }
    }
}

// ------------------------------ 3-term fp16 split GEMM (NT) ----------------
// acc += Ahi*Bhi + Ahi*Blo + Alo*Bhi.  outmode: 0 -> fp32 C (.cs), 2 -> split half C.
__global__ __launch_bounds__(256, 1) void gemm_h3(
    const __half* __restrict__ Ah, const __half* __restrict__ Al,
    const __half* __restrict__ Bh, const __half* __restrict__ Bl,
    float* __restrict__ Cf, __half* __restrict__ Chh, __half* __restrict__ Chl,
    int K, int lda, int ldb, int ldc,
    long long aB, long long aH, long long bB, long long bH,
    long long cB, long long cH, int nH, int outmode)
{
    extern __shared__ char sm[];
    const uint32_t smb = smem_u32(sm);

    const int tid = threadIdx.x;
    const int bb = blockIdx.z / nH, hh = blockIdx.z - bb * nH;
    const long long aOff = bb * aB + hh * aH + (long long)(blockIdx.y * BM) * lda;
    const long long bOff = bb * bB + hh * bH + (long long)(blockIdx.x * BN) * ldb;
    const __half* pAh = Ah + aOff;
    const __half* pAl = Al + aOff;
    const __half* pBh = Bh + bOff;
    const __half* pBl = Bl + bOff;

    const int ldrow = tid >> 3;
    const int seg   = tid & 7;
    const uint32_t swoff = (uint32_t)((seg ^ (ldrow & 7)) << 4);

#define ISSUE3(ch, slot) do {                                                 \
        uint32_t _sb = smb + (uint32_t)(slot) * ST3;                          \
        const __half* _s0 = pAh + (long long)(ch) * BK + (seg << 3);          \
        const __half* _s1 = pAl + (long long)(ch) * BK + (seg << 3);          \
        _Pragma("unroll")                                                     \
        for (int _i = 0; _i < 8; _i++) {                                      \
            uint32_t _o = (uint32_t)((ldrow + 32 * _i) * 128) + swoff;        \
            long long _g = (long long)(ldrow + 32 * _i) * lda;                \
            cp16(_sb + _o, _s0 + _g);                                         \
            cp16(_sb + ATILE + _o, _s1 + _g);                                 \
        }                                                                     \
        const __half* _s2 = pBh + (long long)(ch) * BK + (seg << 3);          \
        const __half* _s3 = pBl + (long long)(ch) * BK + (seg << 3);          \
        _Pragma("unroll")                                                     \
        for (int _i = 0; _i < 4; _i++) {                                      \
            uint32_t _o = (uint32_t)((ldrow + 32 * _i) * 128) + swoff;        \
            long long _g = (long long)(ldrow + 32 * _i) * ldb;                \
            cp16(_sb + 2 * ATILE + _o, _s2 + _g);                             \
            cp16(_sb + 2 * ATILE + BTILE + _o, _s3 + _g);                     \
        }                                                                     \
    } while (0)

    const int lane = tid & 31;
    const int wid = tid >> 5;
    const int wm = (wid & 3) * 64;
    const int wn = (wid >> 2) * 64;
    const int qr = lane >> 2;
    const int qc = lane & 3;
    const int l7 = lane & 7;
    const uint32_t aRow = (uint32_t)(wm + (lane & 15)) * 128;
    const int aCb = lane >> 4;
    const uint32_t bRow = (uint32_t)(wn + l7 + ((lane >> 4) << 3)) * 128;
    const int bCb = (lane >> 3) & 1;

    float acc[4][8][4];
    #pragma unroll
    for (int mi = 0; mi < 4; mi++)
        #pragma unroll
        for (int ni = 0; ni < 8; ni++)
            #pragma unroll
            for (int q = 0; q < 4; q++) acc[mi][ni][q] = 0.f;

    const int nch = K >> 6;

    ISSUE3(0, 0);
    asm volatile("cp.async.commit_group;" ::: "memory");

    for (int ch = 0; ch < nch; ch++) {
        asm volatile("cp.async.wait_group 0;" ::: "memory");
        __syncthreads();
        if (ch + 1 < nch) {
            ISSUE3(ch + 1, (ch + 1) & 1);
            asm volatile("cp.async.commit_group;" ::: "memory");
        }

        const int slot = ch & 1;
        const uint32_t tAh = smb + slot * ST3 + aRow;
        const uint32_t tAl = smb + slot * ST3 + ATILE + aRow;
        const uint32_t tBh = smb + slot * ST3 + 2 * ATILE + bRow;
        const uint32_t tBl = smb + slot * ST3 + 2 * ATILE + BTILE + bRow;

        #pragma unroll
        for (int kk = 0; kk < 4; kk++) {
            const uint32_t aC = (uint32_t)((((kk << 1) + aCb) ^ l7) << 4);
            const uint32_t bC = (uint32_t)((((kk << 1) + bCb) ^ l7) << 4);
            uint32_t ah[4][4], al[4][4], bh[8][2], bl[8][2];
            #pragma unroll
            for (int mi = 0; mi < 4; mi++) {
                LDSM_X4(ah[mi][0], ah[mi][1], ah[mi][2], ah[mi][3], tAh + mi * 2048 + aC);
                LDSM_X4(al[mi][0], al[mi][1], al[mi][2], al[mi][3], tAl + mi * 2048 + aC);
            }
            #pragma unroll
            for (int g = 0; g < 4; g++) {
                LDSM_X4(bh[2*g][0], bh[2*g][1], bh[2*g+1][0], bh[2*g+1][1], tBh + g * 2048 + bC);
                LDSM_X4(bl[2*g][0], bl[2*g][1], bl[2*g+1][0], bl[2*g+1][1], tBl + g * 2048 + bC);
            }
            #pragma unroll
            for (int mi = 0; mi < 4; mi++)
                #pragma unroll
                for (int ni = 0; ni < 8; ni++) {
                    MMA_F16(acc[mi][ni], ah[mi], bl[ni]);
                    MMA_F16(acc[mi][ni], al[mi], bh[ni]);
                    MMA_F16(acc[mi][ni], ah[mi], bh[ni]);
                }
        }
    }
#undef ISSUE3

    const long long cOff = bb * cB + hh * cH;
    const int rbase = blockIdx.y * BM + wm + qr;
    const int cbase = blockIdx.x * BN + wn + (qc << 1);
    #pragma unroll
    for (int mi = 0; mi < 4; mi++) {
        #pragma unroll
        for (int ni = 0; ni < 8; ni++) {
            const long long r = rbase + mi * 16;
            const int c = cbase + ni * 8;
            float v[4] = {acc[mi][ni][0], acc[mi][ni][1], acc[mi][ni][2], acc[mi][ni][3]};
            if (outmode == 2) {
                __half h0 = __float2half_rn(v[0]), h1 = __float2half_rn(v[1]);
                __half h2 = __float2half_rn(v[2]), h3 = __float2half_rn(v[3]);
                __half* ch_ = Chh + cOff;
                __half* cl_ = Chl + cOff;
                *reinterpret_cast<__half2*>(&ch_[r * ldc + c])       = __halves2half2(h0, h1);
                *reinterpret_cast<__half2*>(&ch_[(r + 8) * ldc + c]) = __halves2half2(h2, h3);
                *reinterpret_cast<__half2*>(&cl_[r * ldc + c]) =
                    __halves2half2(__float2half_rn(v[0] - __half2float(h0)),
                                   __float2half_rn(v[1] - __half2float(h1)));
                *reinterpret_cast<__half2*>(&cl_[(r + 8) * ldc + c]) =
                    __halves2half2(__float2half_rn(v[2] - __half2float(h2)),
                                   __float2half_rn(v[3] - __half2float(h3)));
            } else {
                float* cb = Cf + cOff;
                __stcs(reinterpret_cast<float2*>(&cb[r * ldc + c]),
                       make_float2(v[0], v[1]));
                __stcs(reinterpret_cast<float2*>(&cb[(r + 8) * ldc + c]),
                       make_float2(v[2], v[3]));
            }
        }
    }
}

// ------------------------- softmax (2048 cols, fp32 -> half) ---------------
__global__ __launch_bounds__(256) void softmax2048(const float* __restrict__ sc,
                                                   __half* __restrict__ pr)
{
    __shared__ float red[8];
    const float4* p = reinterpret_cast<const float4*>(sc + (long long)blockIdx.x * 2048);
    __half2* q = reinterpret_cast<__half2*>(pr + (long long)blockIdx.x * 2048);
    const int t = threadIdx.x;
    const int wid = t >> 5, lid = t & 31;

    float4 a = __ldcs(p + t);
    float4 b = __ldcs(p + t + 256);

    float mx = fmaxf(fmaxf(fmaxf(a.x, a.y), fmaxf(a.z, a.w)),
                     fmaxf(fmaxf(b.x, b.y), fmaxf(b.z, b.w)));
    #pragma unroll
    for (int s = 16; s > 0; s >>= 1) mx = fmaxf(mx, __shfl_xor_sync(0xffffffffu, mx, s));
    if (lid == 0) red[wid] = mx;
    __syncthreads();
    if (t < 32) {
        float m = (t < 8) ? red[t] : -INFINITY;
        #pragma unroll
        for (int s = 4; s > 0; s >>= 1) m = fmaxf(m, __shfl_xor_sync(0xffffffffu, m, s));
        if (t == 0) red[0] = m;
    }
    __syncthreads();
    mx = red[0];
    __syncthreads();

    a.x = __expf(a.x - mx); a.y = __expf(a.y - mx); a.z = __expf(a.z - mx); a.w = __expf(a.w - mx);
    b.x = __expf(b.x - mx); b.y = __expf(b.y - mx); b.z = __expf(b.z - mx); b.w = __expf(b.w - mx);
    float sum = a.x + a.y + a.z + a.w + b.x + b.y + b.z + b.w;
    #pragma unroll
    for (int s = 16; s > 0; s >>= 1) sum += __shfl_xor_sync(0xffffffffu, sum, s);
    if (lid == 0) red[wid] = sum;
    __syncthreads();
    if (t < 32) {
        float m = (t < 8) ? red[t] : 0.f;
        #pragma unroll
        for (int s = 4; s > 0; s >>= 1) m += __shfl_xor_sync(0xffffffffu, m, s);
        if (t == 0) red[0] = m;
    }
    __syncthreads();
    float inv = 1.0f / red[0];

    __half2 q0 = __halves2half2(__float2half_rn(a.x * inv), __float2half_rn(a.y * inv));
    __half2 q1 = __halves2half2(__float2half_rn(a.z * inv), __float2half_rn(a.w * inv));
    __half2 q2 = __halves2half2(__float2half_rn(b.x * inv), __float2half_rn(b.y * inv));
    __half2 q3 = __halves2half2(__float2half_rn(b.z * inv), __float2half_rn(b.w * inv));
    uint2 u01 = make_uint2(*reinterpret_cast<uint32_t*>(&q0), *reinterpret_cast<uint32_t*>(&q1));
    uint2 u23 = make_uint2(*reinterpret_cast<uint32_t*>(&q2), *reinterpret_cast<uint32_t*>(&q3));
    __stcs(reinterpret_cast<uint2*>(q + t * 2), u01);
    __stcs(reinterpret_cast<uint2*>(q + (t + 256) * 2), u23);
}

// ------------------------------ host side ----------------------------------
template <typename T>
static T* sym_addr(const void* symbol)
{
    void* p = nullptr;
    cudaGetSymbolAddress(&p, symbol);
    return (T*)p;
}

extern "C" void kernel_launch(void* const* d_in, const int* in_sizes, int n_in,
                              void* d_out, int out_size)
{
    const float* x     = (const float*)d_in[0];
    const float* blade = (const float*)d_in[1];
    const float* w_q   = (const float*)d_in[2];
    const float* w_k   = (const float*)d_in[3];
    const float* w_v   = (const float*)d_in[4];
    const float* w_o   = (const float*)d_in[5];
    float* out = (float*)d_out;

    __half* xh   = sym_addr<__half>(g_xh),   *xl   = sym_addr<__half>(g_xl);
    __half* Wqkh = sym_addr<__half>(g_Wqkh), *Wqkl = sym_addr<__half>(g_Wqkl);
    __half* Wvh  = sym_addr<__half>(g_Wvh);
    __half* Woh  = sym_addr<__half>(g_Woh);
    __half* qkmh = sym_addr<__half>(g_qkmh), *qkml = sym_addr<__half>(g_qkml);
    __half* vT   = sym_addr<__half>(g_vT);
    float*  sc   = sym_addr<float >(g_sc);
    __half* pr   = sym_addr<__half>(g_pr);
    __half* ao   = sym_addr<__half>(g_ao);

    static cudaStream_t s1 = nullptr, s2 = nullptr;
    static cudaEvent_t eF = nullptr, e0 = nullptr, e1 = nullptr, e3 = nullptr, e4 = nullptr;
    if (s1 == nullptr) {
        cudaStreamCreateWithFlags(&s1, cudaStreamNonBlocking);
        cudaStreamCreateWithFlags(&s2, cudaStreamNonBlocking);
        cudaEventCreateWithFlags(&eF, cudaEventDisableTiming);
        cudaEventCreateWithFlags(&e0, cudaEventDisableTiming);
        cudaEventCreateWithFlags(&e1, cudaEventDisableTiming);
        cudaEventCreateWithFlags(&e3, cudaEventDisableTiming);
        cudaEventCreateWithFlags(&e4, cudaEventDisableTiming);
        cudaFuncSetAttribute(gemm_h1, cudaFuncAttributeMaxDynamicSharedMemorySize, SMEM_1);
        cudaFuncSetAttribute(gemm_h3, cudaFuncAttributeMaxDynamicSharedMemorySize, SMEM_3);
    }

    const float scale = 1.0f / sqrtf(512.0f);

    // per-batch offsets
    const long long xOff   = 2048LL * 1024;     // token rows
    const long long qkOff  = 2048LL * 4608;
    const long long scOff  = 8LL * 2048 * 2048;
    const long long aoOff  = 2048LL * 8192;
    const long long outOff = 2048LL * 1024;

    // ---- fork ----
    cudaEventRecord(eF, 0);
    cudaStreamWaitEvent(s1, eF, 0);
    cudaStreamWaitEvent(s2, eF, 0);

    // s1: q+k weight precompute
    {
        long long tq = 4096LL * 1024;
        make_weightT<<<(unsigned)((tq + 255) / 256), 256, 0, s1>>>(
            w_q, blade, Wqkh, Wqkl, 64, 1, scale, tq, 1024, 1);
        long long tk = 512LL * 1024;
        make_weightT<<<(unsigned)((tk + 255) / 256), 256, 0, s1>>>(
            w_k, blade, Wqkh + 4096LL * 1024, Wqkl + 4096LL * 1024, 64, 2, 1.0f, tk, 1024, 1);
        cudaEventRecord(e1, s1);
    }
    // s2: v + o weight precompute
    {
        long long tv = 1024LL * 1024;
        make_weightT<<<(unsigned)((tv + 255) / 256), 256, 0, s2>>>(
            w_v, blade, Wvh, nullptr, 64, 0, 1.0f, tv, 1024, 0);
        long long to = 1024LL * 8192;
        make_weightT<<<(unsigned)((to + 255) / 256), 256, 0, s2>>>(
            w_o, blade, Woh, nullptr, 512, 0, 1.0f, to, 8192, 0);
    }

    // main: input split
    split_f16<<<4096, 256>>>((const float4*)x, (__half2*)xh, (__half2*)xl, 4096 * 1024 / 4);
    cudaEventRecord(e0, 0);

    // s2: v projection (all tokens) — covers Wv/Wo ordering for consumers of e3
    cudaStreamWaitEvent(s2, e0, 0);
    gemm_h1<<<dim3(4096 / 128, 1024 / 256, 1), 256, SMEM_1, s2>>>(
        Wvh, xh, nullptr, vT, 1024, 1024, 1024, 4096,
        0, 0, 0, 0, 0, 0, 1, 1);
    cudaEventRecord(e3, s2);

    // ---- per-batch pipelines: batch 0 on stream 0, batch 1 on s1 ----
    cudaStreamWaitEvent(0, e1, 0);     // batch-0 chain needs Wqk
    cudaStreamWaitEvent(s1, e0, 0);    // batch-1 chain needs split (Wqk in-stream on s1)

    cudaStream_t bs[2] = { (cudaStream_t)0, s1 };
    for (int b = 0; b < 2; b++) {
        cudaStream_t st = bs[b];

        // qk projection (rows of batch b)
        gemm_h3<<<dim3(4608 / 128, 2048 / 256, 1), 256, SMEM_3, st>>>(
            xh + b * xOff, xl + b * xOff, Wqkh, Wqkl,
            nullptr, qkmh + b * qkOff, qkml + b * qkOff,
            1024, 1024, 1024, 4608,
            0, 0, 0, 0, 0, 0, 1, 2);

        // scores for batch b (8 heads)
        gemm_h3<<<dim3(2048 / 128, 2048 / 256, 8), 256, SMEM_3, st>>>(
            qkmh + b * qkOff, qkml + b * qkOff,
            qkmh + b * qkOff + 4096, qkml + b * qkOff + 4096,
            sc + b * scOff, nullptr, nullptr,
            512, 4608, 4608, 2048,
            /*aB*/ 0, /*aH*/ 512,
            /*bB*/ 0, /*bH*/ 0,
            /*cB*/ 0, /*cH*/ 2048LL * 2048, 8, 0);

        // softmax for batch b
        softmax2048<<<8 * 2048, 256, 0, st>>>(sc + b * scOff, pr + b * scOff);

        // attn @ V for batch b (needs vT)
        cudaStreamWaitEvent(st, e3, 0);
        gemm_h1<<<dim3(1024 / 128, 2048 / 256, 8), 256, SMEM_1, st>>>(
            pr + b * scOff, vT + b * 2048, nullptr, ao + b * aoOff,
            2048, 2048, 4096, 8192,
            /*aB*/ 0, /*aH*/ 2048LL * 2048,
            /*bB*/ 0, /*bH*/ 0,
            /*cB*/ 0, /*cH*/ 1024, 8, 1);

        // output projection for batch b
        gemm_h1<<<dim3(1024 / 128, 2048 / 256, 1), 256, SMEM_1, st>>>(
            ao + b * aoOff, Woh, out + b * outOff, nullptr,
            8192, 8192, 8192, 1024,
            0, 0, 0, 0, 0, 0, 1, 0);
    }

    // join batch-1 chain back to main stream
    cudaEventRecord(e4, s1);
    cudaStreamWaitEvent(0, e4, 0);
}

// round 11
// speedup vs baseline: 5.8550x; 1.0646x over previous
#include <cuda_runtime.h>
#include <cuda_fp16.h>
#include <math.h>
#include <stdint.h>

// ---------------------------------------------------------------------------
// GeometricAttentionLayer on GB300 — fp16 mma.sync + ldmatrix engine v5
//   CTA tile 256x128, warp tile 64x64 (8 warps, 1 CTA/SM), BK=64.
//   Split (3-pass) GEMMs: q+k proj (merged), scores.
//   Single-pass GEMMs:    v-proj, attn@V, out-proj.
//   v5: fast weight precompute (smem blade, 16 outputs/thread, coalesced).
// ---------------------------------------------------------------------------

#define BM 256
#define BN 128
#define BK 64
#define ATILE 32768                       // 256 rows x 128 B
#define BTILE 16384                       // 128 rows x 128 B
#define ST1 (ATILE + BTILE)               // 48 KB / stage
#define SMEM_1 (3 * ST1)                  // 144 KB
#define ST3 (2 * ATILE + 2 * BTILE)       // 96 KB / stage
#define SMEM_3 (2 * ST3)                  // 192 KB

__constant__ int c_ip[8] = {0, 2, 3, 4, 8, 9, 10, 14};

// ------------------------- scratch (device globals) ------------------------
__device__ __align__(1024) __half g_xh  [4096LL * 1024];
__device__ __align__(1024) __half g_xl  [4096LL * 1024];
__device__ __align__(1024) __half g_Wqkh[4608 * 1024];       // q cols 0..4095, k cols 4096..4607
__device__ __align__(1024) __half g_Wqkl[4608 * 1024];
__device__ __align__(1024) __half g_Wvh [1024 * 1024];
__device__ __align__(1024) __half g_Woh [1024 * 8192];
__device__ __align__(1024) __half g_qkmh[4096LL * 4608];
__device__ __align__(1024) __half g_qkml[4096LL * 4608];
__device__ __align__(1024) __half g_vT  [1024LL * 4096];
__device__ __align__(1024) float  g_sc  [16LL * 2048 * 2048];
__device__ __align__(1024) __half g_pr  [16LL * 2048 * 2048];
__device__ __align__(1024) __half g_ao  [4096LL * 8192];

// ------------------------------ helpers ------------------------------------
__device__ __forceinline__ uint32_t smem_u32(const void* p) {
    uint32_t a;
    asm("{ .reg .u64 t; cvta.to.shared.u64 t, %1; cvt.u32.u64 %0, t; }" : "=r"(a) : "l"(p));
    return a;
}

__device__ __forceinline__ void cp16(uint32_t dst, const __half* src) {
    asm volatile("cp.async.cg.shared.global [%0], [%1], 16;"
                 :: "r"(dst), "l"(src) : "memory");
}

#define LDSM_X4(r0, r1, r2, r3, addr)                                         \
    asm volatile("ldmatrix.sync.aligned.m8n8.x4.shared.b16 {%0,%1,%2,%3}, [%4];" \
        : "=r"(r0), "=r"(r1), "=r"(r2), "=r"(r3) : "r"(addr))

#define MMA_F16(acc, a, b)                                                    \
    asm volatile(                                                             \
        "mma.sync.aligned.m16n8k16.row.col.f32.f16.f16.f32 "                  \
        "{%0,%1,%2,%3}, {%4,%5,%6,%7}, {%8,%9}, {%0,%1,%2,%3};"               \
        : "+f"((acc)[0]), "+f"((acc)[1]), "+f"((acc)[2]), "+f"((acc)[3])      \
        : "r"((a)[0]), "r"((a)[1]), "r"((a)[2]), "r"((a)[3]),                 \
          "r"((b)[0]), "r"((b)[1]))

// ------------------- weight precompute v2 (smem blade, 16 out/thread) ------
// Thread t handles (col = t / I, i = t % I) and emits W^T[col, i*16 + 0..15].
// Same per-element FMA order as v1 -> bit-identical weights.
__global__ __launch_bounds__(256) void make_weightT2(
    const float* __restrict__ w, const float* __restrict__ blade,
    __half* __restrict__ Wh, __half* __restrict__ Wl,
    int I, int mode, float scale, long long totalThreads, int storeLo)
{
    __shared__ float bl[9 * 256];
    for (int idx = threadIdx.x; idx < 9 * 256; idx += 256)
        bl[idx] = blade[idx];
    __syncthreads();

    long long t = (long long)blockIdx.x * 256 + threadIdx.x;
    if (t >= totalThreads) return;
    int col = (int)(t / I);
    int i   = (int)(t % I);

    int j, y;
    if (mode == 0)      { j = col >> 4; y = col & 15; }
    else if (mode == 1) { int e = col & 7; int d = (col >> 3) & 63; int h = col >> 9;
                          j = d * 8 + h; y = c_ip[e]; }
    else                { int e = col & 7; j = col >> 3; y = c_ip[e]; }

    float wr[9];
    const float* wp = w + ((long long)j * I + i) * 9;
    #pragma unroll
    for (int b = 0; b < 9; b++) wr[b] = wp[b];

    __half2 hv[8], lv[8];
    #pragma unroll
    for (int xc2 = 0; xc2 < 8; xc2++) {
        float s0 = 0.f, s1 = 0.f;
        #pragma unroll
        for (int b = 0; b < 9; b++) {
            s0 += wr[b] * bl[b * 256 + (xc2 * 2 + 0) * 16 + y];
            s1 += wr[b] * bl[b * 256 + (xc2 * 2 + 1) * 16 + y];
        }
        s0 *= scale; s1 *= scale;
        __half h0 = __float2half_rn(s0), h1 = __float2half_rn(s1);
        hv[xc2] = __halves2half2(h0, h1);
        lv[xc2] = __halves2half2(__float2half_rn(s0 - __half2float(h0)),
                                 __float2half_rn(s1 - __half2float(h1)));
    }

    long long base = (long long)col * (I * 16) + i * 16;
    __half2* oh = reinterpret_cast<__half2*>(Wh + base);
    #pragma unroll
    for (int u = 0; u < 8; u++) oh[u] = hv[u];
    if (storeLo) {
        __half2* ol = reinterpret_cast<__half2*>(Wl + base);
        #pragma unroll
        for (int u = 0; u < 8; u++) ol[u] = lv[u];
    }
}

// ------------------------------ fp16 split pass ----------------------------
__global__ void split_f16(const float4* __restrict__ in,
                          __half2* __restrict__ oh, __half2* __restrict__ ol, int n4)
{
    int i = blockIdx.x * 256 + threadIdx.x;
    if (i >= n4) return;
    float4 v = in[i];
    __half hx = __float2half_rn(v.x), hy = __float2half_rn(v.y);
    __half hz = __float2half_rn(v.z), hw = __float2half_rn(v.w);
    oh[i * 2 + 0] = __halves2half2(hx, hy);
    oh[i * 2 + 1] = __halves2half2(hz, hw);
    ol[i * 2 + 0] = __halves2half2(__float2half_rn(v.x - __half2float(hx)),
                                   __float2half_rn(v.y - __half2float(hy)));
    ol[i * 2 + 1] = __halves2half2(__float2half_rn(v.z - __half2float(hz)),
                                   __float2half_rn(v.w - __half2float(hw)));
}

// ------------------------------ single fp16 GEMM (NT) ----------------------
// C[m,n] = sum_k A[m,k]*B[n,k].  halfout: 0 -> fp32 C, 1 -> half C.
__global__ __launch_bounds__(256, 1) void gemm_h1(
    const __half* __restrict__ Ag, const __half* __restrict__ Bg,
    float* __restrict__ Cf, __half* __restrict__ Chh,
    int K, int lda, int ldb, int ldc,
    long long aB, long long aH, long long bB, long long bH,
    long long cB, long long cH, int nH, int halfout)
{
    extern __shared__ char sm[];
    const uint32_t smb = smem_u32(sm);

    const int tid = threadIdx.x;
    const int bb = blockIdx.z / nH, hh = blockIdx.z - bb * nH;
    const __half* A = Ag + bb * aB + hh * aH + (long long)(blockIdx.y * BM) * lda;
    const __half* B = Bg + bb * bB + hh * bH + (long long)(blockIdx.x * BN) * ldb;

    const int ldrow = tid >> 3;
    const int seg   = tid & 7;
    const uint32_t swoff = (uint32_t)((seg ^ (ldrow & 7)) << 4);

#define ISSUE1(ch, slot) do {                                                 \
        const __half* _a = A + (long long)(ch) * BK + (seg << 3);             \
        uint32_t _da = smb + (uint32_t)(slot) * ST1;                          \
        _Pragma("unroll")                                                     \
        for (int _i = 0; _i < 8; _i++)                                        \
            cp16(_da + (uint32_t)((ldrow + 32 * _i) * 128) + swoff,           \
                 _a + (long long)(ldrow + 32 * _i) * lda);                    \
        const __half* _b = B + (long long)(ch) * BK + (seg << 3);             \
        uint32_t _db = smb + (uint32_t)(slot) * ST1 + ATILE;                  \
        _Pragma("unroll")                                                     \
        for (int _i = 0; _i < 4; _i++)                                        \
            cp16(_db + (uint32_t)((ldrow + 32 * _i) * 128) + swoff,           \
                 _b + (long long)(ldrow + 32 * _i) * ldb);                    \
    } while (0)

    const int lane = tid & 31;
    const int wid = tid >> 5;
    const int wm = (wid & 3) * 64;
    const int wn = (wid >> 2) * 64;
    const int qr = lane >> 2;
    const int qc = lane & 3;
    const int l7 = lane & 7;
    const uint32_t aRow = (uint32_t)(wm + (lane & 15)) * 128;
    const int aCb = lane >> 4;
    const uint32_t bRow = (uint32_t)(wn + l7 + ((lane >> 4) << 3)) * 128;
    const int bCb = (lane >> 3) & 1;

    float acc[4][8][4];
    #pragma unroll
    for (int mi = 0; mi < 4; mi++)
        #pragma unroll
        for (int ni = 0; ni < 8; ni++)
            #pragma unroll
            for (int q = 0; q < 4; q++) acc[mi][ni][q] = 0.f;

    const int nch = K >> 6;

    #pragma unroll
    for (int p = 0; p < 2; p++) {
        if (p < nch) ISSUE1(p, p);
        asm volatile("cp.async.commit_group;" ::: "memory");
    }

    uint32_t a[2][4][4], b[2][8][2];

#define LOADFRAG1(kk, buf, tA, tB) do {                                       \
        const uint32_t _aC = (uint32_t)(((((kk) << 1) + aCb) ^ l7) << 4);     \
        const uint32_t _bC = (uint32_t)(((((kk) << 1) + bCb) ^ l7) << 4);     \
        _Pragma("unroll")                                                     \
        for (int _mi = 0; _mi < 4; _mi++)                                     \
            LDSM_X4(a[buf][_mi][0], a[buf][_mi][1], a[buf][_mi][2],           \
                    a[buf][_mi][3], (tA) + _mi * 2048 + _aC);                 \
        _Pragma("unroll")                                                     \
        for (int _g = 0; _g < 4; _g++)                                        \
            LDSM_X4(b[buf][2*_g][0], b[buf][2*_g][1], b[buf][2*_g+1][0],      \
                    b[buf][2*_g+1][1], (tB) + _g * 2048 + _bC);               \
    } while (0)

    for (int ch = 0; ch < nch; ch++) {
        asm volatile("cp.async.wait_group 1;" ::: "memory");
        __syncthreads();

        int pf = ch + 2;
        if (pf < nch) ISSUE1(pf, pf % 3);
        asm volatile("cp.async.commit_group;" ::: "memory");

        const int slot = ch % 3;
        const uint32_t tA = smb + slot * ST1 + aRow;
        const uint32_t tB = smb + slot * ST1 + ATILE + bRow;

        LOADFRAG1(0, 0, tA, tB);
        #pragma unroll
        for (int kk = 0; kk < 4; kk++) {
            const int cur = kk & 1;
            if (kk < 3) LOADFRAG1(kk + 1, cur ^ 1, tA, tB);
            #pragma unroll
            for (int mi = 0; mi < 4; mi++)
                #pragma unroll
                for (int ni = 0; ni < 8; ni++)
                    MMA_F16(acc[mi][ni], a[cur][mi], b[cur][ni]);
        }
    }
#undef LOADFRAG1
#undef ISSUE1

    const long long cOff = bb * cB + hh * cH;
    const int rbase = blockIdx.y * BM + wm + qr;
    const int cbase = blockIdx.x * BN + wn + (qc << 1);
    #pragma unroll
    for (int mi = 0; mi < 4; mi++) {
        #pragma unroll
        for (int ni = 0; ni < 8; ni++) {
            const long long r = rbase + mi * 16;
            const int c = cbase + ni * 8;
            if (halfout) {
                __half* cb = Chh + cOff;
                *reinterpret_cast<__half2*>(&cb[r * ldc + c]) =
                    __halves2half2(__float2half_rn(acc[mi][ni][0]),
                                   __float2half_rn(acc[mi][ni][1]));
                *reinterpret_cast<__half2*>(&cb[(r + 8) * ldc + c]) =
                    __halves2half2(__float2half_rn(acc[mi][ni][2]),
                                   __float2half_rn(acc[mi][ni][3]));
            } else {
                float* cb = Cf + cOff;
                *reinterpret_cast<float2*>(&cb[r * ldc + c]) =
                    make_float2(acc[mi][ni][0], acc[mi][ni][1]);
                *reinterpret_cast<float2*>(&cb[(r + 8) * ldc + c]) =
                    make_float2(acc[mi][ni][2], acc[mi][ni][3]);
            }
        }
    }
}

// ------------------------------ 3-term fp16 split GEMM (NT) ----------------
// acc += Ahi*Bhi + Ahi*Blo + Alo*Bhi.  outmode: 0 -> fp32 C (.cs), 2 -> split half C.
__global__ __launch_bounds__(256, 1) void gemm_h3(
    const __half* __restrict__ Ah, const __half* __restrict__ Al,
    const __half* __restrict__ Bh, const __half* __restrict__ Bl,
    float* __restrict__ Cf, __half* __restrict__ Chh, __half* __restrict__ Chl,
    int K, int lda, int ldb, int ldc,
    long long aB, long long aH, long long bB, long long bH,
    long long cB, long long cH, int nH, int outmode)
{
    extern __shared__ char sm[];
    const uint32_t smb = smem_u32(sm);

    const int tid = threadIdx.x;
    const int bb = blockIdx.z / nH, hh = blockIdx.z - bb * nH;
    const long long aOff = bb * aB + hh * aH + (long long)(blockIdx.y * BM) * lda;
    const long long bOff = bb * bB + hh * bH + (long long)(blockIdx.x * BN) * ldb;
    const __half* pAh = Ah + aOff;
    const __half* pAl = Al + aOff;
    const __half* pBh = Bh + bOff;
    const __half* pBl = Bl + bOff;

    const int ldrow = tid >> 3;
    const int seg   = tid & 7;
    const uint32_t swoff = (uint32_t)((seg ^ (ldrow & 7)) << 4);

#define ISSUE3(ch, slot) do {                                                 \
        uint32_t _sb = smb + (uint32_t)(slot) * ST3;                          \
        const __half* _s0 = pAh + (long long)(ch) * BK + (seg << 3);          \
        const __half* _s1 = pAl + (long long)(ch) * BK + (seg << 3);          \
        _Pragma("unroll")                                                     \
        for (int _i = 0; _i < 8; _i++) {                                      \
            uint32_t _o = (uint32_t)((ldrow + 32 * _i) * 128) + swoff;        \
            long long _g = (long long)(ldrow + 32 * _i) * lda;                \
            cp16(_sb + _o, _s0 + _g);                                         \
            cp16(_sb + ATILE + _o, _s1 + _g);                                 \
        }                                                                     \
        const __half* _s2 = pBh + (long long)(ch) * BK + (seg << 3);          \
        const __half* _s3 = pBl + (long long)(ch) * BK + (seg << 3);          \
        _Pragma("unroll")                                                     \
        for (int _i = 0; _i < 4; _i++) {                                      \
            uint32_t _o = (uint32_t)((ldrow + 32 * _i) * 128) + swoff;        \
            long long _g = (long long)(ldrow + 32 * _i) * ldb;                \
            cp16(_sb + 2 * ATILE + _o, _s2 + _g);                             \
            cp16(_sb + 2 * ATILE + BTILE + _o, _s3 + _g);                     \
        }                                                                     \
    } while (0)

    const int lane = tid & 31;
    const int wid = tid >> 5;
    const int wm = (wid & 3) * 64;
    const int wn = (wid >> 2) * 64;
    const int qr = lane >> 2;
    const int qc = lane & 3;
    const int l7 = lane & 7;
    const uint32_t aRow = (uint32_t)(wm + (lane & 15)) * 128;
    const int aCb = lane >> 4;
    const uint32_t bRow = (uint32_t)(wn + l7 + ((lane >> 4) << 3)) * 128;
    const int bCb = (lane >> 3) & 1;

    float acc[4][8][4];
    #pragma unroll
    for (int mi = 0; mi < 4; mi++)
        #pragma unroll
        for (int ni = 0; ni < 8; ni++)
            #pragma unroll
            for (int q = 0; q < 4; q++) acc[mi][ni][q] = 0.f;

    const int nch = K >> 6;

    ISSUE3(0, 0);
    asm volatile("cp.async.commit_group;" ::: "memory");

    for (int ch = 0; ch < nch; ch++) {
        asm volatile("cp.async.wait_group 0;" ::: "memory");
        __syncthreads();
        if (ch + 1 < nch) {
            ISSUE3(ch + 1, (ch + 1) & 1);
            asm volatile("cp.async.commit_group;" ::: "memory");
        }

        const int slot = ch & 1;
        const uint32_t tAh = smb + slot * ST3 + aRow;
        const uint32_t tAl = smb + slot * ST3 + ATILE + aRow;
        const uint32_t tBh = smb + slot * ST3 + 2 * ATILE + bRow;
        const uint32_t tBl = smb + slot * ST3 + 2 * ATILE + BTILE + bRow;

        #pragma unroll
        for (int kk = 0; kk < 4; kk++) {
            const uint32_t aC = (uint32_t)((((kk << 1) + aCb) ^ l7) << 4);
            const uint32_t bC = (uint32_t)((((kk << 1) + bCb) ^ l7) << 4);
            uint32_t ah[4][4], al[4][4], bh[8][2], bl[8][2];
            #pragma unroll
            for (int mi = 0; mi < 4; mi++) {
                LDSM_X4(ah[mi][0], ah[mi][1], ah[mi][2], ah[mi][3], tAh + mi * 2048 + aC);
                LDSM_X4(al[mi][0], al[mi][1], al[mi][2], al[mi][3], tAl + mi * 2048 + aC);
            }
            #pragma unroll
            for (int g = 0; g < 4; g++) {
                LDSM_X4(bh[2*g][0], bh[2*g][1], bh[2*g+1][0], bh[2*g+1][1], tBh + g * 2048 + bC);
                LDSM_X4(bl[2*g][0], bl[2*g][1], bl[2*g+1][0], bl[2*g+1][1], tBl + g * 2048 + bC);
            }
            #pragma unroll
            for (int mi = 0; mi < 4; mi++)
                #pragma unroll
                for (int ni = 0; ni < 8; ni++) {
                    MMA_F16(acc[mi][ni], ah[mi], bl[ni]);
                    MMA_F16(acc[mi][ni], al[mi], bh[ni]);
                    MMA_F16(acc[mi][ni], ah[mi], bh[ni]);
                }
        }
    }
#undef ISSUE3

    const long long cOff = bb * cB + hh * cH;
    const int rbase = blockIdx.y * BM + wm + qr;
    const int cbase = blockIdx.x * BN + wn + (qc << 1);
    #pragma unroll
    for (int mi = 0; mi < 4; mi++) {
        #pragma unroll
        for (int ni = 0; ni < 8; ni++) {
            const long long r = rbase + mi * 16;
            const int c = cbase + ni * 8;
            float v[4] = {acc[mi][ni][0], acc[mi][ni][1], acc[mi][ni][2], acc[mi][ni][3]};
            if (outmode == 2) {
                __half h0 = __float2half_rn(v[0]), h1 = __float2half_rn(v[1]);
                __half h2 = __float2half_rn(v[2]), h3 = __float2half_rn(v[3]);
                __half* ch_ = Chh + cOff;
                __half* cl_ = Chl + cOff;
                *reinterpret_cast<__half2*>(&ch_[r * ldc + c])       = __halves2half2(h0, h1);
                *reinterpret_cast<__half2*>(&ch_[(r + 8) * ldc + c]) = __halves2half2(h2, h3);
                *reinterpret_cast<__half2*>(&cl_[r * ldc + c]) =
                    __halves2half2(__float2half_rn(v[0] - __half2float(h0)),
                                   __float2half_rn(v[1] - __half2float(h1)));
                *reinterpret_cast<__half2*>(&cl_[(r + 8) * ldc + c]) =
                    __halves2half2(__float2half_rn(v[2] - __half2float(h2)),
                                   __float2half_rn(v[3] - __half2float(h3)));
            } else {
                float* cb = Cf + cOff;
                __stcs(reinterpret_cast<float2*>(&cb[r * ldc + c]),
                       make_float2(v[0], v[1]));
                __stcs(reinterpret_cast<float2*>(&cb[(r + 8) * ldc + c]),
                       make_float2(v[2], v[3]));
            }
        }
    }
}

// ------------------------- softmax (2048 cols, fp32 -> half) ---------------
__global__ __launch_bounds__(256) void softmax2048(const float* __restrict__ sc,
                                                   __half* __restrict__ pr)
{
    __shared__ float red[8];
    const float4* p = reinterpret_cast<const float4*>(sc + (long long)blockIdx.x * 2048);
    __half2* q = reinterpret_cast<__half2*>(pr + (long long)blockIdx.x * 2048);
    const int t = threadIdx.x;
    const int wid = t >> 5, lid = t & 31;

    float4 a = __ldcs(p + t);
    float4 b = __ldcs(p + t + 256);

    float mx = fmaxf(fmaxf(fmaxf(a.x, a.y), fmaxf(a.z, a.w)),
                     fmaxf(fmaxf(b.x, b.y), fmaxf(b.z, b.w)));
    #pragma unroll
    for (int s = 16; s > 0; s >>= 1) mx = fmaxf(mx, __shfl_xor_sync(0xffffffffu, mx, s));
    if (lid == 0) red[wid] = mx;
    __syncthreads();
    if (t < 32) {
        float m = (t < 8) ? red[t] : -INFINITY;
        #pragma unroll
        for (int s = 4; s > 0; s >>= 1) m = fmaxf(m, __shfl_xor_sync(0xffffffffu, m, s));
        if (t == 0) red[0] = m;
    }
    __syncthreads();
    mx = red[0];
    __syncthreads();

    a.x = __expf(a.x - mx); a.y = __expf(a.y - mx); a.z = __expf(a.z - mx); a.w = __expf(a.w - mx);
    b.x = __expf(b.x - mx); b.y = __expf(b.y - mx); b.z = __expf(b.z - mx); b.w = __expf(b.w - mx);
    float sum = a.x + a.y + a.z + a.w + b.x + b.y + b.z + b.w;
    #pragma unroll
    for (int s = 16; s > 0; s >>= 1) sum += __shfl_xor_sync(0xffffffffu, sum, s);
    if (lid == 0) red[wid] = sum;
    __syncthreads();
    if (t < 32) {
        float m = (t < 8) ? red[t] : 0.f;
        #pragma unroll
        for (int s = 4; s > 0; s >>= 1) m += __shfl_xor_sync(0xffffffffu, m, s);
        if (t == 0) red[0] = m;
    }
    __syncthreads();
    float inv = 1.0f / red[0];

    __half2 q0 = __halves2half2(__float2half_rn(a.x * inv), __float2half_rn(a.y * inv));
    __half2 q1 = __halves2half2(__float2half_rn(a.z * inv), __float2half_rn(a.w * inv));
    __half2 q2 = __halves2half2(__float2half_rn(b.x * inv), __float2half_rn(b.y * inv));
    __half2 q3 = __halves2half2(__float2half_rn(b.z * inv), __float2half_rn(b.w * inv));
    uint2 u01 = make_uint2(*reinterpret_cast<uint32_t*>(&q0), *reinterpret_cast<uint32_t*>(&q1));
    uint2 u23 = make_uint2(*reinterpret_cast<uint32_t*>(&q2), *reinterpret_cast<uint32_t*>(&q3));
    __stcs(reinterpret_cast<uint2*>(q + t * 2), u01);
    __stcs(reinterpret_cast<uint2*>(q + (t + 256) * 2), u23);
}

// ------------------------------ host side ----------------------------------
template <typename T>
static T* sym_addr(const void* symbol)
{
    void* p = nullptr;
    cudaGetSymbolAddress(&p, symbol);
    return (T*)p;
}

extern "C" void kernel_launch(void* const* d_in, const int* in_sizes, int n_in,
                              void* d_out, int out_size)
{
    const float* x     = (const float*)d_in[0];
    const float* blade = (const float*)d_in[1];
    const float* w_q   = (const float*)d_in[2];
    const float* w_k   = (const float*)d_in[3];
    const float* w_v   = (const float*)d_in[4];
    const float* w_o   = (const float*)d_in[5];
    float* out = (float*)d_out;

    __half* xh   = sym_addr<__half>(g_xh),   *xl   = sym_addr<__half>(g_xl);
    __half* Wqkh = sym_addr<__half>(g_Wqkh), *Wqkl = sym_addr<__half>(g_Wqkl);
    __half* Wvh  = sym_addr<__half>(g_Wvh);
    __half* Woh  = sym_addr<__half>(g_Woh);
    __half* qkmh = sym_addr<__half>(g_qkmh), *qkml = sym_addr<__half>(g_qkml);
    __half* vT   = sym_addr<__half>(g_vT);
    float*  sc   = sym_addr<float >(g_sc);
    __half* pr   = sym_addr<__half>(g_pr);
    __half* ao   = sym_addr<__half>(g_ao);

    static cudaStream_t s1 = nullptr, s2 = nullptr;
    static cudaEvent_t eF = nullptr, e0 = nullptr, e1 = nullptr, e3 = nullptr, e4 = nullptr;
    if (s1 == nullptr) {
        cudaStreamCreateWithFlags(&s1, cudaStreamNonBlocking);
        cudaStreamCreateWithFlags(&s2, cudaStreamNonBlocking);
        cudaEventCreateWithFlags(&eF, cudaEventDisableTiming);
        cudaEventCreateWithFlags(&e0, cudaEventDisableTiming);
        cudaEventCreateWithFlags(&e1, cudaEventDisableTiming);
        cudaEventCreateWithFlags(&e3, cudaEventDisableTiming);
        cudaEventCreateWithFlags(&e4, cudaEventDisableTiming);
        cudaFuncSetAttribute(gemm_h1, cudaFuncAttributeMaxDynamicSharedMemorySize, SMEM_1);
        cudaFuncSetAttribute(gemm_h3, cudaFuncAttributeMaxDynamicSharedMemorySize, SMEM_3);
    }

    const float scale = 1.0f / sqrtf(512.0f);

    // per-batch offsets
    const long long xOff   = 2048LL * 1024;
    const long long qkOff  = 2048LL * 4608;
    const long long scOff  = 8LL * 2048 * 2048;
    const long long aoOff  = 2048LL * 8192;
    const long long outOff = 2048LL * 1024;

    // ---- fork ----
    cudaEventRecord(eF, 0);
    cudaStreamWaitEvent(s1, eF, 0);
    cudaStreamWaitEvent(s2, eF, 0);

    // s1: q+k weight precompute (fast path: threads = cols * I)
    {
        long long tq = 4096LL * 64;     // q cols x I
        make_weightT2<<<(unsigned)((tq + 255) / 256), 256, 0, s1>>>(
            w_q, blade, Wqkh, Wqkl, 64, 1, scale, tq, 1);
        long long tk = 512LL * 64;
        make_weightT2<<<(unsigned)((tk + 255) / 256), 256, 0, s1>>>(
            w_k, blade, Wqkh + 4096LL * 1024, Wqkl + 4096LL * 1024, 64, 2, 1.0f, tk, 1);
        cudaEventRecord(e1, s1);
    }
    // s2: v + o weight precompute
    {
        long long tv = 1024LL * 64;
        make_weightT2<<<(unsigned)((tv + 255) / 256), 256, 0, s2>>>(
            w_v, blade, Wvh, nullptr, 64, 0, 1.0f, tv, 0);
        long long to = 1024LL * 512;
        make_weightT2<<<(unsigned)((to + 255) / 256), 256, 0, s2>>>(
            w_o, blade, Woh, nullptr, 512, 0, 1.0f, to, 0);
    }

    // main: input split
    split_f16<<<4096, 256>>>((const float4*)x, (__half2*)xh, (__half2*)xl, 4096 * 1024 / 4);
    cudaEventRecord(e0, 0);

    // s2: v projection (all tokens)
    cudaStreamWaitEvent(s2, e0, 0);
    gemm_h1<<<dim3(4096 / 128, 1024 / 256, 1), 256, SMEM_1, s2>>>(
        Wvh, xh, nullptr, vT, 1024, 1024, 1024, 4096,
        0, 0, 0, 0, 0, 0, 1, 1);
    cudaEventRecord(e3, s2);

    // ---- per-batch pipelines: batch 0 on stream 0, batch 1 on s1 ----
    cudaStreamWaitEvent(0, e1, 0);
    cudaStreamWaitEvent(s1, e0, 0);

    cudaStream_t bs[2] = { (cudaStream_t)0, s1 };
    for (int b = 0; b < 2; b++) {
        cudaStream_t st = bs[b];

        // qk projection (rows of batch b)
        gemm_h3<<<dim3(4608 / 128, 2048 / 256, 1), 256, SMEM_3, st>>>(
            xh + b * xOff, xl + b * xOff, Wqkh, Wqkl,
            nullptr, qkmh + b * qkOff, qkml + b * qkOff,
            1024, 1024, 1024, 4608,
            0, 0, 0, 0, 0, 0, 1, 2);

        // scores for batch b (8 heads)
        gemm_h3<<<dim3(2048 / 128, 2048 / 256, 8), 256, SMEM_3, st>>>(
            qkmh + b * qkOff, qkml + b * qkOff,
            qkmh + b * qkOff + 4096, qkml + b * qkOff + 4096,
            sc + b * scOff, nullptr, nullptr,
            512, 4608, 4608, 2048,
            0, 512, 0, 0, 0, 2048LL * 2048, 8, 0);

        // softmax for batch b
        softmax2048<<<8 * 2048, 256, 0, st>>>(sc + b * scOff, pr + b * scOff);

        // attn @ V for batch b
        cudaStreamWaitEvent(st, e3, 0);
        gemm_h1<<<dim3(1024 / 128, 2048 / 256, 8), 256, SMEM_1, st>>>(
            pr + b * scOff, vT + b * 2048, nullptr, ao + b * aoOff,
            2048, 2048, 4096, 8192,
            0, 2048LL * 2048, 0, 0, 0, 1024, 8, 1);

        // output projection for batch b
        gemm_h1<<<dim3(1024 / 128, 2048 / 256, 1), 256, SMEM_1, st>>>(
            ao + b * aoOff, Woh, out + b * outOff, nullptr,
            8192, 8192, 8192, 1024,
            0, 0, 0, 0, 0, 0, 1, 0);
    }

    // join batch-1 chain back to main stream
    cudaEventRecord(e4, s1);
    cudaStreamWaitEvent(0, e4, 0);
}

// round 12
// speedup vs baseline: 6.0014x; 1.0250x over previous
#include <cuda_runtime.h>
#include <cuda_fp16.h>
#include <math.h>
#include <stdint.h>

// ---------------------------------------------------------------------------
// GeometricAttentionLayer on GB300 — fp16 mma.sync + ldmatrix engine v6
//   3-pass split GEMMs (qk-proj, scores): 256x128 CTA tile, 64x64 warp tile.
//   Single-pass GEMMs (v-proj, attn@V, out-proj): 128x128 CTA tile (better
//   wave granularity at launch tails), 64x32 warp tile, 2 CTAs/SM.
// ---------------------------------------------------------------------------

#define BM 256
#define BN 128
#define BK 64
#define ATILE 32768                       // 256 rows x 128 B
#define BTILE 16384                       // 128 rows x 128 B
#define ST3 (2 * ATILE + 2 * BTILE)       // 96 KB / stage
#define SMEM_3 (2 * ST3)                  // 192 KB
#define ST1 (2 * BTILE)                   // 32 KB / stage (h1: 128x128)
#define SMEM_1 (3 * ST1)                  // 96 KB

__constant__ int c_ip[8] = {0, 2, 3, 4, 8, 9, 10, 14};

// ------------------------- scratch (device globals) ------------------------
__device__ __align__(1024) __half g_xh  [4096LL * 1024];
__device__ __align__(1024) __half g_xl  [4096LL * 1024];
__device__ __align__(1024) __half g_Wqkh[4608 * 1024];
__device__ __align__(1024) __half g_Wqkl[4608 * 1024];
__device__ __align__(1024) __half g_Wvh [1024 * 1024];
__device__ __align__(1024) __half g_Woh [1024 * 8192];
__device__ __align__(1024) __half g_qkmh[4096LL * 4608];
__device__ __align__(1024) __half g_qkml[4096LL * 4608];
__device__ __align__(1024) __half g_vT  [1024LL * 4096];
__device__ __align__(1024) float  g_sc  [16LL * 2048 * 2048];
__device__ __align__(1024) __half g_pr  [16LL * 2048 * 2048];
__device__ __align__(1024) __half g_ao  [4096LL * 8192];

// ------------------------------ helpers ------------------------------------
__device__ __forceinline__ uint32_t smem_u32(const void* p) {
    uint32_t a;
    asm("{ .reg .u64 t; cvta.to.shared.u64 t, %1; cvt.u32.u64 %0, t; }" : "=r"(a) : "l"(p));
    return a;
}

__device__ __forceinline__ void cp16(uint32_t dst, const __half* src) {
    asm volatile("cp.async.cg.shared.global [%0], [%1], 16;"
                 :: "r"(dst), "l"(src) : "memory");
}

#define LDSM_X4(r0, r1, r2, r3, addr)                                         \
    asm volatile("ldmatrix.sync.aligned.m8n8.x4.shared.b16 {%0,%1,%2,%3}, [%4];" \
        : "=r"(r0), "=r"(r1), "=r"(r2), "=r"(r3) : "r"(addr))

#define MMA_F16(acc, a, b)                                                    \
    asm volatile(                                                             \
        "mma.sync.aligned.m16n8k16.row.col.f32.f16.f16.f32 "                  \
        "{%0,%1,%2,%3}, {%4,%5,%6,%7}, {%8,%9}, {%0,%1,%2,%3};"               \
        : "+f"((acc)[0]), "+f"((acc)[1]), "+f"((acc)[2]), "+f"((acc)[3])      \
        : "r"((a)[0]), "r"((a)[1]), "r"((a)[2]), "r"((a)[3]),                 \
          "r"((b)[0]), "r"((b)[1]))

// ------------------- weight precompute (smem blade, 16 out/thread) ---------
__global__ __launch_bounds__(256) void make_weightT2(
    const float* __restrict__ w, const float* __restrict__ blade,
    __half* __restrict__ Wh, __half* __restrict__ Wl,
    int I, int mode, float scale, long long totalThreads, int storeLo)
{
    __shared__ float bl[9 * 256];
    for (int idx = threadIdx.x; idx < 9 * 256; idx += 256)
        bl[idx] = blade[idx];
    __syncthreads();

    long long t = (long long)blockIdx.x * 256 + threadIdx.x;
    if (t >= totalThreads) return;
    int col = (int)(t / I);
    int i   = (int)(t % I);

    int j, y;
    if (mode == 0)      { j = col >> 4; y = col & 15; }
    else if (mode == 1) { int e = col & 7; int d = (col >> 3) & 63; int h = col >> 9;
                          j = d * 8 + h; y = c_ip[e]; }
    else                { int e = col & 7; j = col >> 3; y = c_ip[e]; }

    float wr[9];
    const float* wp = w + ((long long)j * I + i) * 9;
    #pragma unroll
    for (int b = 0; b < 9; b++) wr[b] = wp[b];

    __half2 hv[8], lv[8];
    #pragma unroll
    for (int xc2 = 0; xc2 < 8; xc2++) {
        float s0 = 0.f, s1 = 0.f;
        #pragma unroll
        for (int b = 0; b < 9; b++) {
            s0 += wr[b] * bl[b * 256 + (xc2 * 2 + 0) * 16 + y];
            s1 += wr[b] * bl[b * 256 + (xc2 * 2 + 1) * 16 + y];
        }
        s0 *= scale; s1 *= scale;
        __half h0 = __float2half_rn(s0), h1 = __float2half_rn(s1);
        hv[xc2] = __halves2half2(h0, h1);
        lv[xc2] = __halves2half2(__float2half_rn(s0 - __half2float(h0)),
                                 __float2half_rn(s1 - __half2float(h1)));
    }

    long long base = (long long)col * (I * 16) + i * 16;
    __half2* oh = reinterpret_cast<__half2*>(Wh + base);
    #pragma unroll
    for (int u = 0; u < 8; u++) oh[u] = hv[u];
    if (storeLo) {
        __half2* ol = reinterpret_cast<__half2*>(Wl + base);
        #pragma unroll
        for (int u = 0; u < 8; u++) ol[u] = lv[u];
    }
}

// ------------------------------ fp16 split pass ----------------------------
__global__ void split_f16(const float4* __restrict__ in,
                          __half2* __restrict__ oh, __half2* __restrict__ ol, int n4)
{
    int i = blockIdx.x * 256 + threadIdx.x;
    if (i >= n4) return;
    float4 v = in[i];
    __half hx = __float2half_rn(v.x), hy = __float2half_rn(v.y);
    __half hz = __float2half_rn(v.z), hw = __float2half_rn(v.w);
    oh[i * 2 + 0] = __halves2half2(hx, hy);
    oh[i * 2 + 1] = __halves2half2(hz, hw);
    ol[i * 2 + 0] = __halves2half2(__float2half_rn(v.x - __half2float(hx)),
                                   __float2half_rn(v.y - __half2float(hy)));
    ol[i * 2 + 1] = __halves2half2(__float2half_rn(v.z - __half2float(hz)),
                                   __float2half_rn(v.w - __half2float(hw)));
}

// ------------------ single fp16 GEMM (NT), 128x128 tile --------------------
// C[m,n] = sum_k A[m,k]*B[n,k].  halfout: 0 -> fp32 C, 1 -> half C.
// 8 warps in 2x4 grid of 64x32 warp tiles, 3-stage cp.async, 2 CTAs/SM.
__global__ __launch_bounds__(256, 2) void gemm_h1(
    const __half* __restrict__ Ag, const __half* __restrict__ Bg,
    float* __restrict__ Cf, __half* __restrict__ Chh,
    int K, int lda, int ldb, int ldc,
    long long aB, long long aH, long long bB, long long bH,
    long long cB, long long cH, int nH, int halfout)
{
    extern __shared__ char sm[];
    const uint32_t smb = smem_u32(sm);

    const int tid = threadIdx.x;
    const int bb = blockIdx.z / nH, hh = blockIdx.z - bb * nH;
    const __half* A = Ag + bb * aB + hh * aH + (long long)(blockIdx.y * 128) * lda;
    const __half* B = Bg + bb * bB + hh * bH + (long long)(blockIdx.x * 128) * ldb;

    const int ldrow = tid >> 3;
    const int seg   = tid & 7;
    const uint32_t swoff = (uint32_t)((seg ^ (ldrow & 7)) << 4);
    uint32_t stoff[4];
    #pragma unroll
    for (int i = 0; i < 4; i++) stoff[i] = (uint32_t)((ldrow + 32 * i) * 128) + swoff;

#define ISSUE1(ch, slot) do {                                                 \
        const __half* _a = A + (long long)(ch) * BK + (seg << 3);             \
        uint32_t _da = smb + (uint32_t)(slot) * ST1;                          \
        _Pragma("unroll")                                                     \
        for (int _i = 0; _i < 4; _i++)                                        \
            cp16(_da + stoff[_i], _a + (long long)(ldrow + 32 * _i) * lda);   \
        const __half* _b = B + (long long)(ch) * BK + (seg << 3);             \
        uint32_t _db = smb + (uint32_t)(slot) * ST1 + BTILE;                  \
        _Pragma("unroll")                                                     \
        for (int _i = 0; _i < 4; _i++)                                        \
            cp16(_db + stoff[_i], _b + (long long)(ldrow + 32 * _i) * ldb);   \
    } while (0)

    const int lane = tid & 31;
    const int wm = ((tid >> 5) & 1) * 64;
    const int wn = (tid >> 6) * 32;
    const int qr = lane >> 2;
    const int qc = lane & 3;
    const int l7 = lane & 7;
    const uint32_t aRow = (uint32_t)(wm + (lane & 15)) * 128;
    const int aCb = lane >> 4;
    const uint32_t bRow = (uint32_t)(wn + l7 + ((lane >> 4) << 3)) * 128;
    const int bCb = (lane >> 3) & 1;

    float acc[4][4][4];
    #pragma unroll
    for (int mi = 0; mi < 4; mi++)
        #pragma unroll
        for (int ni = 0; ni < 4; ni++)
            #pragma unroll
            for (int q = 0; q < 4; q++) acc[mi][ni][q] = 0.f;

    const int nch = K >> 6;

    #pragma unroll
    for (int p = 0; p < 2; p++) {
        if (p < nch) ISSUE1(p, p);
        asm volatile("cp.async.commit_group;" ::: "memory");
    }

    for (int ch = 0; ch < nch; ch++) {
        asm volatile("cp.async.wait_group 1;" ::: "memory");
        __syncthreads();

        int pf = ch + 2;
        if (pf < nch) ISSUE1(pf, pf % 3);
        asm volatile("cp.async.commit_group;" ::: "memory");

        const int slot = ch % 3;
        const uint32_t tA = smb + slot * ST1 + aRow;
        const uint32_t tB = smb + slot * ST1 + BTILE + bRow;

        #pragma unroll
        for (int kk = 0; kk < 4; kk++) {
            const uint32_t aC = (uint32_t)((((kk << 1) + aCb) ^ l7) << 4);
            const uint32_t bC = (uint32_t)((((kk << 1) + bCb) ^ l7) << 4);
            uint32_t a[4][4], b[4][2];
            #pragma unroll
            for (int mi = 0; mi < 4; mi++)
                LDSM_X4(a[mi][0], a[mi][1], a[mi][2], a[mi][3], tA + mi * 2048 + aC);
            #pragma unroll
            for (int g = 0; g < 2; g++)
                LDSM_X4(b[2*g][0], b[2*g][1], b[2*g+1][0], b[2*g+1][1], tB + g * 2048 + bC);
            #pragma unroll
            for (int mi = 0; mi < 4; mi++)
                #pragma unroll
                for (int ni = 0; ni < 4; ni++)
                    MMA_F16(acc[mi][ni], a[mi], b[ni]);
        }
    }
#undef ISSUE1

    const long long cOff = bb * cB + hh * cH;
    const int rbase = blockIdx.y * 128 + wm + qr;
    const int cbase = blockIdx.x * 128 + wn + (qc << 1);
    #pragma unroll
    for (int mi = 0; mi < 4; mi++) {
        #pragma unroll
        for (int ni = 0; ni < 4; ni++) {
            const long long r = rbase + mi * 16;
            const int c = cbase + ni * 8;
            if (halfout) {
                __half* cb = Chh + cOff;
                *reinterpret_cast<__half2*>(&cb[r * ldc + c]) =
                    __halves2half2(__float2half_rn(acc[mi][ni][0]),
                                   __float2half_rn(acc[mi][ni][1]));
                *reinterpret_cast<__half2*>(&cb[(r + 8) * ldc + c]) =
                    __halves2half2(__float2half_rn(acc[mi][ni][2]),
                                   __float2half_rn(acc[mi][ni][3]));
            } else {
                float* cb = Cf + cOff;
                *reinterpret_cast<float2*>(&cb[r * ldc + c]) =
                    make_float2(acc[mi][ni][0], acc[mi][ni][1]);
                *reinterpret_cast<float2*>(&cb[(r + 8) * ldc + c]) =
                    make_float2(acc[mi][ni][2], acc[mi][ni][3]);
            }
        }
    }
}

// ------------------ 3-term fp16 split GEMM (NT), 256x128 tile --------------
// acc += Ahi*Bhi + Ahi*Blo + Alo*Bhi.  outmode: 0 -> fp32 C (.cs), 2 -> split half C.
__global__ __launch_bounds__(256, 1) void gemm_h3(
    const __half* __restrict__ Ah, const __half* __restrict__ Al,
    const __half* __restrict__ Bh, const __half* __restrict__ Bl,
    float* __restrict__ Cf, __half* __restrict__ Chh, __half* __restrict__ Chl,
    int K, int lda, int ldb, int ldc,
    long long aB, long long aH, long long bB, long long bH,
    long long cB, long long cH, int nH, int outmode)
{
    extern __shared__ char sm[];
    const uint32_t smb = smem_u32(sm);

    const int tid = threadIdx.x;
    const int bb = blockIdx.z / nH, hh = blockIdx.z - bb * nH;
    const long long aOff = bb * aB + hh * aH + (long long)(blockIdx.y * BM) * lda;
    const long long bOff = bb * bB + hh * bH + (long long)(blockIdx.x * BN) * ldb;
    const __half* pAh = Ah + aOff;
    const __half* pAl = Al + aOff;
    const __half* pBh = Bh + bOff;
    const __half* pBl = Bl + bOff;

    const int ldrow = tid >> 3;
    const int seg   = tid & 7;
    const uint32_t swoff = (uint32_t)((seg ^ (ldrow & 7)) << 4);

#define ISSUE3(ch, slot) do {                                                 \
        uint32_t _sb = smb + (uint32_t)(slot) * ST3;                          \
        const __half* _s0 = pAh + (long long)(ch) * BK + (seg << 3);          \
        const __half* _s1 = pAl + (long long)(ch) * BK + (seg << 3);          \
        _Pragma("unroll")                                                     \
        for (int _i = 0; _i < 8; _i++) {                                      \
            uint32_t _o = (uint32_t)((ldrow + 32 * _i) * 128) + swoff;        \
            long long _g = (long long)(ldrow + 32 * _i) * lda;                \
            cp16(_sb + _o, _s0 + _g);                                         \
            cp16(_sb + ATILE + _o, _s1 + _g);                                 \
        }                                                                     \
        const __half* _s2 = pBh + (long long)(ch) * BK + (seg << 3);          \
        const __half* _s3 = pBl + (long long)(ch) * BK + (seg << 3);          \
        _Pragma("unroll")                                                     \
        for (int _i = 0; _i < 4; _i++) {                                      \
            uint32_t _o = (uint32_t)((ldrow + 32 * _i) * 128) + swoff;        \
            long long _g = (long long)(ldrow + 32 * _i) * ldb;                \
            cp16(_sb + 2 * ATILE + _o, _s2 + _g);                             \
            cp16(_sb + 2 * ATILE + BTILE + _o, _s3 + _g);                     \
        }                                                                     \
    } while (0)

    const int lane = tid & 31;
    const int wid = tid >> 5;
    const int wm = (wid & 3) * 64;
    const int wn = (wid >> 2) * 64;
    const int qr = lane >> 2;
    const int qc = lane & 3;
    const int l7 = lane & 7;
    const uint32_t aRow = (uint32_t)(wm + (lane & 15)) * 128;
    const int aCb = lane >> 4;
    const uint32_t bRow = (uint32_t)(wn + l7 + ((lane >> 4) << 3)) * 128;
    const int bCb = (lane >> 3) & 1;

    float acc[4][8][4];
    #pragma unroll
    for (int mi = 0; mi < 4; mi++)
        #pragma unroll
        for (int ni = 0; ni < 8; ni++)
            #pragma unroll
            for (int q = 0; q < 4; q++) acc[mi][ni][q] = 0.f;

    const int nch = K >> 6;

    ISSUE3(0, 0);
    asm volatile("cp.async.commit_group;" ::: "memory");

    for (int ch = 0; ch < nch; ch++) {
        asm volatile("cp.async.wait_group 0;" ::: "memory");
        __syncthreads();
        if (ch + 1 < nch) {
            ISSUE3(ch + 1, (ch + 1) & 1);
            asm volatile("cp.async.commit_group;" ::: "memory");
        }

        const int slot = ch & 1;
        const uint32_t tAh = smb + slot * ST3 + aRow;
        const uint32_t tAl = smb + slot * ST3 + ATILE + aRow;
        const uint32_t tBh = smb + slot * ST3 + 2 * ATILE + bRow;
        const uint32_t tBl = smb + slot * ST3 + 2 * ATILE + BTILE + bRow;

        #pragma unroll
        for (int kk = 0; kk < 4; kk++) {
            const uint32_t aC = (uint32_t)((((kk << 1) + aCb) ^ l7) << 4);
            const uint32_t bC = (uint32_t)((((kk << 1) + bCb) ^ l7) << 4);
            uint32_t ah[4][4], al[4][4], bh[8][2], bl[8][2];
            #pragma unroll
            for (int mi = 0; mi < 4; mi++) {
                LDSM_X4(ah[mi][0], ah[mi][1], ah[mi][2], ah[mi][3], tAh + mi * 2048 + aC);
                LDSM_X4(al[mi][0], al[mi][1], al[mi][2], al[mi][3], tAl + mi * 2048 + aC);
            }
            #pragma unroll
            for (int g = 0; g < 4; g++) {
                LDSM_X4(bh[2*g][0], bh[2*g][1], bh[2*g+1][0], bh[2*g+1][1], tBh + g * 2048 + bC);
                LDSM_X4(bl[2*g][0], bl[2*g][1], bl[2*g+1][0], bl[2*g+1][1], tBl + g * 2048 + bC);
            }
            #pragma unroll
            for (int mi = 0; mi < 4; mi++)
                #pragma unroll
                for (int ni = 0; ni < 8; ni++) {
                    MMA_F16(acc[mi][ni], ah[mi], bl[ni]);
                    MMA_F16(acc[mi][ni], al[mi], bh[ni]);
                    MMA_F16(acc[mi][ni], ah[mi], bh[ni]);
                }
        }
    }
#undef ISSUE3

    const long long cOff = bb * cB + hh * cH;
    const int rbase = blockIdx.y * BM + wm + qr;
    const int cbase = blockIdx.x * BN + wn + (qc << 1);
    #pragma unroll
    for (int mi = 0; mi < 4; mi++) {
        #pragma unroll
        for (int ni = 0; ni < 8; ni++) {
            const long long r = rbase + mi * 16;
            const int c = cbase + ni * 8;
            float v[4] = {acc[mi][ni][0], acc[mi][ni][1], acc[mi][ni][2], acc[mi][ni][3]};
            if (outmode == 2) {
                __half h0 = __float2half_rn(v[0]), h1 = __float2half_rn(v[1]);
                __half h2 = __float2half_rn(v[2]), h3 = __float2half_rn(v[3]);
                __half* ch_ = Chh + cOff;
                __half* cl_ = Chl + cOff;
                *reinterpret_cast<__half2*>(&ch_[r * ldc + c])       = __halves2half2(h0, h1);
                *reinterpret_cast<__half2*>(&ch_[(r + 8) * ldc + c]) = __halves2half2(h2, h3);
                *reinterpret_cast<__half2*>(&cl_[r * ldc + c]) =
                    __halves2half2(__float2half_rn(v[0] - __half2float(h0)),
                                   __float2half_rn(v[1] - __half2float(h1)));
                *reinterpret_cast<__half2*>(&cl_[(r + 8) * ldc + c]) =
                    __halves2half2(__float2half_rn(v[2] - __half2float(h2)),
                                   __float2half_rn(v[3] - __half2float(h3)));
            } else {
                float* cb = Cf + cOff;
                __stcs(reinterpret_cast<float2*>(&cb[r * ldc + c]),
                       make_float2(v[0], v[1]));
                __stcs(reinterpret_cast<float2*>(&cb[(r + 8) * ldc + c]),
                       make_float2(v[2], v[3]));
            }
        }
    }
}

// ------------------------- softmax (2048 cols, fp32 -> half) ---------------
__global__ __launch_bounds__(256) void softmax2048(const float* __restrict__ sc,
                                                   __half* __restrict__ pr)
{
    __shared__ float red[8];
    const float4* p = reinterpret_cast<const float4*>(sc + (long long)blockIdx.x * 2048);
    __half2* q = reinterpret_cast<__half2*>(pr + (long long)blockIdx.x * 2048);
    const int t = threadIdx.x;
    const int wid = t >> 5, lid = t & 31;

    float4 a = __ldcs(p + t);
    float4 b = __ldcs(p + t + 256);

    float mx = fmaxf(fmaxf(fmaxf(a.x, a.y), fmaxf(a.z, a.w)),
                     fmaxf(fmaxf(b.x, b.y), fmaxf(b.z, b.w)));
    #pragma unroll
    for (int s = 16; s > 0; s >>= 1) mx = fmaxf(mx, __shfl_xor_sync(0xffffffffu, mx, s));
    if (lid == 0) red[wid] = mx;
    __syncthreads();
    if (t < 32) {
        float m = (t < 8) ? red[t] : -INFINITY;
        #pragma unroll
        for (int s = 4; s > 0; s >>= 1) m = fmaxf(m, __shfl_xor_sync(0xffffffffu, m, s));
        if (t == 0) red[0] = m;
    }
    __syncthreads();
    mx = red[0];
    __syncthreads();

    a.x = __expf(a.x - mx); a.y = __expf(a.y - mx); a.z = __expf(a.z - mx); a.w = __expf(a.w - mx);
    b.x = __expf(b.x - mx); b.y = __expf(b.y - mx); b.z = __expf(b.z - mx); b.w = __expf(b.w - mx);
    float sum = a.x + a.y + a.z + a.w + b.x + b.y + b.z + b.w;
    #pragma unroll
    for (int s = 16; s > 0; s >>= 1) sum += __shfl_xor_sync(0xffffffffu, sum, s);
    if (lid == 0) red[wid] = sum;
    __syncthreads();
    if (t < 32) {
        float m = (t < 8) ? red[t] : 0.f;
        #pragma unroll
        for (int s = 4; s > 0; s >>= 1) m += __shfl_xor_sync(0xffffffffu, m, s);
        if (t == 0) red[0] = m;
    }
    __syncthreads();
    float inv = 1.0f / red[0];

    __half2 q0 = __halves2half2(__float2half_rn(a.x * inv), __float2half_rn(a.y * inv));
    __half2 q1 = __halves2half2(__float2half_rn(a.z * inv), __float2half_rn(a.w * inv));
    __half2 q2 = __halves2half2(__float2half_rn(b.x * inv), __float2half_rn(b.y * inv));
    __half2 q3 = __halves2half2(__float2half_rn(b.z * inv), __float2half_rn(b.w * inv));
    uint2 u01 = make_uint2(*reinterpret_cast<uint32_t*>(&q0), *reinterpret_cast<uint32_t*>(&q1));
    uint2 u23 = make_uint2(*reinterpret_cast<uint32_t*>(&q2), *reinterpret_cast<uint32_t*>(&q3));
    __stcs(reinterpret_cast<uint2*>(q + t * 2), u01);
    __stcs(reinterpret_cast<uint2*>(q + (t + 256) * 2), u23);
}

// ------------------------------ host side ----------------------------------
template <typename T>
static T* sym_addr(const void* symbol)
{
    void* p = nullptr;
    cudaGetSymbolAddress(&p, symbol);
    return (T*)p;
}

extern "C" void kernel_launch(void* const* d_in, const int* in_sizes, int n_in,
                              void* d_out, int out_size)
{
    const float* x     = (const float*)d_in[0];
    const float* blade = (const float*)d_in[1];
    const float* w_q   = (const float*)d_in[2];
    const float* w_k   = (const float*)d_in[3];
    const float* w_v   = (const float*)d_in[4];
    const float* w_o   = (const float*)d_in[5];
    float* out = (float*)d_out;

    __half* xh   = sym_addr<__half>(g_xh),   *xl   = sym_addr<__half>(g_xl);
    __half* Wqkh = sym_addr<__half>(g_Wqkh), *Wqkl = sym_addr<__half>(g_Wqkl);
    __half* Wvh  = sym_addr<__half>(g_Wvh);
    __half* Woh  = sym_addr<__half>(g_Woh);
    __half* qkmh = sym_addr<__half>(g_qkmh), *qkml = sym_addr<__half>(g_qkml);
    __half* vT   = sym_addr<__half>(g_vT);
    float*  sc   = sym_addr<float >(g_sc);
    __half* pr   = sym_addr<__half>(g_pr);
    __half* ao   = sym_addr<__half>(g_ao);

    static cudaStream_t s1 = nullptr, s2 = nullptr;
    static cudaEvent_t eF = nullptr, e0 = nullptr, e1 = nullptr, e3 = nullptr, e4 = nullptr;
    if (s1 == nullptr) {
        cudaStreamCreateWithFlags(&s1, cudaStreamNonBlocking);
        cudaStreamCreateWithFlags(&s2, cudaStreamNonBlocking);
        cudaEventCreateWithFlags(&eF, cudaEventDisableTiming);
        cudaEventCreateWithFlags(&e0, cudaEventDisableTiming);
        cudaEventCreateWithFlags(&e1, cudaEventDisableTiming);
        cudaEventCreateWithFlags(&e3, cudaEventDisableTiming);
        cudaEventCreateWithFlags(&e4, cudaEventDisableTiming);
        cudaFuncSetAttribute(gemm_h1, cudaFuncAttributeMaxDynamicSharedMemorySize, SMEM_1);
        cudaFuncSetAttribute(gemm_h3, cudaFuncAttributeMaxDynamicSharedMemorySize, SMEM_3);
    }

    const float scale = 1.0f / sqrtf(512.0f);

    const long long xOff   = 2048LL * 1024;
    const long long qkOff  = 2048LL * 4608;
    const long long scOff  = 8LL * 2048 * 2048;
    const long long aoOff  = 2048LL * 8192;
    const long long outOff = 2048LL * 1024;

    // ---- fork ----
    cudaEventRecord(eF, 0);
    cudaStreamWaitEvent(s1, eF, 0);
    cudaStreamWaitEvent(s2, eF, 0);

    // s1: q+k weight precompute
    {
        long long tq = 4096LL * 64;
        make_weightT2<<<(unsigned)((tq + 255) / 256), 256, 0, s1>>>(
            w_q, blade, Wqkh, Wqkl, 64, 1, scale, tq, 1);
        long long tk = 512LL * 64;
        make_weightT2<<<(unsigned)((tk + 255) / 256), 256, 0, s1>>>(
            w_k, blade, Wqkh + 4096LL * 1024, Wqkl + 4096LL * 1024, 64, 2, 1.0f, tk, 1);
        cudaEventRecord(e1, s1);
    }
    // s2: v + o weight precompute
    {
        long long tv = 1024LL * 64;
        make_weightT2<<<(unsigned)((tv + 255) / 256), 256, 0, s2>>>(
            w_v, blade, Wvh, nullptr, 64, 0, 1.0f, tv, 0);
        long long to = 1024LL * 512;
        make_weightT2<<<(unsigned)((to + 255) / 256), 256, 0, s2>>>(
            w_o, blade, Woh, nullptr, 512, 0, 1.0f, to, 0);
    }

    // main: input split
    split_f16<<<4096, 256>>>((const float4*)x, (__half2*)xh, (__half2*)xl, 4096 * 1024 / 4);
    cudaEventRecord(e0, 0);

    // s2: v projection (all tokens): vT[f, m]
    cudaStreamWaitEvent(s2, e0, 0);
    gemm_h1<<<dim3(4096 / 128, 1024 / 128, 1), 256, SMEM_1, s2>>>(
        Wvh, xh, nullptr, vT, 1024, 1024, 1024, 4096,
        0, 0, 0, 0, 0, 0, 1, 1);
    cudaEventRecord(e3, s2);

    // ---- per-batch pipelines: batch 0 on stream 0, batch 1 on s1 ----
    cudaStreamWaitEvent(0, e1, 0);
    cudaStreamWaitEvent(s1, e0, 0);

    cudaStream_t bs[2] = { (cudaStream_t)0, s1 };
    for (int b = 0; b < 2; b++) {
        cudaStream_t st = bs[b];

        // qk projection (rows of batch b)
        gemm_h3<<<dim3(4608 / 128, 2048 / 256, 1), 256, SMEM_3, st>>>(
            xh + b * xOff, xl + b * xOff, Wqkh, Wqkl,
            nullptr, qkmh + b * qkOff, qkml + b * qkOff,
            1024, 1024, 1024, 4608,
            0, 0, 0, 0, 0, 0, 1, 2);

        // scores for batch b (8 heads)
        gemm_h3<<<dim3(2048 / 128, 2048 / 256, 8), 256, SMEM_3, st>>>(
            qkmh + b * qkOff, qkml + b * qkOff,
            qkmh + b * qkOff + 4096, qkml + b * qkOff + 4096,
            sc + b * scOff, nullptr, nullptr,
            512, 4608, 4608, 2048,
            0, 512, 0, 0, 0, 2048LL * 2048, 8, 0);

        // softmax for batch b
        softmax2048<<<8 * 2048, 256, 0, st>>>(sc + b * scOff, pr + b * scOff);

        // attn @ V for batch b (128x128 tiles: 8x16x8 = 1024 CTAs)
        cudaStreamWaitEvent(st, e3, 0);
        gemm_h1<<<dim3(1024 / 128, 2048 / 128, 8), 256, SMEM_1, st>>>(
            pr + b * scOff, vT + b * 2048, nullptr, ao + b * aoOff,
            2048, 2048, 4096, 8192,
            0, 2048LL * 2048, 0, 0, 0, 1024, 8, 1);

        // output projection for batch b (128 CTAs)
        gemm_h1<<<dim3(1024 / 128, 2048 / 128, 1), 256, SMEM_1, st>>>(
            ao + b * aoOff, Woh, out + b * outOff, nullptr,
            8192, 8192, 8192, 1024,
            0, 0, 0, 0, 0, 0, 1, 0);
    }

    // join batch-1 chain back to main stream
    cudaEventRecord(e4, s1);
    cudaStreamWaitEvent(0, e4, 0);
}